// round 3
// baseline (speedup 1.0000x reference)
#include <cuda_runtime.h>
#include <math.h>

#define Bsz  256
#define Tlen 64
#define Hdim 1024
#define Xdim 512
#define Edim 256
#define DIN  768
#define G4   4096
#define NTAG 512

// ---- scratch layout (floats) ----
// xpart   [256*4096]          @ 0          (1,048,576)
// embproj [512*4096]          @ 1,048,576  (2,097,152)
// hA      [256*1024]          @ 3,145,728
// hB      [256*1024]          @ 3,407,872
// cbuf    [256*1024]          @ 3,670,016
// hs      [64*256*1024]       @ 3,932,160  (16,777,216)
// logits  [64*256*512]        @ 20,709,376 (8,388,608)
// rownll  [16384]             @ 29,097,984
// rowmask [16384]             @ 29,114,368
__device__ float g_scratch[29130752];
__device__ int   g_mask_mode;   // 0 = int32, 1 = byte, 2 = float32

// ============================================================================
// Generic SGEMM: C[M,N] = A[M,K] @ B[N,K]^T (+bias0[n]) (+bias1[n])
// 64x64 tile, BK=16, 256 threads, 4x4 per thread.
// M, N multiples of 64; K multiple of 16 (all true for our shapes).
// ============================================================================
__global__ __launch_bounds__(256) void sgemm_tn(
    const float* __restrict__ A, int lda,
    const float* __restrict__ Bm, int ldb,
    float* __restrict__ C, int ldc, int K,
    const float* __restrict__ bias0,
    const float* __restrict__ bias1)
{
    __shared__ float As[16][68];
    __shared__ float Bs[16][68];
    const int m0 = blockIdx.y * 64;
    const int n0 = blockIdx.x * 64;
    const int tid = threadIdx.x;
    const int ty = tid >> 4;   // 0..15
    const int tx = tid & 15;   // 0..15
    float acc[4][4] = {};

    for (int k0 = 0; k0 < K; k0 += 16) {
        #pragma unroll
        for (int i = 0; i < 4; i++) {
            int idx = tid + i * 256;
            int m = idx >> 4, k = idx & 15;
            As[k][m] = A[(size_t)(m0 + m) * lda + k0 + k];
            Bs[k][m] = Bm[(size_t)(n0 + m) * ldb + k0 + k];
        }
        __syncthreads();
        #pragma unroll
        for (int k = 0; k < 16; k++) {
            float4 a = *(const float4*)&As[k][ty * 4];
            float4 b = *(const float4*)&Bs[k][tx * 4];
            float av[4] = {a.x, a.y, a.z, a.w};
            float bv[4] = {b.x, b.y, b.z, b.w};
            #pragma unroll
            for (int i = 0; i < 4; i++)
                #pragma unroll
                for (int j = 0; j < 4; j++)
                    acc[i][j] += av[i] * bv[j];
        }
        __syncthreads();
    }

    #pragma unroll
    for (int i = 0; i < 4; i++) {
        int m = m0 + ty * 4 + i;
        #pragma unroll
        for (int j = 0; j < 4; j++) {
            int n = n0 + tx * 4 + j;
            float v = acc[i][j];
            if (bias0) v += bias0[n];
            if (bias1) v += bias1[n];
            C[(size_t)m * ldc + n] = v;
        }
    }
}

// ============================================================================
// Fused LSTM step: for a 32(batch) x 32(j) tile, compute all 4 gate columns
// gates[b][gate*H + j] = xpart + embproj[prev_tok] + h @ W_hh^T,
// apply activations, update c and h, store h into hs[t].
// h is double-buffered across steps (hin/hout) to avoid intra-step races.
// Grid: (H/32, B/32) = (32, 8); 256 threads.
// ============================================================================
__global__ __launch_bounds__(256) void lstm_step(
    const float* __restrict__ hin,
    float* __restrict__ hout,
    float* __restrict__ cbuf,
    const float* __restrict__ xpart,
    const float* __restrict__ embproj,
    float* __restrict__ hs,
    const float* __restrict__ W_hh,
    const int* __restrict__ atom_truth,
    int t)
{
    __shared__ float As[32][36];    // h tile, transposed: As[k][m]
    __shared__ float Bs[32][132];   // W_hh tile, transposed: Bs[k][c], c = gate*32+jj
    __shared__ float Gs[32][128];   // staged gate pre-activations [local_b][c]

    const int b0 = blockIdx.y * 32;
    const int j0 = blockIdx.x * 32;
    const int tid = threadIdx.x;
    const int ty = tid >> 5;        // 0..7  -> 4 batch rows each
    const int tx = tid & 31;        // 0..31 -> 4 gate-cols each
    float acc[4][4] = {};

    for (int k0 = 0; k0 < Hdim; k0 += 32) {
        #pragma unroll
        for (int i = 0; i < 4; i++) {
            int idx = tid + i * 256;
            int m = idx >> 5, k = idx & 31;
            As[k][m] = hin[(b0 + m) * Hdim + k0 + k];
        }
        #pragma unroll
        for (int i = 0; i < 16; i++) {
            int idx = tid + i * 256;
            int n = idx >> 5, k = idx & 31;            // n in 0..127
            int grow = (n >> 5) * Hdim + j0 + (n & 31); // gate*H + j
            Bs[k][n] = W_hh[(size_t)grow * Hdim + k0 + k];
        }
        __syncthreads();
        #pragma unroll
        for (int k = 0; k < 32; k++) {
            float4 a = *(const float4*)&As[k][ty * 4];
            float4 b = *(const float4*)&Bs[k][tx * 4];
            float av[4] = {a.x, a.y, a.z, a.w};
            float bv[4] = {b.x, b.y, b.z, b.w};
            #pragma unroll
            for (int i = 0; i < 4; i++)
                #pragma unroll
                for (int j = 0; j < 4; j++)
                    acc[i][j] += av[i] * bv[j];
        }
        __syncthreads();
    }

    // previous-step tokens (teacher forcing); step 0 uses token 0 (emb row 0 = 0)
    int toks[4];
    #pragma unroll
    for (int i = 0; i < 4; i++) {
        int b = b0 + ty * 4 + i;
        toks[i] = (t == 0) ? 0 : atom_truth[b * Tlen + (t - 1)];
    }

    // add input projection + embedding projection, stage to smem
    #pragma unroll
    for (int i = 0; i < 4; i++) {
        int b = b0 + ty * 4 + i;
        #pragma unroll
        for (int j = 0; j < 4; j++) {
            int c = tx * 4 + j;
            int gcol = (c >> 5) * Hdim + j0 + (c & 31);
            float v = acc[i][j]
                    + xpart[(size_t)b * G4 + gcol]
                    + embproj[(size_t)toks[i] * G4 + gcol];
            Gs[ty * 4 + i][c] = v;
        }
    }
    __syncthreads();

    // cell update: 1024 (b,jj) pairs, 4 per thread
    #pragma unroll
    for (int i = 0; i < 4; i++) {
        int idx = tid + i * 256;
        int bl = idx >> 5, jj = idx & 31;
        float ig = Gs[bl][jj];
        float fg = Gs[bl][32 + jj];
        float gg = Gs[bl][64 + jj];
        float og = Gs[bl][96 + jj];
        ig = 1.f / (1.f + expf(-ig));
        fg = 1.f / (1.f + expf(-fg));
        og = 1.f / (1.f + expf(-og));
        gg = tanhf(gg);
        int b = b0 + bl, j = j0 + jj;
        float cv = fg * cbuf[b * Hdim + j] + ig * gg;
        float hv = og * tanhf(cv);
        cbuf[b * Hdim + j] = cv;
        hout[b * Hdim + j] = hv;
        hs[((size_t)t * Bsz + b) * Hdim + j] = hv;
    }
}

// ============================================================================
// Detect host encoding of the bool atom_mask (deterministic given inputs).
// Reads the first 4096 u32 words (= 16 KB, within bounds for all encodings).
//   float32 (1.0f) -> some word == 0x3F800000
//   byte            -> some word > 1 (packed 0/1 bytes)
//   int32           -> all words in {0,1}
// ============================================================================
__global__ void detect_mask(const unsigned* __restrict__ m)
{
    __shared__ int isByte, isFloat;
    if (threadIdx.x == 0) { isByte = 0; isFloat = 0; }
    __syncthreads();
    for (int i = threadIdx.x; i < (Bsz * Tlen) / 4; i += blockDim.x) {
        unsigned v = m[i];
        if (v == 0x3F800000u) isFloat = 1;
        else if (v > 1u) isByte = 1;
    }
    __syncthreads();
    if (threadIdx.x == 0) g_mask_mode = isFloat ? 2 : (isByte ? 1 : 0);
}

// ============================================================================
// Per-row log-softmax + NLL (row = t*B + b), masked.
// ============================================================================
__global__ __launch_bounds__(128) void nll_rows(
    const float* __restrict__ logits,
    const int* __restrict__ atom_truth,
    const void* __restrict__ atom_mask,
    float* __restrict__ rownll,
    float* __restrict__ rowmask)
{
    const int r = blockIdx.x;       // t*B + b
    const int t = r >> 8;
    const int b = r & 255;
    const float* row = logits + (size_t)r * NTAG;
    const int tid = threadIdx.x;
    __shared__ float red[128];

    float mx = -1e30f;
    for (int i = tid; i < NTAG; i += 128) mx = fmaxf(mx, row[i]);
    red[tid] = mx; __syncthreads();
    for (int s = 64; s > 0; s >>= 1) {
        if (tid < s) red[tid] = fmaxf(red[tid], red[tid + s]);
        __syncthreads();
    }
    mx = red[0]; __syncthreads();

    float sm = 0.f;
    for (int i = tid; i < NTAG; i += 128) sm += expf(row[i] - mx);
    red[tid] = sm; __syncthreads();
    for (int s = 64; s > 0; s >>= 1) {
        if (tid < s) red[tid] += red[tid + s];
        __syncthreads();
    }

    if (tid == 0) {
        int tgt = atom_truth[b * Tlen + t];
        float lp = row[tgt] - mx - logf(red[0]);
        int mode = g_mask_mode;
        float m;
        if (mode == 2)      m = (((const float*)atom_mask)[b * Tlen + t] != 0.f) ? 1.f : 0.f;
        else if (mode == 1) m = (((const unsigned char*)atom_mask)[b * Tlen + t] != 0) ? 1.f : 0.f;
        else                m = (((const int*)atom_mask)[b * Tlen + t] != 0) ? 1.f : 0.f;
        rownll[r]  = -lp * m;
        rowmask[r] = m;
    }
}

// ============================================================================
// Final masked-mean reduction (double accumulation).
// ============================================================================
__global__ __launch_bounds__(256) void final_reduce(
    const float* __restrict__ rownll,
    const float* __restrict__ rowmask,
    float* __restrict__ out)
{
    __shared__ double rn[256], rm[256];
    double sn = 0.0, sm = 0.0;
    for (int i = threadIdx.x; i < Tlen * Bsz; i += 256) {
        sn += (double)rownll[i];
        sm += (double)rowmask[i];
    }
    rn[threadIdx.x] = sn; rm[threadIdx.x] = sm;
    __syncthreads();
    for (int s = 128; s > 0; s >>= 1) {
        if (threadIdx.x < s) {
            rn[threadIdx.x] += rn[threadIdx.x + s];
            rm[threadIdx.x] += rm[threadIdx.x + s];
        }
        __syncthreads();
    }
    if (threadIdx.x == 0) out[0] = (float)(rn[0] / rm[0]);
}

// ============================================================================
// Launch
// ============================================================================
extern "C" void kernel_launch(void* const* d_in, const int* in_sizes, int n_in,
                              void* d_out, int out_size)
{
    const float* x      = (const float*)d_in[0];
    const int*   atomtr = (const int*)d_in[1];
    const void*  mask   = d_in[2];
    const float* emb    = (const float*)d_in[3];
    const float* W_ih   = (const float*)d_in[4];
    const float* W_hh   = (const float*)d_in[5];
    const float* b_ih   = (const float*)d_in[6];
    const float* b_hh   = (const float*)d_in[7];
    const float* W_out  = (const float*)d_in[8];
    const float* b_out  = (const float*)d_in[9];
    const float* h0     = (const float*)d_in[10];
    const float* c0     = (const float*)d_in[11];

    float* sc = nullptr;
    cudaGetSymbolAddress((void**)&sc, g_scratch);
    float* xpart   = sc + 0;
    float* embproj = sc + 1048576;
    float* hA      = sc + 3145728;
    float* hB      = sc + 3407872;
    float* cbuf    = sc + 3670016;
    float* hs      = sc + 3932160;
    float* logits  = sc + 20709376;
    float* rownll  = sc + 29097984;
    float* rowmask = sc + 29114368;

    // init recurrent state
    cudaMemcpyAsync(hA,   h0, (size_t)Bsz * Hdim * sizeof(float), cudaMemcpyDeviceToDevice, 0);
    cudaMemcpyAsync(cbuf, c0, (size_t)Bsz * Hdim * sizeof(float), cudaMemcpyDeviceToDevice, 0);

    detect_mask<<<1, 256>>>((const unsigned*)mask);

    // xpart = x @ W_ih[:, :512]^T + b_ih + b_hh      [256, 4096]
    sgemm_tn<<<dim3(G4 / 64, Bsz / 64), 256>>>(x, Xdim, W_ih, DIN, xpart, G4, Xdim, b_ih, b_hh);
    // embproj = emb @ W_ih[:, 512:768]^T             [512, 4096]
    sgemm_tn<<<dim3(G4 / 64, NTAG / 64), 256>>>(emb, Edim, W_ih + Xdim, DIN, embproj, G4, Edim, nullptr, nullptr);

    // sequential LSTM
    for (int t = 0; t < Tlen; t++) {
        const float* hin = (t & 1) ? hB : hA;
        float* hout      = (t & 1) ? hA : hB;
        lstm_step<<<dim3(Hdim / 32, Bsz / 32), 256>>>(
            hin, hout, cbuf, xpart, embproj, hs, W_hh, atomtr, t);
    }

    // logits = hs @ W_out^T + b_out   [16384, 512]
    sgemm_tn<<<dim3(NTAG / 64, (Tlen * Bsz) / 64), 256>>>(
        hs, Hdim, W_out, Hdim, logits, NTAG, Hdim, b_out, nullptr);

    nll_rows<<<Tlen * Bsz, 128>>>(logits, atomtr, mask, rownll, rowmask);
    final_reduce<<<1, 256>>>(rownll, rowmask, (float*)d_out);
}

// round 4
// speedup vs baseline: 1.0479x; 1.0479x over previous
#include <cuda_runtime.h>
#include <math.h>

#define Bsz  256
#define Tlen 64
#define Hdim 1024
#define Xdim 512
#define Edim 256
#define DIN  768
#define G4   4096
#define NTAG 512

// ---- scratch layout (floats) ----
__device__ float g_scratch[29130752];
__device__ int   g_mask_mode;   // 0 = int32, 1 = byte, 2 = float32

// packed fp32x2 FMA (Blackwell full-rate fp32 path; ptxas never auto-emits it)
#define FFMA2(d, a, b) asm("fma.rn.f32x2 %0, %1, %2, %0;" : "+l"(d) : "l"(a), "l"(b))

union F2U { unsigned long long u; float2 f; };

__device__ __forceinline__ unsigned long long dup2(float a) {
    unsigned x = __float_as_uint(a);
    return ((unsigned long long)x << 32) | (unsigned long long)x;
}

// ============================================================================
// Generic f32x2 SGEMM: C[M,N] = A[M,K] @ B[N,K]^T (+bias0[n]) (+bias1[n])
// TILE_M=128, TILE_N=64, BK=16, 256 threads, microtile 8 rows x 4 cols
// (col pairs packed as f32x2). M%128==0, N%64==0, K%16==0.
// ============================================================================
__global__ __launch_bounds__(256) void sgemm2(
    const float* __restrict__ A, int lda,
    const float* __restrict__ Bm, int ldb,
    float* __restrict__ C, int ldc, int K,
    const float* __restrict__ bias0,
    const float* __restrict__ bias1)
{
    __shared__ unsigned long long As2[16][128];  // dup pairs (16 KB)
    __shared__ float Bs[16][64];                 // 4 KB

    const int m0 = blockIdx.y * 128;
    const int n0 = blockIdx.x * 64;
    const int tid = threadIdx.x;
    const int rg = tid >> 4;    // 0..15 -> rows rg*8..rg*8+7
    const int cg = tid & 15;    // 0..15 -> cols cg*4..cg*4+3

    unsigned long long acc[8][2];
    #pragma unroll
    for (int i = 0; i < 8; i++) { acc[i][0] = 0ull; acc[i][1] = 0ull; }

    const int fm = tid >> 2;          // 0..63
    const int fk = (tid & 3) * 4;     // 0,4,8,12

    for (int k0 = 0; k0 < K; k0 += 16) {
        __syncthreads();
        // fill As2 (2048 dups, 8/thread)
        #pragma unroll
        for (int half = 0; half < 2; half++) {
            int m = fm + half * 64;
            float4 v = *(const float4*)&A[(size_t)(m0 + m) * lda + k0 + fk];
            As2[fk + 0][m] = dup2(v.x);
            As2[fk + 1][m] = dup2(v.y);
            As2[fk + 2][m] = dup2(v.z);
            As2[fk + 3][m] = dup2(v.w);
        }
        // fill Bs (1024, 4/thread)
        {
            int n = fm;  // 0..63
            float4 v = *(const float4*)&Bm[(size_t)(n0 + n) * ldb + k0 + fk];
            Bs[fk + 0][n] = v.x;
            Bs[fk + 1][n] = v.y;
            Bs[fk + 2][n] = v.z;
            Bs[fk + 3][n] = v.w;
        }
        __syncthreads();
        #pragma unroll
        for (int k = 0; k < 16; k++) {
            const ulonglong2* ap = (const ulonglong2*)&As2[k][rg * 8];
            ulonglong2 bv = *(const ulonglong2*)&Bs[k][cg * 4];
            #pragma unroll
            for (int i2 = 0; i2 < 4; i2++) {
                ulonglong2 a = ap[i2];
                FFMA2(acc[2 * i2 + 0][0], a.x, bv.x);
                FFMA2(acc[2 * i2 + 0][1], a.x, bv.y);
                FFMA2(acc[2 * i2 + 1][0], a.y, bv.x);
                FFMA2(acc[2 * i2 + 1][1], a.y, bv.y);
            }
        }
    }

    #pragma unroll
    for (int i = 0; i < 8; i++) {
        int m = m0 + rg * 8 + i;
        #pragma unroll
        for (int p = 0; p < 2; p++) {
            int n = n0 + cg * 4 + p * 2;
            F2U u; u.u = acc[i][p];
            float v0 = u.f.x, v1 = u.f.y;
            if (bias0) { v0 += bias0[n]; v1 += bias0[n + 1]; }
            if (bias1) { v0 += bias1[n]; v1 += bias1[n + 1]; }
            *(float2*)&C[(size_t)m * ldc + n] = make_float2(v0, v1);
        }
    }
}

// ============================================================================
// Fused LSTM step, f32x2. Tile: 64 batch x (32 j x 4 gates). 256 threads.
// Thread (ty,tx): rows b0+ty*8..+7, j = j0+tx, cols = 4 gates of j.
// Gate columns interleaved in Bs as c = jj*4 + gate so each thread's 4 cols
// are exactly {i,f,g,o} of its j -> cell update fully in-register.
// Grid: (1024/32, 256/64) = (32, 4) = 128 blocks.
// ============================================================================
__global__ __launch_bounds__(256) void lstm_step(
    const float* __restrict__ hin,
    float* __restrict__ hout,
    float* __restrict__ cbuf,
    const float* __restrict__ xpart,
    const float* __restrict__ embproj,
    float* __restrict__ hs,
    const float* __restrict__ W_hh,
    const int* __restrict__ atom_truth,
    int t)
{
    __shared__ unsigned long long As2[16][64];   // dup pairs of h tile (8 KB)
    __shared__ float Bs[16][128];                // W_hh tile, col = jj*4+g (8 KB)

    const int j0 = blockIdx.x * 32;
    const int b0 = blockIdx.y * 64;
    const int tid = threadIdx.x;
    const int ty = tid >> 5;    // 0..7
    const int tx = tid & 31;    // jj local

    unsigned long long acc[8][2];
    #pragma unroll
    for (int i = 0; i < 8; i++) { acc[i][0] = 0ull; acc[i][1] = 0ull; }

    const int am = tid >> 2;          // 0..63
    const int ak = (tid & 3) * 4;     // 0,4,8,12
    const int bc = tid >> 1;          // 0..127
    const int bk = (tid & 1) * 8;     // 0, 8
    const int bg = bc & 3;            // gate
    const int bj = bc >> 2;           // jj
    const float* wrow = &W_hh[(size_t)(bg * Hdim + j0 + bj) * Hdim];

    for (int k0 = 0; k0 < Hdim; k0 += 16) {
        __syncthreads();
        // As2 fill: 1024 dups, 4/thread
        {
            float4 v = *(const float4*)&hin[(b0 + am) * Hdim + k0 + ak];
            As2[ak + 0][am] = dup2(v.x);
            As2[ak + 1][am] = dup2(v.y);
            As2[ak + 2][am] = dup2(v.z);
            As2[ak + 3][am] = dup2(v.w);
        }
        // Bs fill: 2048 floats, 8/thread
        {
            float4 v0 = *(const float4*)&wrow[k0 + bk];
            float4 v1 = *(const float4*)&wrow[k0 + bk + 4];
            Bs[bk + 0][bc] = v0.x;  Bs[bk + 1][bc] = v0.y;
            Bs[bk + 2][bc] = v0.z;  Bs[bk + 3][bc] = v0.w;
            Bs[bk + 4][bc] = v1.x;  Bs[bk + 5][bc] = v1.y;
            Bs[bk + 6][bc] = v1.z;  Bs[bk + 7][bc] = v1.w;
        }
        __syncthreads();
        #pragma unroll
        for (int k = 0; k < 16; k++) {
            const ulonglong2* ap = (const ulonglong2*)&As2[k][ty * 8];
            ulonglong2 bv = *(const ulonglong2*)&Bs[k][tx * 4]; // (g0,g1),(g2,g3)
            #pragma unroll
            for (int i2 = 0; i2 < 4; i2++) {
                ulonglong2 a = ap[i2];
                FFMA2(acc[2 * i2 + 0][0], a.x, bv.x);
                FFMA2(acc[2 * i2 + 0][1], a.x, bv.y);
                FFMA2(acc[2 * i2 + 1][0], a.y, bv.x);
                FFMA2(acc[2 * i2 + 1][1], a.y, bv.y);
            }
        }
    }

    // epilogue: per (b, j) cell update, all in registers
    const int jj = j0 + tx;
    #pragma unroll
    for (int i = 0; i < 8; i++) {
        int b = b0 + ty * 8 + i;
        int tok = (t == 0) ? 0 : atom_truth[b * Tlen + (t - 1)];
        const float* xp = xpart + (size_t)b * G4 + jj;
        const float* ep = embproj + (size_t)tok * G4 + jj;
        F2U u0, u1; u0.u = acc[i][0]; u1.u = acc[i][1];
        float ig = u0.f.x + xp[0]        + ep[0];
        float fg = u0.f.y + xp[Hdim]     + ep[Hdim];
        float gg = u1.f.x + xp[2 * Hdim] + ep[2 * Hdim];
        float og = u1.f.y + xp[3 * Hdim] + ep[3 * Hdim];
        ig = 1.f / (1.f + expf(-ig));
        fg = 1.f / (1.f + expf(-fg));
        og = 1.f / (1.f + expf(-og));
        gg = tanhf(gg);
        float cv = fg * cbuf[b * Hdim + jj] + ig * gg;
        float hv = og * tanhf(cv);
        cbuf[b * Hdim + jj] = cv;
        hout[b * Hdim + jj] = hv;
        hs[((size_t)t * Bsz + b) * Hdim + jj] = hv;
    }
}

// ============================================================================
// Mask encoding detection (deterministic).
// ============================================================================
__global__ void detect_mask(const unsigned* __restrict__ m)
{
    __shared__ int isByte, isFloat;
    if (threadIdx.x == 0) { isByte = 0; isFloat = 0; }
    __syncthreads();
    for (int i = threadIdx.x; i < (Bsz * Tlen) / 4; i += blockDim.x) {
        unsigned v = m[i];
        if (v == 0x3F800000u) isFloat = 1;
        else if (v > 1u) isByte = 1;
    }
    __syncthreads();
    if (threadIdx.x == 0) g_mask_mode = isFloat ? 2 : (isByte ? 1 : 0);
}

// ============================================================================
// Per-row log-softmax + NLL (row = t*B + b), masked.
// ============================================================================
__global__ __launch_bounds__(128) void nll_rows(
    const float* __restrict__ logits,
    const int* __restrict__ atom_truth,
    const void* __restrict__ atom_mask,
    float* __restrict__ rownll,
    float* __restrict__ rowmask)
{
    const int r = blockIdx.x;
    const int t = r >> 8;
    const int b = r & 255;
    const float* row = logits + (size_t)r * NTAG;
    const int tid = threadIdx.x;
    __shared__ float red[128];

    float mx = -1e30f;
    for (int i = tid; i < NTAG; i += 128) mx = fmaxf(mx, row[i]);
    red[tid] = mx; __syncthreads();
    for (int s = 64; s > 0; s >>= 1) {
        if (tid < s) red[tid] = fmaxf(red[tid], red[tid + s]);
        __syncthreads();
    }
    mx = red[0]; __syncthreads();

    float sm = 0.f;
    for (int i = tid; i < NTAG; i += 128) sm += expf(row[i] - mx);
    red[tid] = sm; __syncthreads();
    for (int s = 64; s > 0; s >>= 1) {
        if (tid < s) red[tid] += red[tid + s];
        __syncthreads();
    }

    if (tid == 0) {
        int tgt = atom_truth[b * Tlen + t];
        float lp = row[tgt] - mx - logf(red[0]);
        int mode = g_mask_mode;
        float m;
        if (mode == 2)      m = (((const float*)atom_mask)[b * Tlen + t] != 0.f) ? 1.f : 0.f;
        else if (mode == 1) m = (((const unsigned char*)atom_mask)[b * Tlen + t] != 0) ? 1.f : 0.f;
        else                m = (((const int*)atom_mask)[b * Tlen + t] != 0) ? 1.f : 0.f;
        rownll[r]  = -lp * m;
        rowmask[r] = m;
    }
}

__global__ __launch_bounds__(256) void final_reduce(
    const float* __restrict__ rownll,
    const float* __restrict__ rowmask,
    float* __restrict__ out)
{
    __shared__ double rn[256], rm[256];
    double sn = 0.0, sm = 0.0;
    for (int i = threadIdx.x; i < Tlen * Bsz; i += 256) {
        sn += (double)rownll[i];
        sm += (double)rowmask[i];
    }
    rn[threadIdx.x] = sn; rm[threadIdx.x] = sm;
    __syncthreads();
    for (int s = 128; s > 0; s >>= 1) {
        if (threadIdx.x < s) {
            rn[threadIdx.x] += rn[threadIdx.x + s];
            rm[threadIdx.x] += rm[threadIdx.x + s];
        }
        __syncthreads();
    }
    if (threadIdx.x == 0) out[0] = (float)(rn[0] / rm[0]);
}

// ============================================================================
// Launch
// ============================================================================
extern "C" void kernel_launch(void* const* d_in, const int* in_sizes, int n_in,
                              void* d_out, int out_size)
{
    const float* x      = (const float*)d_in[0];
    const int*   atomtr = (const int*)d_in[1];
    const void*  mask   = d_in[2];
    const float* emb    = (const float*)d_in[3];
    const float* W_ih   = (const float*)d_in[4];
    const float* W_hh   = (const float*)d_in[5];
    const float* b_ih   = (const float*)d_in[6];
    const float* b_hh   = (const float*)d_in[7];
    const float* W_out  = (const float*)d_in[8];
    const float* b_out  = (const float*)d_in[9];
    const float* h0     = (const float*)d_in[10];
    const float* c0     = (const float*)d_in[11];

    float* sc = nullptr;
    cudaGetSymbolAddress((void**)&sc, g_scratch);
    float* xpart   = sc + 0;
    float* embproj = sc + 1048576;
    float* hA      = sc + 3145728;
    float* hB      = sc + 3407872;
    float* cbuf    = sc + 3670016;
    float* hs      = sc + 3932160;
    float* logits  = sc + 20709376;
    float* rownll  = sc + 29097984;
    float* rowmask = sc + 29114368;

    cudaMemcpyAsync(hA,   h0, (size_t)Bsz * Hdim * sizeof(float), cudaMemcpyDeviceToDevice, 0);
    cudaMemcpyAsync(cbuf, c0, (size_t)Bsz * Hdim * sizeof(float), cudaMemcpyDeviceToDevice, 0);

    detect_mask<<<1, 256>>>((const unsigned*)mask);

    // xpart = x @ W_ih[:, :512]^T + b_ih + b_hh   [256, 4096]
    sgemm2<<<dim3(G4 / 64, Bsz / 128), 256>>>(x, Xdim, W_ih, DIN, xpart, G4, Xdim, b_ih, b_hh);
    // embproj = emb @ W_ih[:, 512:768]^T          [512, 4096]
    sgemm2<<<dim3(G4 / 64, NTAG / 128), 256>>>(emb, Edim, W_ih + Xdim, DIN, embproj, G4, Edim, nullptr, nullptr);

    for (int t = 0; t < Tlen; t++) {
        const float* hin = (t & 1) ? hB : hA;
        float* hout      = (t & 1) ? hA : hB;
        lstm_step<<<dim3(Hdim / 32, Bsz / 64), 256>>>(
            hin, hout, cbuf, xpart, embproj, hs, W_hh, atomtr, t);
    }

    // logits = hs @ W_out^T + b_out   [16384, 512]
    sgemm2<<<dim3(NTAG / 64, (Tlen * Bsz) / 128), 256>>>(
        hs, Hdim, W_out, Hdim, logits, NTAG, Hdim, b_out, nullptr);

    nll_rows<<<Tlen * Bsz, 128>>>(logits, atomtr, mask, rownll, rowmask);
    final_reduce<<<1, 256>>>(rownll, rowmask, (float*)d_out);
}

// round 6
// speedup vs baseline: 2.3198x; 2.2138x over previous
#include <cuda_runtime.h>
#include <cuda_bf16.h>
#include <math.h>

#define Bsz  256
#define Tlen 64
#define Hdim 1024
#define Xdim 512
#define Edim 256
#define DIN  768
#define G4   4096
#define NTAG 512

// ---- scratch layout ----
// floats:
//   xpart   @0          (1,048,576)
//   embproj @1,048,576  (2,097,152)
//   cbuf    @3,145,728  (262,144)
//   logits  @3,407,872  (8,388,608)
//   rownll  @11,796,480 (16,384)
//   rowmask @11,812,864 (16,384)
// bf16 region starts at float offset 11,829,248; bf16-element offsets:
//   whh_hi 0            whh_lo 4,194,304
//   wout_hi 8,388,608   wout_lo 8,912,896
//   hA_hi 9,437,184  hA_lo 9,699,328  hB_hi 9,961,472  hB_lo 10,223,616
//   hs_hi 10,485,760 (16,777,216)   hs_lo 27,262,976 (16,777,216)
__device__ float g_scratch[33849344];
__device__ int   g_mask_mode;   // 0 = int32, 1 = byte, 2 = float32

#define MMA_BF16(c, a, b) \
    asm volatile("mma.sync.aligned.m16n8k16.row.col.f32.bf16.bf16.f32 " \
                 "{%0,%1,%2,%3},{%4,%5,%6,%7},{%8,%9},{%0,%1,%2,%3};" \
                 : "+f"((c)[0]), "+f"((c)[1]), "+f"((c)[2]), "+f"((c)[3]) \
                 : "r"((a)[0]), "r"((a)[1]), "r"((a)[2]), "r"((a)[3]), \
                   "r"((b)[0]), "r"((b)[1]))

// packed fp32x2 FMA (kept for xpart/embproj GEMM)
#define FFMA2(d, a, b) asm("fma.rn.f32x2 %0, %1, %2, %0;" : "+l"(d) : "l"(a), "l"(b))
union F2U { unsigned long long u; float2 f; };
__device__ __forceinline__ unsigned long long dup2(float a) {
    unsigned x = __float_as_uint(a);
    return ((unsigned long long)x << 32) | (unsigned long long)x;
}

// ============================================================================
// Split helpers: v = hi + lo (bf16 pair)
// ============================================================================
__device__ __forceinline__ void bf16split(float v, __nv_bfloat16& hi, __nv_bfloat16& lo) {
    hi = __float2bfloat16_rn(v);
    lo = __float2bfloat16_rn(v - __bfloat162float(hi));
}

// W_hh [4H, H] -> gate-interleaved rows c = j*4+g, split hi/lo
__global__ void split_whh(const float* __restrict__ W,
                          __nv_bfloat16* __restrict__ hi,
                          __nv_bfloat16* __restrict__ lo)
{
    int c = blockIdx.x;             // 0..4095
    int j = c >> 2, g = c & 3;
    const float* src = W + (size_t)(g * Hdim + j) * Hdim;
    int k = threadIdx.x * 4;
    float4 v = *(const float4*)&src[k];
    size_t o = (size_t)c * Hdim + k;
    float a[4] = {v.x, v.y, v.z, v.w};
    #pragma unroll
    for (int q = 0; q < 4; q++) bf16split(a[q], hi[o + q], lo[o + q]);
}

// plain row-major [rows, 1024] split
__global__ void split_plain(const float* __restrict__ W,
                            __nv_bfloat16* __restrict__ hi,
                            __nv_bfloat16* __restrict__ lo)
{
    int r = blockIdx.x;
    const float* src = W + (size_t)r * Hdim;
    int k = threadIdx.x * 4;
    float4 v = *(const float4*)&src[k];
    size_t o = (size_t)r * Hdim + k;
    float a[4] = {v.x, v.y, v.z, v.w};
    #pragma unroll
    for (int q = 0; q < 4; q++) bf16split(a[q], hi[o + q], lo[o + q]);
}

// ============================================================================
// f32x2 SGEMM (xpart / embproj only): C[M,N] = A[M,K] @ B[N,K]^T (+b0)(+b1)
// ============================================================================
__global__ __launch_bounds__(256) void sgemm2(
    const float* __restrict__ A, int lda,
    const float* __restrict__ Bm, int ldb,
    float* __restrict__ C, int ldc, int K,
    const float* __restrict__ bias0,
    const float* __restrict__ bias1)
{
    __shared__ unsigned long long As2[16][128];
    __shared__ float Bs[16][64];
    const int m0 = blockIdx.y * 128;
    const int n0 = blockIdx.x * 64;
    const int tid = threadIdx.x;
    const int rg = tid >> 4;
    const int cg = tid & 15;
    unsigned long long acc[8][2];
    #pragma unroll
    for (int i = 0; i < 8; i++) { acc[i][0] = 0ull; acc[i][1] = 0ull; }
    const int fm = tid >> 2;
    const int fk = (tid & 3) * 4;

    for (int k0 = 0; k0 < K; k0 += 16) {
        __syncthreads();
        #pragma unroll
        for (int half = 0; half < 2; half++) {
            int m = fm + half * 64;
            float4 v = *(const float4*)&A[(size_t)(m0 + m) * lda + k0 + fk];
            As2[fk + 0][m] = dup2(v.x);
            As2[fk + 1][m] = dup2(v.y);
            As2[fk + 2][m] = dup2(v.z);
            As2[fk + 3][m] = dup2(v.w);
        }
        {
            float4 v = *(const float4*)&Bm[(size_t)(n0 + fm) * ldb + k0 + fk];
            Bs[fk + 0][fm] = v.x; Bs[fk + 1][fm] = v.y;
            Bs[fk + 2][fm] = v.z; Bs[fk + 3][fm] = v.w;
        }
        __syncthreads();
        #pragma unroll
        for (int k = 0; k < 16; k++) {
            const ulonglong2* ap = (const ulonglong2*)&As2[k][rg * 8];
            ulonglong2 bv = *(const ulonglong2*)&Bs[k][cg * 4];
            #pragma unroll
            for (int i2 = 0; i2 < 4; i2++) {
                ulonglong2 a = ap[i2];
                FFMA2(acc[2 * i2 + 0][0], a.x, bv.x);
                FFMA2(acc[2 * i2 + 0][1], a.x, bv.y);
                FFMA2(acc[2 * i2 + 1][0], a.y, bv.x);
                FFMA2(acc[2 * i2 + 1][1], a.y, bv.y);
            }
        }
    }
    #pragma unroll
    for (int i = 0; i < 8; i++) {
        int m = m0 + rg * 8 + i;
        #pragma unroll
        for (int p = 0; p < 2; p++) {
            int n = n0 + cg * 4 + p * 2;
            F2U u; u.u = acc[i][p];
            float v0 = u.f.x, v1 = u.f.y;
            if (bias0) { v0 += bias0[n]; v1 += bias0[n + 1]; }
            if (bias1) { v0 += bias1[n]; v1 += bias1[n + 1]; }
            *(float2*)&C[(size_t)m * ldc + n] = make_float2(v0, v1);
        }
    }
}

// ============================================================================
// LSTM step via bf16-split tensor-core MMA.
// Block tile: 64 batch x 128 gate-cols (= 32 j x 4 gates interleaved c=jj*4+g).
// 8 warps as 2(m) x 4(n), warp tile 32x32, mma m16n8k16, 3 split terms.
// Grid (1024/32, 256/64) = (32,4) = 128 blocks.
// ============================================================================
__global__ __launch_bounds__(256) void lstm_step_mma(
    const __nv_bfloat16* __restrict__ hinhi,
    const __nv_bfloat16* __restrict__ hinlo,
    __nv_bfloat16* __restrict__ houthi,
    __nv_bfloat16* __restrict__ houtlo,
    float* __restrict__ cbuf,
    const float* __restrict__ xpart,
    const float* __restrict__ embproj,
    __nv_bfloat16* __restrict__ hshi,
    __nv_bfloat16* __restrict__ hslo,
    const __nv_bfloat16* __restrict__ whhhi,
    const __nv_bfloat16* __restrict__ whhlo,
    const int* __restrict__ atom_truth,
    int t)
{
    __shared__ __align__(16) unsigned char smraw[34048];
    __nv_bfloat16* Ahi = (__nv_bfloat16*)smraw;       // [64][40]
    __nv_bfloat16* Alo = Ahi + 64 * 40;
    __nv_bfloat16* Bhi = Alo + 64 * 40;               // [128][40]
    __nv_bfloat16* Blo = Bhi + 128 * 40;
    float* Gs = (float*)smraw;                        // [64][132] (aliased after loop)

    const int j0 = blockIdx.x * 32;
    const int b0 = blockIdx.y * 64;
    const int c0 = j0 * 4;
    const int tid = threadIdx.x;
    const int lane = tid & 31, w = tid >> 5;
    const int wm = w & 1, wn = w >> 1;
    const int qr = lane >> 2, qk = (lane & 3) * 2;

    float acc[2][4][4];
    #pragma unroll
    for (int mt = 0; mt < 2; mt++)
        #pragma unroll
        for (int nt = 0; nt < 4; nt++)
            #pragma unroll
            for (int q = 0; q < 4; q++) acc[mt][nt][q] = 0.f;

    const int ar = tid >> 2, akc = (tid & 3) * 8;
    const int br = tid >> 1, bkc = (tid & 1) * 16;
    const __nv_bfloat16* gAh = hinhi + (size_t)(b0 + ar) * Hdim + akc;
    const __nv_bfloat16* gAl = hinlo + (size_t)(b0 + ar) * Hdim + akc;
    const __nv_bfloat16* gBh = whhhi + (size_t)(c0 + br) * Hdim + bkc;
    const __nv_bfloat16* gBl = whhlo + (size_t)(c0 + br) * Hdim + bkc;

    // prologue fill (k0 = 0)
    *(uint4*)&Ahi[ar * 40 + akc]     = *(const uint4*)gAh;
    *(uint4*)&Alo[ar * 40 + akc]     = *(const uint4*)gAl;
    *(uint4*)&Bhi[br * 40 + bkc]     = *(const uint4*)gBh;
    *(uint4*)&Bhi[br * 40 + bkc + 8] = *(const uint4*)(gBh + 8);
    *(uint4*)&Blo[br * 40 + bkc]     = *(const uint4*)gBl;
    *(uint4*)&Blo[br * 40 + bkc + 8] = *(const uint4*)(gBl + 8);
    __syncthreads();

    for (int k0 = 0; k0 < Hdim; k0 += 32) {
        uint4 pah, pal, pbh0, pbh1, pbl0, pbl1;
        const bool more = (k0 + 32) < Hdim;
        if (more) {  // prefetch next chunk to regs while computing current
            pah  = *(const uint4*)(gAh + k0 + 32);
            pal  = *(const uint4*)(gAl + k0 + 32);
            pbh0 = *(const uint4*)(gBh + k0 + 32);
            pbh1 = *(const uint4*)(gBh + k0 + 40);
            pbl0 = *(const uint4*)(gBl + k0 + 32);
            pbl1 = *(const uint4*)(gBl + k0 + 40);
        }
        #pragma unroll
        for (int kh = 0; kh < 2; kh++) {
            const int kk = kh * 16 + qk;
            unsigned ah[2][4], al[2][4];
            #pragma unroll
            for (int mt = 0; mt < 2; mt++) {
                int r0 = wm * 32 + mt * 16 + qr;
                ah[mt][0] = *(const unsigned*)&Ahi[r0 * 40 + kk];
                ah[mt][1] = *(const unsigned*)&Ahi[(r0 + 8) * 40 + kk];
                ah[mt][2] = *(const unsigned*)&Ahi[r0 * 40 + kk + 8];
                ah[mt][3] = *(const unsigned*)&Ahi[(r0 + 8) * 40 + kk + 8];
                al[mt][0] = *(const unsigned*)&Alo[r0 * 40 + kk];
                al[mt][1] = *(const unsigned*)&Alo[(r0 + 8) * 40 + kk];
                al[mt][2] = *(const unsigned*)&Alo[r0 * 40 + kk + 8];
                al[mt][3] = *(const unsigned*)&Alo[(r0 + 8) * 40 + kk + 8];
            }
            #pragma unroll
            for (int nt = 0; nt < 4; nt++) {
                int n = wn * 32 + nt * 8 + qr;
                unsigned bh[2], bl[2];
                bh[0] = *(const unsigned*)&Bhi[n * 40 + kk];
                bh[1] = *(const unsigned*)&Bhi[n * 40 + kk + 8];
                bl[0] = *(const unsigned*)&Blo[n * 40 + kk];
                bl[1] = *(const unsigned*)&Blo[n * 40 + kk + 8];
                #pragma unroll
                for (int mt = 0; mt < 2; mt++) {
                    MMA_BF16(acc[mt][nt], ah[mt], bh);
                    MMA_BF16(acc[mt][nt], ah[mt], bl);
                    MMA_BF16(acc[mt][nt], al[mt], bh);
                }
            }
        }
        __syncthreads();
        if (more) {
            *(uint4*)&Ahi[ar * 40 + akc]     = pah;
            *(uint4*)&Alo[ar * 40 + akc]     = pal;
            *(uint4*)&Bhi[br * 40 + bkc]     = pbh0;
            *(uint4*)&Bhi[br * 40 + bkc + 8] = pbh1;
            *(uint4*)&Blo[br * 40 + bkc]     = pbl0;
            *(uint4*)&Blo[br * 40 + bkc + 8] = pbl1;
        }
        __syncthreads();
    }

    // stage gate pre-activations to smem (cols already interleaved jj*4+g)
    #pragma unroll
    for (int mt = 0; mt < 2; mt++)
        #pragma unroll
        for (int nt = 0; nt < 4; nt++) {
            int r = wm * 32 + mt * 16 + qr;
            int cc = wn * 32 + nt * 8 + qk;
            *(float2*)&Gs[r * 132 + cc]       = make_float2(acc[mt][nt][0], acc[mt][nt][1]);
            *(float2*)&Gs[(r + 8) * 132 + cc] = make_float2(acc[mt][nt][2], acc[mt][nt][3]);
        }
    __syncthreads();

    // cell update: 2048 (b,jj), 8 per thread
    #pragma unroll
    for (int i = 0; i < 8; i++) {
        int idx = tid + i * 256;
        int bl = idx >> 5, jj = idx & 31;
        float4 gv = *(const float4*)&Gs[bl * 132 + jj * 4];   // (i,f,g,o)
        int b = b0 + bl, j = j0 + jj;
        int tok = (t == 0) ? 0 : atom_truth[b * Tlen + (t - 1)];
        const float* xp = xpart + (size_t)b * G4 + j;
        const float* ep = embproj + (size_t)tok * G4 + j;
        float ig = gv.x + xp[0]        + ep[0];
        float fg = gv.y + xp[Hdim]     + ep[Hdim];
        float gg = gv.z + xp[2 * Hdim] + ep[2 * Hdim];
        float og = gv.w + xp[3 * Hdim] + ep[3 * Hdim];
        ig = 1.f / (1.f + expf(-ig));
        fg = 1.f / (1.f + expf(-fg));
        og = 1.f / (1.f + expf(-og));
        gg = tanhf(gg);
        float cv = fg * cbuf[b * Hdim + j] + ig * gg;
        float hv = og * tanhf(cv);
        cbuf[b * Hdim + j] = cv;
        __nv_bfloat16 hh, hl;
        bf16split(hv, hh, hl);
        houthi[b * Hdim + j] = hh;
        houtlo[b * Hdim + j] = hl;
        size_t ho = ((size_t)t * Bsz + b) * Hdim + j;
        hshi[ho] = hh;
        hslo[ho] = hl;
    }
}

// ============================================================================
// Logits GEMM via bf16-split MMA: C[16384,512] = hs @ W_out^T + b_out.
// Same 64m x 128n tile. Grid (512/128, 16384/64) = (4, 256).
// ============================================================================
__global__ __launch_bounds__(256) void logits_mma(
    const __nv_bfloat16* __restrict__ Ahi_g,
    const __nv_bfloat16* __restrict__ Alo_g,
    const __nv_bfloat16* __restrict__ Bhi_g,
    const __nv_bfloat16* __restrict__ Blo_g,
    float* __restrict__ C,
    const float* __restrict__ bias)
{
    __shared__ __align__(16) unsigned char smraw[30720];
    __nv_bfloat16* Ahi = (__nv_bfloat16*)smraw;
    __nv_bfloat16* Alo = Ahi + 64 * 40;
    __nv_bfloat16* Bhi = Alo + 64 * 40;
    __nv_bfloat16* Blo = Bhi + 128 * 40;

    const int n0 = blockIdx.x * 128;
    const int m0 = blockIdx.y * 64;
    const int tid = threadIdx.x;
    const int lane = tid & 31, w = tid >> 5;
    const int wm = w & 1, wn = w >> 1;
    const int qr = lane >> 2, qk = (lane & 3) * 2;

    float acc[2][4][4];
    #pragma unroll
    for (int mt = 0; mt < 2; mt++)
        #pragma unroll
        for (int nt = 0; nt < 4; nt++)
            #pragma unroll
            for (int q = 0; q < 4; q++) acc[mt][nt][q] = 0.f;

    const int ar = tid >> 2, akc = (tid & 3) * 8;
    const int br = tid >> 1, bkc = (tid & 1) * 16;
    const __nv_bfloat16* gAh = Ahi_g + (size_t)(m0 + ar) * Hdim + akc;
    const __nv_bfloat16* gAl = Alo_g + (size_t)(m0 + ar) * Hdim + akc;
    const __nv_bfloat16* gBh = Bhi_g + (size_t)(n0 + br) * Hdim + bkc;
    const __nv_bfloat16* gBl = Blo_g + (size_t)(n0 + br) * Hdim + bkc;

    *(uint4*)&Ahi[ar * 40 + akc]     = *(const uint4*)gAh;
    *(uint4*)&Alo[ar * 40 + akc]     = *(const uint4*)gAl;
    *(uint4*)&Bhi[br * 40 + bkc]     = *(const uint4*)gBh;
    *(uint4*)&Bhi[br * 40 + bkc + 8] = *(const uint4*)(gBh + 8);
    *(uint4*)&Blo[br * 40 + bkc]     = *(const uint4*)gBl;
    *(uint4*)&Blo[br * 40 + bkc + 8] = *(const uint4*)(gBl + 8);
    __syncthreads();

    for (int k0 = 0; k0 < Hdim; k0 += 32) {
        uint4 pah, pal, pbh0, pbh1, pbl0, pbl1;
        const bool more = (k0 + 32) < Hdim;
        if (more) {
            pah  = *(const uint4*)(gAh + k0 + 32);
            pal  = *(const uint4*)(gAl + k0 + 32);
            pbh0 = *(const uint4*)(gBh + k0 + 32);
            pbh1 = *(const uint4*)(gBh + k0 + 40);
            pbl0 = *(const uint4*)(gBl + k0 + 32);
            pbl1 = *(const uint4*)(gBl + k0 + 40);
        }
        #pragma unroll
        for (int kh = 0; kh < 2; kh++) {
            const int kk = kh * 16 + qk;
            unsigned ah[2][4], al[2][4];
            #pragma unroll
            for (int mt = 0; mt < 2; mt++) {
                int r0 = wm * 32 + mt * 16 + qr;
                ah[mt][0] = *(const unsigned*)&Ahi[r0 * 40 + kk];
                ah[mt][1] = *(const unsigned*)&Ahi[(r0 + 8) * 40 + kk];
                ah[mt][2] = *(const unsigned*)&Ahi[r0 * 40 + kk + 8];
                ah[mt][3] = *(const unsigned*)&Ahi[(r0 + 8) * 40 + kk + 8];
                al[mt][0] = *(const unsigned*)&Alo[r0 * 40 + kk];
                al[mt][1] = *(const unsigned*)&Alo[(r0 + 8) * 40 + kk];
                al[mt][2] = *(const unsigned*)&Alo[r0 * 40 + kk + 8];
                al[mt][3] = *(const unsigned*)&Alo[(r0 + 8) * 40 + kk + 8];
            }
            #pragma unroll
            for (int nt = 0; nt < 4; nt++) {
                int n = wn * 32 + nt * 8 + qr;
                unsigned bh[2], bl[2];
                bh[0] = *(const unsigned*)&Bhi[n * 40 + kk];
                bh[1] = *(const unsigned*)&Bhi[n * 40 + kk + 8];
                bl[0] = *(const unsigned*)&Blo[n * 40 + kk];
                bl[1] = *(const unsigned*)&Blo[n * 40 + kk + 8];
                #pragma unroll
                for (int mt = 0; mt < 2; mt++) {
                    MMA_BF16(acc[mt][nt], ah[mt], bh);
                    MMA_BF16(acc[mt][nt], ah[mt], bl);
                    MMA_BF16(acc[mt][nt], al[mt], bh);
                }
            }
        }
        __syncthreads();
        if (more) {
            *(uint4*)&Ahi[ar * 40 + akc]     = pah;
            *(uint4*)&Alo[ar * 40 + akc]     = pal;
            *(uint4*)&Bhi[br * 40 + bkc]     = pbh0;
            *(uint4*)&Bhi[br * 40 + bkc + 8] = pbh1;
            *(uint4*)&Blo[br * 40 + bkc]     = pbl0;
            *(uint4*)&Blo[br * 40 + bkc + 8] = pbl1;
        }
        __syncthreads();
    }

    #pragma unroll
    for (int mt = 0; mt < 2; mt++)
        #pragma unroll
        for (int nt = 0; nt < 4; nt++) {
            int m = m0 + wm * 32 + mt * 16 + qr;
            int n = n0 + wn * 32 + nt * 8 + qk;
            float b0v = bias[n], b1v = bias[n + 1];
            *(float2*)&C[(size_t)m * NTAG + n] =
                make_float2(acc[mt][nt][0] + b0v, acc[mt][nt][1] + b1v);
            *(float2*)&C[(size_t)(m + 8) * NTAG + n] =
                make_float2(acc[mt][nt][2] + b0v, acc[mt][nt][3] + b1v);
        }
}

// ============================================================================
// Mask encoding detection (deterministic).
// ============================================================================
__global__ void detect_mask(const unsigned* __restrict__ m)
{
    __shared__ int isByte, isFloat;
    if (threadIdx.x == 0) { isByte = 0; isFloat = 0; }
    __syncthreads();
    for (int i = threadIdx.x; i < (Bsz * Tlen) / 4; i += blockDim.x) {
        unsigned v = m[i];
        if (v == 0x3F800000u) isFloat = 1;
        else if (v > 1u) isByte = 1;
    }
    __syncthreads();
    if (threadIdx.x == 0) g_mask_mode = isFloat ? 2 : (isByte ? 1 : 0);
}

// ============================================================================
// Per-row log-softmax + NLL (row = t*B + b), masked.
// ============================================================================
__global__ __launch_bounds__(128) void nll_rows(
    const float* __restrict__ logits,
    const int* __restrict__ atom_truth,
    const void* __restrict__ atom_mask,
    float* __restrict__ rownll,
    float* __restrict__ rowmask)
{
    const int r = blockIdx.x;
    const int t = r >> 8;
    const int b = r & 255;
    const float* row = logits + (size_t)r * NTAG;
    const int tid = threadIdx.x;
    __shared__ float red[128];

    float mx = -1e30f;
    for (int i = tid; i < NTAG; i += 128) mx = fmaxf(mx, row[i]);
    red[tid] = mx; __syncthreads();
    for (int s = 64; s > 0; s >>= 1) {
        if (tid < s) red[tid] = fmaxf(red[tid], red[tid + s]);
        __syncthreads();
    }
    mx = red[0]; __syncthreads();

    float sm = 0.f;
    for (int i = tid; i < NTAG; i += 128) sm += expf(row[i] - mx);
    red[tid] = sm; __syncthreads();
    for (int s = 64; s > 0; s >>= 1) {
        if (tid < s) red[tid] += red[tid + s];
        __syncthreads();
    }

    if (tid == 0) {
        int tgt = atom_truth[b * Tlen + t];
        float lp = row[tgt] - mx - logf(red[0]);
        int mode = g_mask_mode;
        float m;
        if (mode == 2)      m = (((const float*)atom_mask)[b * Tlen + t] != 0.f) ? 1.f : 0.f;
        else if (mode == 1) m = (((const unsigned char*)atom_mask)[b * Tlen + t] != 0) ? 1.f : 0.f;
        else                m = (((const int*)atom_mask)[b * Tlen + t] != 0) ? 1.f : 0.f;
        rownll[r]  = -lp * m;
        rowmask[r] = m;
    }
}

__global__ __launch_bounds__(256) void final_reduce(
    const float* __restrict__ rownll,
    const float* __restrict__ rowmask,
    float* __restrict__ out)
{
    __shared__ double rn[256], rm[256];
    double sn = 0.0, sm = 0.0;
    for (int i = threadIdx.x; i < Tlen * Bsz; i += 256) {
        sn += (double)rownll[i];
        sm += (double)rowmask[i];
    }
    rn[threadIdx.x] = sn; rm[threadIdx.x] = sm;
    __syncthreads();
    for (int s = 128; s > 0; s >>= 1) {
        if (threadIdx.x < s) {
            rn[threadIdx.x] += rn[threadIdx.x + s];
            rm[threadIdx.x] += rm[threadIdx.x + s];
        }
        __syncthreads();
    }
    if (threadIdx.x == 0) out[0] = (float)(rn[0] / rm[0]);
}

// ============================================================================
// Launch
// ============================================================================
extern "C" void kernel_launch(void* const* d_in, const int* in_sizes, int n_in,
                              void* d_out, int out_size)
{
    const float* x      = (const float*)d_in[0];
    const int*   atomtr = (const int*)d_in[1];
    const void*  mask   = d_in[2];
    const float* emb    = (const float*)d_in[3];
    const float* W_ih   = (const float*)d_in[4];
    const float* W_hh   = (const float*)d_in[5];
    const float* b_ih   = (const float*)d_in[6];
    const float* b_hh   = (const float*)d_in[7];
    const float* W_out  = (const float*)d_in[8];
    const float* b_out  = (const float*)d_in[9];
    const float* h0     = (const float*)d_in[10];
    const float* c0     = (const float*)d_in[11];

    float* sc = nullptr;
    cudaGetSymbolAddress((void**)&sc, g_scratch);
    float* xpart   = sc + 0;
    float* embproj = sc + 1048576;
    float* cbuf    = sc + 3145728;
    float* logits  = sc + 3407872;
    float* rownll  = sc + 11796480;
    float* rowmask = sc + 11812864;
    __nv_bfloat16* bb = (__nv_bfloat16*)(sc + 11829248);
    __nv_bfloat16* whh_hi  = bb + 0;
    __nv_bfloat16* whh_lo  = bb + 4194304;
    __nv_bfloat16* wout_hi = bb + 8388608;
    __nv_bfloat16* wout_lo = bb + 8912896;
    __nv_bfloat16* hA_hi   = bb + 9437184;
    __nv_bfloat16* hA_lo   = bb + 9699328;
    __nv_bfloat16* hB_hi   = bb + 9961472;
    __nv_bfloat16* hB_lo   = bb + 10223616;
    __nv_bfloat16* hs_hi   = bb + 10485760;
    __nv_bfloat16* hs_lo   = bb + 27262976;

    cudaMemcpyAsync(cbuf, c0, (size_t)Bsz * Hdim * sizeof(float), cudaMemcpyDeviceToDevice, 0);

    detect_mask<<<1, 256>>>((const unsigned*)mask);

    // one-time weight / state splits
    split_whh<<<4096, 256>>>(W_hh, whh_hi, whh_lo);
    split_plain<<<512, 256>>>(W_out, wout_hi, wout_lo);
    split_plain<<<256, 256>>>(h0, hA_hi, hA_lo);

    // xpart = x @ W_ih[:, :512]^T + b_ih + b_hh   [256, 4096]
    sgemm2<<<dim3(G4 / 64, Bsz / 128), 256>>>(x, Xdim, W_ih, DIN, xpart, G4, Xdim, b_ih, b_hh);
    // embproj = emb @ W_ih[:, 512:768]^T          [512, 4096]
    sgemm2<<<dim3(G4 / 64, NTAG / 128), 256>>>(emb, Edim, W_ih + Xdim, DIN, embproj, G4, Edim, nullptr, nullptr);

    for (int t = 0; t < Tlen; t++) {
        const __nv_bfloat16* ih = (t & 1) ? hB_hi : hA_hi;
        const __nv_bfloat16* il = (t & 1) ? hB_lo : hA_lo;
        __nv_bfloat16* oh = (t & 1) ? hA_hi : hB_hi;
        __nv_bfloat16* ol = (t & 1) ? hA_lo : hB_lo;
        lstm_step_mma<<<dim3(Hdim / 32, Bsz / 64), 256>>>(
            ih, il, oh, ol, cbuf, xpart, embproj, hs_hi, hs_lo,
            whh_hi, whh_lo, atomtr, t);
    }

    // logits = hs @ W_out^T + b_out   [16384, 512]
    logits_mma<<<dim3(NTAG / 128, (Tlen * Bsz) / 64), 256>>>(
        hs_hi, hs_lo, wout_hi, wout_lo, logits, b_out);

    nll_rows<<<Tlen * Bsz, 128>>>(logits, atomtr, mask, rownll, rowmask);
    final_reduce<<<1, 256>>>(rownll, rowmask, (float*)d_out);
}

// round 7
// speedup vs baseline: 2.3555x; 1.0154x over previous
#include <cuda_runtime.h>
#include <cuda_bf16.h>
#include <math.h>

#define Bsz  256
#define Tlen 64
#define Hdim 1024
#define Xdim 512
#define Edim 256
#define DIN  768
#define G4   4096
#define NTAG 512

// ---- scratch layout ----
// floats:
//   xpart   @0          (1,048,576)
//   embproj @1,048,576  (2,097,152)
//   logits  @3,407,872  (8,388,608)
//   rownll  @11,796,480 (16,384)
//   rowmask @11,812,864 (16,384)
// bf16 region at float offset 11,829,248 (bf16-element offsets):
//   whh_hi 0            whh_lo 4,194,304
//   wout_hi 8,388,608   wout_lo 8,912,896
//   hA_hi 9,437,184  hA_lo 9,699,328  hB_hi 9,961,472  hB_lo 10,223,616
//   hs_hi 10,485,760 (16,777,216)   hs_lo 27,262,976 (16,777,216)
__device__ float g_scratch[33849344];
__device__ int   g_mask_mode;
__device__ unsigned g_bar_arrive;
__device__ unsigned g_bar_gen;

// ---------------------------------------------------------------------------
// PTX helpers
// ---------------------------------------------------------------------------
#define MMA4(c, a, b0_, b1_) \
    asm volatile("mma.sync.aligned.m16n8k16.row.col.f32.bf16.bf16.f32 " \
                 "{%0,%1,%2,%3},{%4,%5,%6,%7},{%8,%9},{%0,%1,%2,%3};" \
                 : "+f"((c)[0]), "+f"((c)[1]), "+f"((c)[2]), "+f"((c)[3]) \
                 : "r"((a)[0]), "r"((a)[1]), "r"((a)[2]), "r"((a)[3]), \
                   "r"(b0_), "r"(b1_))

#define LDSM4(r, addr) \
    asm volatile("ldmatrix.sync.aligned.m8n8.x4.shared.b16 {%0,%1,%2,%3}, [%4];" \
                 : "=r"((r)[0]), "=r"((r)[1]), "=r"((r)[2]), "=r"((r)[3]) \
                 : "r"(addr))

#define CP16(dst, src) \
    asm volatile("cp.async.cg.shared.global [%0], [%1], 16;" :: "r"(dst), "l"(src))
#define CPCOMMIT() asm volatile("cp.async.commit_group;" ::: "memory")
#define CPWAIT(n)  asm volatile("cp.async.wait_group %0;" :: "n"(n) : "memory")

#define FFMA2(d, a, b) asm("fma.rn.f32x2 %0, %1, %2, %0;" : "+l"(d) : "l"(a), "l"(b))
union F2U { unsigned long long u; float2 f; };
__device__ __forceinline__ unsigned long long dup2(float a) {
    unsigned x = __float_as_uint(a);
    return ((unsigned long long)x << 32) | (unsigned long long)x;
}

__device__ __forceinline__ void bf16split(float v, __nv_bfloat16& hi, __nv_bfloat16& lo) {
    hi = __float2bfloat16_rn(v);
    lo = __float2bfloat16_rn(v - __bfloat162float(hi));
}

// ---------------------------------------------------------------------------
// Shared 64m x 128n x 1024k bf16-split MMA mainloop.
// Stage layout per stage s (30720 B): Ahi[64][40] @0, Alo @5120,
// Bhi[128][40] @10240, Blo @20480. 3 stages (92160 B dynamic smem).
// gA*/gB* are pre-offset per-thread cp.async source pointers.
// ---------------------------------------------------------------------------
__device__ __forceinline__ void mma_mainloop(
    const __nv_bfloat16* __restrict__ gAh, const __nv_bfloat16* __restrict__ gAl,
    const __nv_bfloat16* __restrict__ gBh, const __nv_bfloat16* __restrict__ gBl,
    unsigned smem_u, int tid, float acc[2][4][4])
{
    const int lane = tid & 31, w = tid >> 5;
    const int wm = w & 1, wn = w >> 1;
    const int lrow = (lane & 7) + ((lane >> 3) & 1) * 8;
    const int lcol = (lane >> 4) * 8;
    const unsigned aoff = ((wm * 32 + lrow) * 40 + lcol) * 2;
    const unsigned boff = ((wn * 32 + lrow) * 40 + lcol) * 2;

    const int ar = tid >> 2, akc = (tid & 3) * 8;
    const int br = tid >> 1, bkc = (tid & 1) * 16;
    (void)akc; (void)bkc;
    const unsigned dA  = (ar * 40 + (tid & 3) * 8) * 2;
    const unsigned dB0 = (br * 40 + (tid & 1) * 16) * 2;
    const unsigned dB1 = dB0 + 16;

    // prologue: stages 0,1
    #pragma unroll
    for (int s = 0; s < 2; s++) {
        unsigned sb = smem_u + s * 30720;
        int k0 = s * 32;
        CP16(sb + dA,          gAh + k0);
        CP16(sb + 5120  + dA,  gAl + k0);
        CP16(sb + 10240 + dB0, gBh + k0);
        CP16(sb + 10240 + dB1, gBh + k0 + 8);
        CP16(sb + 20480 + dB0, gBl + k0);
        CP16(sb + 20480 + dB1, gBl + k0 + 8);
        CPCOMMIT();
    }

    for (int i = 0; i < 32; i++) {
        if (i < 31) { CPWAIT(1); } else { CPWAIT(0); }
        __syncthreads();
        if (i + 2 < 32) {
            unsigned sb = smem_u + ((i + 2) % 3) * 30720;
            int k0 = (i + 2) * 32;
            CP16(sb + dA,          gAh + k0);
            CP16(sb + 5120  + dA,  gAl + k0);
            CP16(sb + 10240 + dB0, gBh + k0);
            CP16(sb + 10240 + dB1, gBh + k0 + 8);
            CP16(sb + 20480 + dB0, gBl + k0);
            CP16(sb + 20480 + dB1, gBl + k0 + 8);
            CPCOMMIT();
        }
        unsigned sb = smem_u + (i % 3) * 30720;
        #pragma unroll
        for (int kh = 0; kh < 2; kh++) {
            const unsigned kb = kh * 32;
            unsigned a0[4], a1[4], l0[4], l1[4];
            LDSM4(a0, sb + aoff + kb);
            LDSM4(a1, sb + aoff + 1280 + kb);
            LDSM4(l0, sb + 5120 + aoff + kb);
            LDSM4(l1, sb + 5120 + aoff + 1280 + kb);
            unsigned bh0[4], bh1[4], bl0[4], bl1[4];
            LDSM4(bh0, sb + 10240 + boff + kb);
            LDSM4(bh1, sb + 10240 + boff + 1280 + kb);
            LDSM4(bl0, sb + 20480 + boff + kb);
            LDSM4(bl1, sb + 20480 + boff + 1280 + kb);
            #pragma unroll
            for (int nt = 0; nt < 4; nt++) {
                const unsigned* bhp = (nt < 2) ? bh0 : bh1;
                const unsigned* blp = (nt < 2) ? bl0 : bl1;
                unsigned h0v = bhp[nt & 1], h1v = bhp[(nt & 1) + 2];
                unsigned l0v = blp[nt & 1], l1v = blp[(nt & 1) + 2];
                MMA4(acc[0][nt], a0, h0v, h1v);
                MMA4(acc[0][nt], a0, l0v, l1v);
                MMA4(acc[0][nt], l0, h0v, h1v);
                MMA4(acc[1][nt], a1, h0v, h1v);
                MMA4(acc[1][nt], a1, l0v, l1v);
                MMA4(acc[1][nt], l1, h0v, h1v);
            }
        }
    }
}

// ---------------------------------------------------------------------------
// Split kernels
// ---------------------------------------------------------------------------
__global__ void split_whh(const float* __restrict__ W,
                          __nv_bfloat16* __restrict__ hi,
                          __nv_bfloat16* __restrict__ lo)
{
    int c = blockIdx.x;
    int j = c >> 2, g = c & 3;
    const float* src = W + (size_t)(g * Hdim + j) * Hdim;
    int k = threadIdx.x * 4;
    float4 v = *(const float4*)&src[k];
    size_t o = (size_t)c * Hdim + k;
    float a[4] = {v.x, v.y, v.z, v.w};
    #pragma unroll
    for (int q = 0; q < 4; q++) bf16split(a[q], hi[o + q], lo[o + q]);
}

__global__ void split_plain(const float* __restrict__ W,
                            __nv_bfloat16* __restrict__ hi,
                            __nv_bfloat16* __restrict__ lo)
{
    int r = blockIdx.x;
    const float* src = W + (size_t)r * Hdim;
    int k = threadIdx.x * 4;
    float4 v = *(const float4*)&src[k];
    size_t o = (size_t)r * Hdim + k;
    float a[4] = {v.x, v.y, v.z, v.w};
    #pragma unroll
    for (int q = 0; q < 4; q++) bf16split(a[q], hi[o + q], lo[o + q]);
}

// ---------------------------------------------------------------------------
// f32x2 SGEMM (xpart / embproj): C[M,N] = A[M,K] @ B[N,K]^T (+b0)(+b1)
// ---------------------------------------------------------------------------
__global__ __launch_bounds__(256) void sgemm2(
    const float* __restrict__ A, int lda,
    const float* __restrict__ Bm, int ldb,
    float* __restrict__ C, int ldc, int K,
    const float* __restrict__ bias0,
    const float* __restrict__ bias1)
{
    __shared__ unsigned long long As2[16][128];
    __shared__ float Bs[16][64];
    const int m0 = blockIdx.y * 128;
    const int n0 = blockIdx.x * 64;
    const int tid = threadIdx.x;
    const int rg = tid >> 4;
    const int cg = tid & 15;
    unsigned long long acc[8][2];
    #pragma unroll
    for (int i = 0; i < 8; i++) { acc[i][0] = 0ull; acc[i][1] = 0ull; }
    const int fm = tid >> 2;
    const int fk = (tid & 3) * 4;

    for (int k0 = 0; k0 < K; k0 += 16) {
        __syncthreads();
        #pragma unroll
        for (int half = 0; half < 2; half++) {
            int m = fm + half * 64;
            float4 v = *(const float4*)&A[(size_t)(m0 + m) * lda + k0 + fk];
            As2[fk + 0][m] = dup2(v.x);
            As2[fk + 1][m] = dup2(v.y);
            As2[fk + 2][m] = dup2(v.z);
            As2[fk + 3][m] = dup2(v.w);
        }
        {
            float4 v = *(const float4*)&Bm[(size_t)(n0 + fm) * ldb + k0 + fk];
            Bs[fk + 0][fm] = v.x; Bs[fk + 1][fm] = v.y;
            Bs[fk + 2][fm] = v.z; Bs[fk + 3][fm] = v.w;
        }
        __syncthreads();
        #pragma unroll
        for (int k = 0; k < 16; k++) {
            const ulonglong2* ap = (const ulonglong2*)&As2[k][rg * 8];
            ulonglong2 bv = *(const ulonglong2*)&Bs[k][cg * 4];
            #pragma unroll
            for (int i2 = 0; i2 < 4; i2++) {
                ulonglong2 a = ap[i2];
                FFMA2(acc[2 * i2 + 0][0], a.x, bv.x);
                FFMA2(acc[2 * i2 + 0][1], a.x, bv.y);
                FFMA2(acc[2 * i2 + 1][0], a.y, bv.x);
                FFMA2(acc[2 * i2 + 1][1], a.y, bv.y);
            }
        }
    }
    #pragma unroll
    for (int i = 0; i < 8; i++) {
        int m = m0 + rg * 8 + i;
        #pragma unroll
        for (int p = 0; p < 2; p++) {
            int n = n0 + cg * 4 + p * 2;
            F2U u; u.u = acc[i][p];
            float v0 = u.f.x, v1 = u.f.y;
            if (bias0) { v0 += bias0[n]; v1 += bias0[n + 1]; }
            if (bias1) { v0 += bias1[n]; v1 += bias1[n + 1]; }
            *(float2*)&C[(size_t)m * ldc + n] = make_float2(v0, v1);
        }
    }
}

// ---------------------------------------------------------------------------
// Persistent LSTM kernel: all 64 steps, grid=128 blocks (1/SM, co-resident),
// c state in registers, grid barrier between steps.
// ---------------------------------------------------------------------------
__global__ void init_bar() { g_bar_arrive = 0; g_bar_gen = 0; }

__device__ __forceinline__ void grid_sync(int tid, unsigned gen)
{
    __syncthreads();
    if (tid == 0) {
        __threadfence();
        unsigned a = atomicAdd(&g_bar_arrive, 1);
        if (a == 127) {
            g_bar_arrive = 0;
            __threadfence();
            atomicExch(&g_bar_gen, gen);
        } else {
            while (atomicAdd(&g_bar_gen, 0u) < gen) __nanosleep(64);
            __threadfence();
        }
    }
    __syncthreads();
}

__global__ __launch_bounds__(256, 1) void lstm_persistent(
    __nv_bfloat16* hA_hi, __nv_bfloat16* hA_lo,
    __nv_bfloat16* hB_hi, __nv_bfloat16* hB_lo,
    const float* __restrict__ c0,
    const float* __restrict__ xpart,
    const float* __restrict__ embproj,
    __nv_bfloat16* __restrict__ hshi,
    __nv_bfloat16* __restrict__ hslo,
    const __nv_bfloat16* __restrict__ whhhi,
    const __nv_bfloat16* __restrict__ whhlo,
    const int* __restrict__ atom_truth)
{
    extern __shared__ __align__(16) unsigned char dsm[];
    unsigned smem_u = (unsigned)__cvta_generic_to_shared(dsm);
    float* Gs = (float*)dsm;     // [64][132], aliases stage buffers after loop

    const int bx = blockIdx.x;
    const int j0 = (bx & 31) * 32;
    const int b0 = (bx >> 5) * 64;
    const int gcol0 = j0 * 4;
    const int tid = threadIdx.x;
    const int lane = tid & 31, w = tid >> 5;
    const int wm = w & 1, wn = w >> 1;
    const int qr = lane >> 2, qk = (lane & 3) * 2;
    const int ar = tid >> 2, akc = (tid & 3) * 8;
    const int br = tid >> 1, bkc = (tid & 1) * 16;

    const __nv_bfloat16* gBh = whhhi + (size_t)(gcol0 + br) * Hdim + bkc;
    const __nv_bfloat16* gBl = whhlo + (size_t)(gcol0 + br) * Hdim + bkc;

    // c state in registers for the whole sequence (block owns fixed (b,j) tile)
    float creg[8];
    #pragma unroll
    for (int i = 0; i < 8; i++) {
        int idx = tid + i * 256;
        creg[i] = c0[(b0 + (idx >> 5)) * Hdim + j0 + (idx & 31)];
    }

    for (int t = 0; t < Tlen; t++) {
        const __nv_bfloat16* hih = (t & 1) ? hB_hi : hA_hi;
        const __nv_bfloat16* hil = (t & 1) ? hB_lo : hA_lo;
        __nv_bfloat16* hoh = (t & 1) ? hA_hi : hB_hi;
        __nv_bfloat16* hol = (t & 1) ? hA_lo : hB_lo;

        float acc[2][4][4];
        #pragma unroll
        for (int mt = 0; mt < 2; mt++)
            #pragma unroll
            for (int nt = 0; nt < 4; nt++)
                #pragma unroll
                for (int q = 0; q < 4; q++) acc[mt][nt][q] = 0.f;

        mma_mainloop(hih + (size_t)(b0 + ar) * Hdim + akc,
                     hil + (size_t)(b0 + ar) * Hdim + akc,
                     gBh, gBl, smem_u, tid, acc);

        __syncthreads();   // all warps done with stage smem -> alias as Gs
        #pragma unroll
        for (int mt = 0; mt < 2; mt++)
            #pragma unroll
            for (int nt = 0; nt < 4; nt++) {
                int r = wm * 32 + mt * 16 + qr;
                int cc = wn * 32 + nt * 8 + qk;
                *(float2*)&Gs[r * 132 + cc]       = make_float2(acc[mt][nt][0], acc[mt][nt][1]);
                *(float2*)&Gs[(r + 8) * 132 + cc] = make_float2(acc[mt][nt][2], acc[mt][nt][3]);
            }
        __syncthreads();

        #pragma unroll
        for (int i = 0; i < 8; i++) {
            int idx = tid + i * 256;
            int bl = idx >> 5, jj = idx & 31;
            float4 gv = *(const float4*)&Gs[bl * 132 + jj * 4];   // (i,f,g,o)
            int b = b0 + bl, j = j0 + jj;
            int tok = (t == 0) ? 0 : atom_truth[b * Tlen + (t - 1)];
            const float* xp = xpart + (size_t)b * G4 + j;
            const float* ep = embproj + (size_t)tok * G4 + j;
            float ig = gv.x + xp[0]        + ep[0];
            float fg = gv.y + xp[Hdim]     + ep[Hdim];
            float gg = gv.z + xp[2 * Hdim] + ep[2 * Hdim];
            float og = gv.w + xp[3 * Hdim] + ep[3 * Hdim];
            ig = 1.f / (1.f + expf(-ig));
            fg = 1.f / (1.f + expf(-fg));
            og = 1.f / (1.f + expf(-og));
            gg = tanhf(gg);
            float cv = fg * creg[i] + ig * gg;
            creg[i] = cv;
            float hv = og * tanhf(cv);
            __nv_bfloat16 hh, hl;
            bf16split(hv, hh, hl);
            hoh[b * Hdim + j] = hh;
            hol[b * Hdim + j] = hl;
            size_t ho = ((size_t)t * Bsz + b) * Hdim + j;
            hshi[ho] = hh;
            hslo[ho] = hl;
        }

        if (t < Tlen - 1) grid_sync(tid, (unsigned)(t + 1));
    }
}

// ---------------------------------------------------------------------------
// Logits GEMM: C[16384,512] = hs @ W_out^T + b_out, same mainloop.
// Grid (512/128, 16384/64) = (4, 256).
// ---------------------------------------------------------------------------
__global__ __launch_bounds__(256) void logits_mma(
    const __nv_bfloat16* __restrict__ Ahi_g,
    const __nv_bfloat16* __restrict__ Alo_g,
    const __nv_bfloat16* __restrict__ Bhi_g,
    const __nv_bfloat16* __restrict__ Blo_g,
    float* __restrict__ C,
    const float* __restrict__ bias)
{
    extern __shared__ __align__(16) unsigned char dsm[];
    unsigned smem_u = (unsigned)__cvta_generic_to_shared(dsm);

    const int n0 = blockIdx.x * 128;
    const int m0 = blockIdx.y * 64;
    const int tid = threadIdx.x;
    const int lane = tid & 31, w = tid >> 5;
    const int wm = w & 1, wn = w >> 1;
    const int qr = lane >> 2, qk = (lane & 3) * 2;
    const int ar = tid >> 2, akc = (tid & 3) * 8;
    const int br = tid >> 1, bkc = (tid & 1) * 16;

    float acc[2][4][4];
    #pragma unroll
    for (int mt = 0; mt < 2; mt++)
        #pragma unroll
        for (int nt = 0; nt < 4; nt++)
            #pragma unroll
            for (int q = 0; q < 4; q++) acc[mt][nt][q] = 0.f;

    mma_mainloop(Ahi_g + (size_t)(m0 + ar) * Hdim + akc,
                 Alo_g + (size_t)(m0 + ar) * Hdim + akc,
                 Bhi_g + (size_t)(n0 + br) * Hdim + bkc,
                 Blo_g + (size_t)(n0 + br) * Hdim + bkc,
                 smem_u, tid, acc);

    #pragma unroll
    for (int mt = 0; mt < 2; mt++)
        #pragma unroll
        for (int nt = 0; nt < 4; nt++) {
            int m = m0 + wm * 32 + mt * 16 + qr;
            int n = n0 + wn * 32 + nt * 8 + qk;
            float b0v = bias[n], b1v = bias[n + 1];
            *(float2*)&C[(size_t)m * NTAG + n] =
                make_float2(acc[mt][nt][0] + b0v, acc[mt][nt][1] + b1v);
            *(float2*)&C[(size_t)(m + 8) * NTAG + n] =
                make_float2(acc[mt][nt][2] + b0v, acc[mt][nt][3] + b1v);
        }
}

// ---------------------------------------------------------------------------
// Mask detection / NLL / reduction
// ---------------------------------------------------------------------------
__global__ void detect_mask(const unsigned* __restrict__ m)
{
    __shared__ int isByte, isFloat;
    if (threadIdx.x == 0) { isByte = 0; isFloat = 0; }
    __syncthreads();
    for (int i = threadIdx.x; i < (Bsz * Tlen) / 4; i += blockDim.x) {
        unsigned v = m[i];
        if (v == 0x3F800000u) isFloat = 1;
        else if (v > 1u) isByte = 1;
    }
    __syncthreads();
    if (threadIdx.x == 0) g_mask_mode = isFloat ? 2 : (isByte ? 1 : 0);
}

__global__ __launch_bounds__(128) void nll_rows(
    const float* __restrict__ logits,
    const int* __restrict__ atom_truth,
    const void* __restrict__ atom_mask,
    float* __restrict__ rownll,
    float* __restrict__ rowmask)
{
    const int r = blockIdx.x;
    const int t = r >> 8;
    const int b = r & 255;
    const float* row = logits + (size_t)r * NTAG;
    const int tid = threadIdx.x;
    __shared__ float red[128];

    float mx = -1e30f;
    for (int i = tid; i < NTAG; i += 128) mx = fmaxf(mx, row[i]);
    red[tid] = mx; __syncthreads();
    for (int s = 64; s > 0; s >>= 1) {
        if (tid < s) red[tid] = fmaxf(red[tid], red[tid + s]);
        __syncthreads();
    }
    mx = red[0]; __syncthreads();

    float sm = 0.f;
    for (int i = tid; i < NTAG; i += 128) sm += expf(row[i] - mx);
    red[tid] = sm; __syncthreads();
    for (int s = 64; s > 0; s >>= 1) {
        if (tid < s) red[tid] += red[tid + s];
        __syncthreads();
    }

    if (tid == 0) {
        int tgt = atom_truth[b * Tlen + t];
        float lp = row[tgt] - mx - logf(red[0]);
        int mode = g_mask_mode;
        float m;
        if (mode == 2)      m = (((const float*)atom_mask)[b * Tlen + t] != 0.f) ? 1.f : 0.f;
        else if (mode == 1) m = (((const unsigned char*)atom_mask)[b * Tlen + t] != 0) ? 1.f : 0.f;
        else                m = (((const int*)atom_mask)[b * Tlen + t] != 0) ? 1.f : 0.f;
        rownll[r]  = -lp * m;
        rowmask[r] = m;
    }
}

__global__ __launch_bounds__(256) void final_reduce(
    const float* __restrict__ rownll,
    const float* __restrict__ rowmask,
    float* __restrict__ out)
{
    __shared__ double rn[256], rm[256];
    double sn = 0.0, sm = 0.0;
    for (int i = threadIdx.x; i < Tlen * Bsz; i += 256) {
        sn += (double)rownll[i];
        sm += (double)rowmask[i];
    }
    rn[threadIdx.x] = sn; rm[threadIdx.x] = sm;
    __syncthreads();
    for (int s = 128; s > 0; s >>= 1) {
        if (threadIdx.x < s) {
            rn[threadIdx.x] += rn[threadIdx.x + s];
            rm[threadIdx.x] += rm[threadIdx.x + s];
        }
        __syncthreads();
    }
    if (threadIdx.x == 0) out[0] = (float)(rn[0] / rm[0]);
}

// ---------------------------------------------------------------------------
// Launch
// ---------------------------------------------------------------------------
extern "C" void kernel_launch(void* const* d_in, const int* in_sizes, int n_in,
                              void* d_out, int out_size)
{
    const float* x      = (const float*)d_in[0];
    const int*   atomtr = (const int*)d_in[1];
    const void*  mask   = d_in[2];
    const float* emb    = (const float*)d_in[3];
    const float* W_ih   = (const float*)d_in[4];
    const float* W_hh   = (const float*)d_in[5];
    const float* b_ih   = (const float*)d_in[6];
    const float* b_hh   = (const float*)d_in[7];
    const float* W_out  = (const float*)d_in[8];
    const float* b_out  = (const float*)d_in[9];
    const float* h0     = (const float*)d_in[10];
    const float* c0     = (const float*)d_in[11];

    float* sc = nullptr;
    cudaGetSymbolAddress((void**)&sc, g_scratch);
    float* xpart   = sc + 0;
    float* embproj = sc + 1048576;
    float* logits  = sc + 3407872;
    float* rownll  = sc + 11796480;
    float* rowmask = sc + 11812864;
    __nv_bfloat16* bb = (__nv_bfloat16*)(sc + 11829248);
    __nv_bfloat16* whh_hi  = bb + 0;
    __nv_bfloat16* whh_lo  = bb + 4194304;
    __nv_bfloat16* wout_hi = bb + 8388608;
    __nv_bfloat16* wout_lo = bb + 8912896;
    __nv_bfloat16* hA_hi   = bb + 9437184;
    __nv_bfloat16* hA_lo   = bb + 9699328;
    __nv_bfloat16* hB_hi   = bb + 9961472;
    __nv_bfloat16* hB_lo   = bb + 10223616;
    __nv_bfloat16* hs_hi   = bb + 10485760;
    __nv_bfloat16* hs_lo   = bb + 27262976;

    const int DSMEM = 3 * 30720;   // 92160 B
    static int attr_done = 0;
    if (!attr_done) {
        cudaFuncSetAttribute(lstm_persistent, cudaFuncAttributeMaxDynamicSharedMemorySize, DSMEM);
        cudaFuncSetAttribute(logits_mma,      cudaFuncAttributeMaxDynamicSharedMemorySize, DSMEM);
        attr_done = 1;
    }

    detect_mask<<<1, 256>>>((const unsigned*)mask);
    init_bar<<<1, 1>>>();

    // one-time weight / state splits
    split_whh<<<4096, 256>>>(W_hh, whh_hi, whh_lo);
    split_plain<<<512, 256>>>(W_out, wout_hi, wout_lo);
    split_plain<<<256, 256>>>(h0, hA_hi, hA_lo);

    // xpart = x @ W_ih[:, :512]^T + b_ih + b_hh   [256, 4096]
    sgemm2<<<dim3(G4 / 64, Bsz / 128), 256>>>(x, Xdim, W_ih, DIN, xpart, G4, Xdim, b_ih, b_hh);
    // embproj = emb @ W_ih[:, 512:768]^T          [512, 4096]
    sgemm2<<<dim3(G4 / 64, NTAG / 128), 256>>>(emb, Edim, W_ih + Xdim, DIN, embproj, G4, Edim, nullptr, nullptr);

    // all 64 LSTM steps in one persistent kernel
    lstm_persistent<<<128, 256, DSMEM>>>(
        hA_hi, hA_lo, hB_hi, hB_lo, c0, xpart, embproj,
        hs_hi, hs_lo, whh_hi, whh_lo, atomtr);

    // logits = hs @ W_out^T + b_out   [16384, 512]
    logits_mma<<<dim3(NTAG / 128, (Tlen * Bsz) / 64), 256, DSMEM>>>(
        hs_hi, hs_lo, wout_hi, wout_lo, logits, b_out);

    nll_rows<<<Tlen * Bsz, 128>>>(logits, atomtr, mask, rownll, rowmask);
    final_reduce<<<1, 256>>>(rownll, rowmask, (float*)d_out);
}

// round 9
// speedup vs baseline: 3.2786x; 1.3919x over previous
#include <cuda_runtime.h>
#include <cuda_bf16.h>
#include <math.h>

#define Bsz  256
#define Tlen 64
#define Hdim 1024
#define Xdim 512
#define Edim 256
#define DIN  768
#define G4   4096
#define NTAG 512

// ---- scratch layout ----
// floats:
//   xpart   @0          (1,048,576)
//   embproj @1,048,576  (2,097,152)
//   logits  @3,407,872  (8,388,608)
//   rownll  @11,796,480 (16,384)
//   rowmask @11,812,864 (16,384)
// bf16 region at float offset 11,829,248 (bf16-element offsets):
//   whh_hi 0            whh_lo 4,194,304
//   wout_hi 8,388,608   wout_lo 8,912,896
//   hA_hi 9,437,184  hA_lo 9,699,328  hB_hi 9,961,472  hB_lo 10,223,616
//   hs_hi 10,485,760 (16,777,216)   hs_lo 27,262,976 (16,777,216)
__device__ float g_scratch[33849344];
__device__ int   g_mask_mode;
__device__ unsigned g_bar_arrive;
__device__ unsigned g_bar_gen;

// ---------------------------------------------------------------------------
// PTX helpers (portable: mma.sync / ldmatrix / cp.async)
// ---------------------------------------------------------------------------
#define MMA4(c, a, b0_, b1_) \
    asm volatile("mma.sync.aligned.m16n8k16.row.col.f32.bf16.bf16.f32 " \
                 "{%0,%1,%2,%3},{%4,%5,%6,%7},{%8,%9},{%0,%1,%2,%3};" \
                 : "+f"((c)[0]), "+f"((c)[1]), "+f"((c)[2]), "+f"((c)[3]) \
                 : "r"((a)[0]), "r"((a)[1]), "r"((a)[2]), "r"((a)[3]), \
                   "r"(b0_), "r"(b1_))

#define LDSM4(r, addr) \
    asm volatile("ldmatrix.sync.aligned.m8n8.x4.shared.b16 {%0,%1,%2,%3}, [%4];" \
                 : "=r"((r)[0]), "=r"((r)[1]), "=r"((r)[2]), "=r"((r)[3]) \
                 : "r"(addr))

#define CP16(dst, src) \
    asm volatile("cp.async.cg.shared.global [%0], [%1], 16;" :: "r"(dst), "l"(src))
#define CPCOMMIT() asm volatile("cp.async.commit_group;" ::: "memory")
#define CPWAIT(n)  asm volatile("cp.async.wait_group %0;" :: "n"(n) : "memory")

#define FFMA2(d, a, b) asm("fma.rn.f32x2 %0, %1, %2, %0;" : "+l"(d) : "l"(a), "l"(b))
union F2U { unsigned long long u; float2 f; };
__device__ __forceinline__ unsigned long long dup2(float a) {
    unsigned x = __float_as_uint(a);
    return ((unsigned long long)x << 32) | (unsigned long long)x;
}

__device__ __forceinline__ void bf16split(float v, __nv_bfloat16& hi, __nv_bfloat16& lo) {
    hi = __float2bfloat16_rn(v);
    lo = __float2bfloat16_rn(v - __bfloat162float(hi));
}

__device__ __forceinline__ unsigned smem_u32(const void* p) {
    return (unsigned)__cvta_generic_to_shared(p);
}

// ---------------------------------------------------------------------------
// tcgen05 helpers — ONLY compiled on the sm_100a ("arch-accelerated") pass.
// ---------------------------------------------------------------------------
#if defined(__CUDA_ARCH_FEAT_SM100_ALL)
__device__ __forceinline__ bool elect1() {
    unsigned p;
    asm volatile("{\n\t.reg .pred p;\n\telect.sync _|p, 0xFFFFFFFF;\n\tselp.b32 %0,1,0,p;\n\t}"
                 : "=r"(p));
    return p != 0;
}
__device__ __forceinline__ unsigned long long mk_desc(unsigned addr) {
    // SW128, version=1 (Blackwell), SBO=64, LBO=1 (K-major, 128B rows)
    return 0x4000404000010000ULL | ((unsigned long long)(addr >> 4) & 0x3FFF);
}
__device__ __forceinline__ void tc_mma_f16_ss(unsigned d, unsigned long long ad,
                                              unsigned long long bd, unsigned idesc,
                                              unsigned en)
{
    asm volatile(
        "{\n\t.reg .pred p;\n\tsetp.ne.u32 p, %5, 0;\n\t"
        "tcgen05.mma.cta_group::1.kind::f16 [%0], %1, %2, %3, {%4, %4, %4, %4}, p;\n\t}"
        :: "r"(d), "l"(ad), "l"(bd), "r"(idesc), "r"(0u), "r"(en)
        : "memory");
}
#define TC_ALLOC(smaddr, n) \
    asm volatile("tcgen05.alloc.cta_group::1.sync.aligned.shared::cta.b32 [%0], %1;" \
                 :: "r"(smaddr), "r"((unsigned)(n)) : "memory")
#define TC_DEALLOC(base, n) \
    asm volatile("tcgen05.dealloc.cta_group::1.sync.aligned.b32 %0, %1;" \
                 :: "r"(base), "r"((unsigned)(n)))
#define TC_COMMIT(mb) \
    asm volatile("tcgen05.commit.cta_group::1.mbarrier::arrive::one.shared::cluster.b64 [%0];" \
                 :: "r"(mb) : "memory")
#define TC_FENCE_AFTER()  asm volatile("tcgen05.fence::after_thread_sync;" ::: "memory")
#define TC_FENCE_BEFORE() asm volatile("tcgen05.fence::before_thread_sync;" ::: "memory")
#define TC_WAIT_LD()      asm volatile("tcgen05.wait::ld.sync.aligned;" ::: "memory")

#define MBAR_INIT(mb, cnt) \
    asm volatile("mbarrier.init.shared.b64 [%0], %1;" :: "r"(mb), "r"((unsigned)(cnt)) : "memory")
#define MBAR_WAIT(mb, par) do { \
    unsigned _m = (mb), _p = (par), _d; \
    asm volatile("{\n\t.reg .pred p;\n\t" \
                 "mbarrier.try_wait.parity.acquire.cta.shared::cta.b64 p, [%1], %2;\n\t" \
                 "selp.b32 %0,1,0,p;\n\t}" : "=r"(_d) : "r"(_m), "r"(_p) : "memory"); \
    if (!_d) { \
        asm volatile("{\n\t.reg .pred P1;\n\t" \
                     "WL%=:\n\t" \
                     "mbarrier.try_wait.parity.acquire.cta.shared::cta.b64 P1, [%0], %1, 0x989680;\n\t" \
                     "@P1 bra.uni WD%=;\n\tbra.uni WL%=;\n\tWD%=:\n\t}" \
                     :: "r"(_m), "r"(_p) : "memory"); \
    } \
} while(0)

#define TC_LD32(r, addr) \
    asm volatile("tcgen05.ld.sync.aligned.32x32b.x32.b32 " \
        "{%0,%1,%2,%3,%4,%5,%6,%7,%8,%9,%10,%11,%12,%13,%14,%15," \
        "%16,%17,%18,%19,%20,%21,%22,%23,%24,%25,%26,%27,%28,%29,%30,%31}, [%32];" \
        : "=r"((r)[0]),"=r"((r)[1]),"=r"((r)[2]),"=r"((r)[3]), \
          "=r"((r)[4]),"=r"((r)[5]),"=r"((r)[6]),"=r"((r)[7]), \
          "=r"((r)[8]),"=r"((r)[9]),"=r"((r)[10]),"=r"((r)[11]), \
          "=r"((r)[12]),"=r"((r)[13]),"=r"((r)[14]),"=r"((r)[15]), \
          "=r"((r)[16]),"=r"((r)[17]),"=r"((r)[18]),"=r"((r)[19]), \
          "=r"((r)[20]),"=r"((r)[21]),"=r"((r)[22]),"=r"((r)[23]), \
          "=r"((r)[24]),"=r"((r)[25]),"=r"((r)[26]),"=r"((r)[27]), \
          "=r"((r)[28]),"=r"((r)[29]),"=r"((r)[30]),"=r"((r)[31]) \
        : "r"(addr))

// idesc: f32 accum, bf16 a/b, M=128, N=64
#define TC_IDESC 0x08100490u
#endif // __CUDA_ARCH_FEAT_SM100_ALL

// ---------------------------------------------------------------------------
// Split kernels
// ---------------------------------------------------------------------------
__global__ void split_whh(const float* __restrict__ W,
                          __nv_bfloat16* __restrict__ hi,
                          __nv_bfloat16* __restrict__ lo)
{
    int c = blockIdx.x;
    int j = c >> 2, g = c & 3;
    const float* src = W + (size_t)(g * Hdim + j) * Hdim;
    int k = threadIdx.x * 4;
    float4 v = *(const float4*)&src[k];
    size_t o = (size_t)c * Hdim + k;
    float a[4] = {v.x, v.y, v.z, v.w};
    #pragma unroll
    for (int q = 0; q < 4; q++) bf16split(a[q], hi[o + q], lo[o + q]);
}

__global__ void split_plain(const float* __restrict__ W,
                            __nv_bfloat16* __restrict__ hi,
                            __nv_bfloat16* __restrict__ lo)
{
    int r = blockIdx.x;
    const float* src = W + (size_t)r * Hdim;
    int k = threadIdx.x * 4;
    float4 v = *(const float4*)&src[k];
    size_t o = (size_t)r * Hdim + k;
    float a[4] = {v.x, v.y, v.z, v.w};
    #pragma unroll
    for (int q = 0; q < 4; q++) bf16split(a[q], hi[o + q], lo[o + q]);
}

// ---------------------------------------------------------------------------
// f32x2 SGEMM (xpart / embproj): C[M,N] = A[M,K] @ B[N,K]^T (+b0)(+b1)
// ---------------------------------------------------------------------------
__global__ __launch_bounds__(256) void sgemm2(
    const float* __restrict__ A, int lda,
    const float* __restrict__ Bm, int ldb,
    float* __restrict__ C, int ldc, int K,
    const float* __restrict__ bias0,
    const float* __restrict__ bias1)
{
    __shared__ unsigned long long As2[16][128];
    __shared__ float Bs[16][64];
    const int m0 = blockIdx.y * 128;
    const int n0 = blockIdx.x * 64;
    const int tid = threadIdx.x;
    const int rg = tid >> 4;
    const int cg = tid & 15;
    unsigned long long acc[8][2];
    #pragma unroll
    for (int i = 0; i < 8; i++) { acc[i][0] = 0ull; acc[i][1] = 0ull; }
    const int fm = tid >> 2;
    const int fk = (tid & 3) * 4;

    for (int k0 = 0; k0 < K; k0 += 16) {
        __syncthreads();
        #pragma unroll
        for (int half = 0; half < 2; half++) {
            int m = fm + half * 64;
            float4 v = *(const float4*)&A[(size_t)(m0 + m) * lda + k0 + fk];
            As2[fk + 0][m] = dup2(v.x);
            As2[fk + 1][m] = dup2(v.y);
            As2[fk + 2][m] = dup2(v.z);
            As2[fk + 3][m] = dup2(v.w);
        }
        {
            float4 v = *(const float4*)&Bm[(size_t)(n0 + fm) * ldb + k0 + fk];
            Bs[fk + 0][fm] = v.x; Bs[fk + 1][fm] = v.y;
            Bs[fk + 2][fm] = v.z; Bs[fk + 3][fm] = v.w;
        }
        __syncthreads();
        #pragma unroll
        for (int k = 0; k < 16; k++) {
            const ulonglong2* ap = (const ulonglong2*)&As2[k][rg * 8];
            ulonglong2 bv = *(const ulonglong2*)&Bs[k][cg * 4];
            #pragma unroll
            for (int i2 = 0; i2 < 4; i2++) {
                ulonglong2 a = ap[i2];
                FFMA2(acc[2 * i2 + 0][0], a.x, bv.x);
                FFMA2(acc[2 * i2 + 0][1], a.x, bv.y);
                FFMA2(acc[2 * i2 + 1][0], a.y, bv.x);
                FFMA2(acc[2 * i2 + 1][1], a.y, bv.y);
            }
        }
    }
    #pragma unroll
    for (int i = 0; i < 8; i++) {
        int m = m0 + rg * 8 + i;
        #pragma unroll
        for (int p = 0; p < 2; p++) {
            int n = n0 + cg * 4 + p * 2;
            F2U u; u.u = acc[i][p];
            float v0 = u.f.x, v1 = u.f.y;
            if (bias0) { v0 += bias0[n]; v1 += bias0[n + 1]; }
            if (bias1) { v0 += bias1[n]; v1 += bias1[n + 1]; }
            *(float2*)&C[(size_t)m * ldc + n] = make_float2(v0, v1);
        }
    }
}

// ---------------------------------------------------------------------------
// mma.sync mainloop (logits GEMM + LSTM fallback path)
// ---------------------------------------------------------------------------
__device__ __forceinline__ void mma_mainloop(
    const __nv_bfloat16* __restrict__ gAh, const __nv_bfloat16* __restrict__ gAl,
    const __nv_bfloat16* __restrict__ gBh, const __nv_bfloat16* __restrict__ gBl,
    unsigned smem_u, int tid, float acc[2][4][4])
{
    const int lane = tid & 31, w = tid >> 5;
    const int wm = w & 1, wn = w >> 1;
    const int lrow = (lane & 7) + ((lane >> 3) & 1) * 8;
    const int lcol = (lane >> 4) * 8;
    const unsigned aoff = ((wm * 32 + lrow) * 40 + lcol) * 2;
    const unsigned boff = ((wn * 32 + lrow) * 40 + lcol) * 2;

    const int ar = tid >> 2;
    const int br = tid >> 1;
    const unsigned dA  = (ar * 40 + (tid & 3) * 8) * 2;
    const unsigned dB0 = (br * 40 + (tid & 1) * 16) * 2;
    const unsigned dB1 = dB0 + 16;

    #pragma unroll
    for (int s = 0; s < 2; s++) {
        unsigned sb = smem_u + s * 30720;
        int k0 = s * 32;
        CP16(sb + dA,          gAh + k0);
        CP16(sb + 5120  + dA,  gAl + k0);
        CP16(sb + 10240 + dB0, gBh + k0);
        CP16(sb + 10240 + dB1, gBh + k0 + 8);
        CP16(sb + 20480 + dB0, gBl + k0);
        CP16(sb + 20480 + dB1, gBl + k0 + 8);
        CPCOMMIT();
    }

    for (int i = 0; i < 32; i++) {
        if (i < 31) { CPWAIT(1); } else { CPWAIT(0); }
        __syncthreads();
        if (i + 2 < 32) {
            unsigned sb = smem_u + ((i + 2) % 3) * 30720;
            int k0 = (i + 2) * 32;
            CP16(sb + dA,          gAh + k0);
            CP16(sb + 5120  + dA,  gAl + k0);
            CP16(sb + 10240 + dB0, gBh + k0);
            CP16(sb + 10240 + dB1, gBh + k0 + 8);
            CP16(sb + 20480 + dB0, gBl + k0);
            CP16(sb + 20480 + dB1, gBl + k0 + 8);
            CPCOMMIT();
        }
        unsigned sb = smem_u + (i % 3) * 30720;
        #pragma unroll
        for (int kh = 0; kh < 2; kh++) {
            const unsigned kb = kh * 32;
            unsigned a0[4], a1[4], l0[4], l1[4];
            LDSM4(a0, sb + aoff + kb);
            LDSM4(a1, sb + aoff + 1280 + kb);
            LDSM4(l0, sb + 5120 + aoff + kb);
            LDSM4(l1, sb + 5120 + aoff + 1280 + kb);
            unsigned bh0[4], bh1[4], bl0[4], bl1[4];
            LDSM4(bh0, sb + 10240 + boff + kb);
            LDSM4(bh1, sb + 10240 + boff + 1280 + kb);
            LDSM4(bl0, sb + 20480 + boff + kb);
            LDSM4(bl1, sb + 20480 + boff + 1280 + kb);
            #pragma unroll
            for (int nt = 0; nt < 4; nt++) {
                const unsigned* bhp = (nt < 2) ? bh0 : bh1;
                const unsigned* blp = (nt < 2) ? bl0 : bl1;
                unsigned h0v = bhp[nt & 1], h1v = bhp[(nt & 1) + 2];
                unsigned l0v = blp[nt & 1], l1v = blp[(nt & 1) + 2];
                MMA4(acc[0][nt], a0, h0v, h1v);
                MMA4(acc[0][nt], a0, l0v, l1v);
                MMA4(acc[0][nt], l0, h0v, h1v);
                MMA4(acc[1][nt], a1, h0v, h1v);
                MMA4(acc[1][nt], a1, l0v, l1v);
                MMA4(acc[1][nt], l1, h0v, h1v);
            }
        }
    }
}

// ---------------------------------------------------------------------------
// Grid barrier
// ---------------------------------------------------------------------------
__global__ void init_bar() { g_bar_arrive = 0; g_bar_gen = 0; }

__device__ __forceinline__ void grid_sync(int tid, unsigned gen)
{
    __syncthreads();
    if (tid == 0) {
        __threadfence();
        unsigned a = atomicAdd(&g_bar_arrive, 1);
        if (a == 127) {
            g_bar_arrive = 0;
            __threadfence();
            atomicExch(&g_bar_gen, gen);
        } else {
            while (atomicAdd(&g_bar_gen, 0u) < gen) __nanosleep(64);
            __threadfence();
        }
    }
    __syncthreads();
}

#define STG_SZ 49152   // tcgen05 stage: Ahi 16K @0, Alo @16384, Bhi 8K @32768, Blo @40960
#define DSMEM_LSTM (4 * STG_SZ)   // 196608

// ---------------------------------------------------------------------------
// Persistent LSTM sequence kernel — dual path:
//   sm_100a pass:   tcgen05 SS-MMA with TMEM accumulators
//   plain pass:     mma.sync fallback (proven R7 body)
// Launch: grid=128, block=256, dsmem=196608 for BOTH paths.
// ---------------------------------------------------------------------------
__global__ __launch_bounds__(256, 1) void lstm_seq(
    __nv_bfloat16* hA_hi, __nv_bfloat16* hA_lo,
    __nv_bfloat16* hB_hi, __nv_bfloat16* hB_lo,
    const float* __restrict__ c0,
    const float* __restrict__ xpart,
    const float* __restrict__ embproj,
    __nv_bfloat16* __restrict__ hshi,
    __nv_bfloat16* __restrict__ hslo,
    const __nv_bfloat16* __restrict__ whhhi,
    const __nv_bfloat16* __restrict__ whhlo,
    const int* __restrict__ atom_truth)
{
#if defined(__CUDA_ARCH_FEAT_SM100_ALL)
    // ======================= tcgen05 path =======================
    // Block bx: mt=bx>>6 (batch tile of 128), ntb=bx&63 (64 gate-cols =
    // 16 j x 4 gates, W rows pre-interleaved c=j*4+g).
    extern __shared__ __align__(1024) unsigned char dsm[];
    __shared__ unsigned s_tmem;
    __shared__ __align__(8) unsigned long long s_mbar[4];

    const unsigned smem_u = smem_u32(dsm);
    const int tid = threadIdx.x;
    const int wid = tid >> 5, lane = tid & 31;
    const int bx = blockIdx.x;
    const int b0 = (bx >> 6) * 128;
    const int ntb = bx & 63;
    const int c0g = ntb * 64;
    const int jb = ntb * 16;

    if (tid == 0) {
        #pragma unroll
        for (int i = 0; i < 4; i++) MBAR_INIT(smem_u32(&s_mbar[i]), 1);
    }
    __syncthreads();
    if (wid == 0) TC_ALLOC(smem_u32(&s_tmem), 512);
    __syncthreads();
    const unsigned tmem = s_tmem;
    unsigned mbu[4];
    #pragma unroll
    for (int i = 0; i < 4; i++) mbu[i] = smem_u32(&s_mbar[i]);
    int ph[4] = {0, 0, 0, 0};

    // fill geometry (256 threads, 12 CP16/thread/stage)
    const int ra = tid >> 1, ca = (tid & 1) * 4;       // A: row, 4 chunks
    const int rb = tid >> 2, cbb = (tid & 3) * 2;      // B: row, 2 chunks
    const int ram = ra & 7, rbm = rb & 7;
    const __nv_bfloat16* Bsrc_h = whhhi + (size_t)(c0g + rb) * Hdim;
    const __nv_bfloat16* Bsrc_l = whhlo + (size_t)(c0g + rb) * Hdim;

    // epilogue geometry: warp w -> rows (w&3)*32+lane, j-half (w>>2)*8
    const int b = b0 + (wid & 3) * 32 + lane;
    const int jh = (wid >> 2) * 8;
    float creg[8];
    {
        const float* cp = c0 + (size_t)b * Hdim + jb + jh;
        float4 v0 = *(const float4*)&cp[0];
        float4 v1 = *(const float4*)&cp[4];
        creg[0] = v0.x; creg[1] = v0.y; creg[2] = v0.z; creg[3] = v0.w;
        creg[4] = v1.x; creg[5] = v1.y; creg[6] = v1.z; creg[7] = v1.w;
    }

    for (int t = 0; t < Tlen; t++) {
        const __nv_bfloat16* hih = (t & 1) ? hB_hi : hA_hi;
        const __nv_bfloat16* hil = (t & 1) ? hB_lo : hA_lo;
        __nv_bfloat16* hoh = (t & 1) ? hA_hi : hB_hi;
        __nv_bfloat16* hol = (t & 1) ? hA_lo : hB_lo;
        const __nv_bfloat16* Asrc_h = hih + (size_t)(b0 + ra) * Hdim;
        const __nv_bfloat16* Asrc_l = hil + (size_t)(b0 + ra) * Hdim;

        #define FILL(kc_, st_) do { \
            unsigned ab = smem_u + (st_) * STG_SZ; \
            const __nv_bfloat16* sh = Asrc_h + (kc_) * 64; \
            const __nv_bfloat16* sl = Asrc_l + (kc_) * 64; \
            _Pragma("unroll") \
            for (int c = 0; c < 4; c++) { \
                int cc = ca + c; \
                unsigned d = ra * 128 + ((cc ^ ram) * 16); \
                CP16(ab + d,          sh + cc * 8); \
                CP16(ab + 16384 + d,  sl + cc * 8); \
            } \
            const __nv_bfloat16* bh = Bsrc_h + (kc_) * 64; \
            const __nv_bfloat16* bl = Bsrc_l + (kc_) * 64; \
            _Pragma("unroll") \
            for (int c = 0; c < 2; c++) { \
                int cc = cbb + c; \
                unsigned d = rb * 128 + ((cc ^ rbm) * 16); \
                CP16(ab + 32768 + d,  bh + cc * 8); \
                CP16(ab + 40960 + d,  bl + cc * 8); \
            } \
            CPCOMMIT(); \
        } while (0)

        FILL(0, 0); FILL(1, 1); FILL(2, 2);

        for (int kc = 0; kc < 16; kc++) {
            if (kc <= 13) { CPWAIT(2); } else if (kc == 14) { CPWAIT(1); } else { CPWAIT(0); }
            __syncthreads();
            if (wid == 0 && elect1()) {
                unsigned sb = smem_u + (kc & 3) * STG_SZ;
                unsigned long long adh = mk_desc(sb);
                unsigned long long adl = mk_desc(sb + 16384);
                unsigned long long bdh = mk_desc(sb + 32768);
                unsigned long long bdl = mk_desc(sb + 40960);
                #pragma unroll
                for (int ks = 0; ks < 4; ks++) {
                    unsigned en0 = (kc == 0 && ks == 0) ? 0u : 1u;
                    tc_mma_f16_ss(tmem, adh + ks * 2, bdh + ks * 2, TC_IDESC, en0);
                    tc_mma_f16_ss(tmem, adh + ks * 2, bdl + ks * 2, TC_IDESC, 1u);
                    tc_mma_f16_ss(tmem, adl + ks * 2, bdh + ks * 2, TC_IDESC, 1u);
                }
                TC_COMMIT(mbu[kc & 3]);
            }
            if (kc + 3 < 16) {
                if (kc >= 1) {
                    int s = (kc - 1) & 3;
                    MBAR_WAIT(mbu[s], (unsigned)(ph[s] & 1));
                    ph[s]++;
                }
                FILL(kc + 3, (kc + 3) & 3);
            }
        }
        #pragma unroll
        for (int c = 12; c < 16; c++) {
            int s = c & 3;
            MBAR_WAIT(mbu[s], (unsigned)(ph[s] & 1));
            ph[s]++;
        }
        TC_FENCE_AFTER();

        // epilogue: warp reads its 32 cols (j-half) of D
        unsigned dr[32];
        TC_LD32(dr, tmem + (wid >> 2) * 32);
        TC_WAIT_LD();
        TC_FENCE_BEFORE();

        int tok = (t == 0) ? 0 : atom_truth[b * Tlen + (t - 1)];
        const float* xp = xpart + (size_t)b * G4;
        const float* ep = embproj + (size_t)tok * G4;
        __nv_bfloat16 hh[8], hl[8];
        #pragma unroll
        for (int jl = 0; jl < 8; jl++) {
            int j = jb + jh + jl;
            float ig = __uint_as_float(dr[4 * jl + 0]) + xp[j]            + ep[j];
            float fg = __uint_as_float(dr[4 * jl + 1]) + xp[Hdim + j]     + ep[Hdim + j];
            float gg = __uint_as_float(dr[4 * jl + 2]) + xp[2 * Hdim + j] + ep[2 * Hdim + j];
            float og = __uint_as_float(dr[4 * jl + 3]) + xp[3 * Hdim + j] + ep[3 * Hdim + j];
            ig = 1.f / (1.f + expf(-ig));
            fg = 1.f / (1.f + expf(-fg));
            og = 1.f / (1.f + expf(-og));
            gg = tanhf(gg);
            float cv = fg * creg[jl] + ig * gg;
            creg[jl] = cv;
            float hv = og * tanhf(cv);
            bf16split(hv, hh[jl], hl[jl]);
        }
        {
            size_t o = (size_t)b * Hdim + jb + jh;
            *(uint4*)&hoh[o] = *(uint4*)&hh[0];
            *(uint4*)&hol[o] = *(uint4*)&hl[0];
            size_t ho = ((size_t)t * Bsz + b) * Hdim + jb + jh;
            *(uint4*)&hshi[ho] = *(uint4*)&hh[0];
            *(uint4*)&hslo[ho] = *(uint4*)&hl[0];
        }

        if (t < Tlen - 1) grid_sync(tid, (unsigned)(t + 1));
        #undef FILL
    }

    __syncthreads();
    if (wid == 0) TC_DEALLOC(tmem, 512);

#else
    // ======================= mma.sync fallback (R7 body) =======================
    extern __shared__ __align__(1024) unsigned char dsm[];
    unsigned smem_u = smem_u32(dsm);
    float* Gs = (float*)dsm;     // [64][132], aliases stage buffers after loop

    const int bx = blockIdx.x;
    const int j0 = (bx & 31) * 32;
    const int b0 = (bx >> 5) * 64;
    const int gcol0 = j0 * 4;
    const int tid = threadIdx.x;
    const int lane = tid & 31, w = tid >> 5;
    const int wm = w & 1, wn = w >> 1;
    const int qr = lane >> 2, qk = (lane & 3) * 2;
    const int ar = tid >> 2, akc = (tid & 3) * 8;
    const int br = tid >> 1, bkc = (tid & 1) * 16;

    const __nv_bfloat16* gBh = whhhi + (size_t)(gcol0 + br) * Hdim + bkc;
    const __nv_bfloat16* gBl = whhlo + (size_t)(gcol0 + br) * Hdim + bkc;

    float creg[8];
    #pragma unroll
    for (int i = 0; i < 8; i++) {
        int idx = tid + i * 256;
        creg[i] = c0[(b0 + (idx >> 5)) * Hdim + j0 + (idx & 31)];
    }

    for (int t = 0; t < Tlen; t++) {
        const __nv_bfloat16* hih = (t & 1) ? hB_hi : hA_hi;
        const __nv_bfloat16* hil = (t & 1) ? hB_lo : hA_lo;
        __nv_bfloat16* hoh = (t & 1) ? hA_hi : hB_hi;
        __nv_bfloat16* hol = (t & 1) ? hA_lo : hB_lo;

        float acc[2][4][4];
        #pragma unroll
        for (int mt = 0; mt < 2; mt++)
            #pragma unroll
            for (int nt = 0; nt < 4; nt++)
                #pragma unroll
                for (int q = 0; q < 4; q++) acc[mt][nt][q] = 0.f;

        mma_mainloop(hih + (size_t)(b0 + ar) * Hdim + akc,
                     hil + (size_t)(b0 + ar) * Hdim + akc,
                     gBh, gBl, smem_u, tid, acc);

        __syncthreads();
        #pragma unroll
        for (int mt = 0; mt < 2; mt++)
            #pragma unroll
            for (int nt = 0; nt < 4; nt++) {
                int r = wm * 32 + mt * 16 + qr;
                int cc = wn * 32 + nt * 8 + qk;
                *(float2*)&Gs[r * 132 + cc]       = make_float2(acc[mt][nt][0], acc[mt][nt][1]);
                *(float2*)&Gs[(r + 8) * 132 + cc] = make_float2(acc[mt][nt][2], acc[mt][nt][3]);
            }
        __syncthreads();

        #pragma unroll
        for (int i = 0; i < 8; i++) {
            int idx = tid + i * 256;
            int bl = idx >> 5, jj = idx & 31;
            float4 gv = *(const float4*)&Gs[bl * 132 + jj * 4];
            int b = b0 + bl, j = j0 + jj;
            int tok = (t == 0) ? 0 : atom_truth[b * Tlen + (t - 1)];
            const float* xp = xpart + (size_t)b * G4 + j;
            const float* ep = embproj + (size_t)tok * G4 + j;
            float ig = gv.x + xp[0]        + ep[0];
            float fg = gv.y + xp[Hdim]     + ep[Hdim];
            float gg = gv.z + xp[2 * Hdim] + ep[2 * Hdim];
            float og = gv.w + xp[3 * Hdim] + ep[3 * Hdim];
            ig = 1.f / (1.f + expf(-ig));
            fg = 1.f / (1.f + expf(-fg));
            og = 1.f / (1.f + expf(-og));
            gg = tanhf(gg);
            float cv = fg * creg[i] + ig * gg;
            creg[i] = cv;
            float hv = og * tanhf(cv);
            __nv_bfloat16 hh, hl;
            bf16split(hv, hh, hl);
            hoh[b * Hdim + j] = hh;
            hol[b * Hdim + j] = hl;
            size_t ho = ((size_t)t * Bsz + b) * Hdim + j;
            hshi[ho] = hh;
            hslo[ho] = hl;
        }

        if (t < Tlen - 1) grid_sync(tid, (unsigned)(t + 1));
    }
#endif
}

// ---------------------------------------------------------------------------
// Logits GEMM (mma.sync path): C[16384,512] = hs @ W_out^T + b_out.
// ---------------------------------------------------------------------------
__global__ __launch_bounds__(256) void logits_mma(
    const __nv_bfloat16* __restrict__ Ahi_g,
    const __nv_bfloat16* __restrict__ Alo_g,
    const __nv_bfloat16* __restrict__ Bhi_g,
    const __nv_bfloat16* __restrict__ Blo_g,
    float* __restrict__ C,
    const float* __restrict__ bias)
{
    extern __shared__ __align__(16) unsigned char dsm2[];
    unsigned smem_u = (unsigned)__cvta_generic_to_shared(dsm2);

    const int n0 = blockIdx.x * 128;
    const int m0 = blockIdx.y * 64;
    const int tid = threadIdx.x;
    const int lane = tid & 31, w = tid >> 5;
    const int wm = w & 1, wn = w >> 1;
    const int qr = lane >> 2, qk = (lane & 3) * 2;
    const int ar = tid >> 2, akc = (tid & 3) * 8;
    const int br = tid >> 1, bkc = (tid & 1) * 16;

    float acc[2][4][4];
    #pragma unroll
    for (int mt = 0; mt < 2; mt++)
        #pragma unroll
        for (int nt = 0; nt < 4; nt++)
            #pragma unroll
            for (int q = 0; q < 4; q++) acc[mt][nt][q] = 0.f;

    mma_mainloop(Ahi_g + (size_t)(m0 + ar) * Hdim + akc,
                 Alo_g + (size_t)(m0 + ar) * Hdim + akc,
                 Bhi_g + (size_t)(n0 + br) * Hdim + bkc,
                 Blo_g + (size_t)(n0 + br) * Hdim + bkc,
                 smem_u, tid, acc);

    #pragma unroll
    for (int mt = 0; mt < 2; mt++)
        #pragma unroll
        for (int nt = 0; nt < 4; nt++) {
            int m = m0 + wm * 32 + mt * 16 + qr;
            int n = n0 + wn * 32 + nt * 8 + qk;
            float b0v = bias[n], b1v = bias[n + 1];
            *(float2*)&C[(size_t)m * NTAG + n] =
                make_float2(acc[mt][nt][0] + b0v, acc[mt][nt][1] + b1v);
            *(float2*)&C[(size_t)(m + 8) * NTAG + n] =
                make_float2(acc[mt][nt][2] + b0v, acc[mt][nt][3] + b1v);
        }
}

// ---------------------------------------------------------------------------
// Mask detection / NLL / reduction
// ---------------------------------------------------------------------------
__global__ void detect_mask(const unsigned* __restrict__ m)
{
    __shared__ int isByte, isFloat;
    if (threadIdx.x == 0) { isByte = 0; isFloat = 0; }
    __syncthreads();
    for (int i = threadIdx.x; i < (Bsz * Tlen) / 4; i += blockDim.x) {
        unsigned v = m[i];
        if (v == 0x3F800000u) isFloat = 1;
        else if (v > 1u) isByte = 1;
    }
    __syncthreads();
    if (threadIdx.x == 0) g_mask_mode = isFloat ? 2 : (isByte ? 1 : 0);
}

__global__ __launch_bounds__(128) void nll_rows(
    const float* __restrict__ logits,
    const int* __restrict__ atom_truth,
    const void* __restrict__ atom_mask,
    float* __restrict__ rownll,
    float* __restrict__ rowmask)
{
    const int r = blockIdx.x;
    const int t = r >> 8;
    const int b = r & 255;
    const float* row = logits + (size_t)r * NTAG;
    const int tid = threadIdx.x;
    __shared__ float red[128];

    float mx = -1e30f;
    for (int i = tid; i < NTAG; i += 128) mx = fmaxf(mx, row[i]);
    red[tid] = mx; __syncthreads();
    for (int s = 64; s > 0; s >>= 1) {
        if (tid < s) red[tid] = fmaxf(red[tid], red[tid + s]);
        __syncthreads();
    }
    mx = red[0]; __syncthreads();

    float sm = 0.f;
    for (int i = tid; i < NTAG; i += 128) sm += expf(row[i] - mx);
    red[tid] = sm; __syncthreads();
    for (int s = 64; s > 0; s >>= 1) {
        if (tid < s) red[tid] += red[tid + s];
        __syncthreads();
    }

    if (tid == 0) {
        int tgt = atom_truth[b * Tlen + t];
        float lp = row[tgt] - mx - logf(red[0]);
        int mode = g_mask_mode;
        float m;
        if (mode == 2)      m = (((const float*)atom_mask)[b * Tlen + t] != 0.f) ? 1.f : 0.f;
        else if (mode == 1) m = (((const unsigned char*)atom_mask)[b * Tlen + t] != 0) ? 1.f : 0.f;
        else                m = (((const int*)atom_mask)[b * Tlen + t] != 0) ? 1.f : 0.f;
        rownll[r]  = -lp * m;
        rowmask[r] = m;
    }
}

__global__ __launch_bounds__(256) void final_reduce(
    const float* __restrict__ rownll,
    const float* __restrict__ rowmask,
    float* __restrict__ out)
{
    __shared__ double rn[256], rm[256];
    double sn = 0.0, sm = 0.0;
    for (int i = threadIdx.x; i < Tlen * Bsz; i += 256) {
        sn += (double)rownll[i];
        sm += (double)rowmask[i];
    }
    rn[threadIdx.x] = sn; rm[threadIdx.x] = sm;
    __syncthreads();
    for (int s = 128; s > 0; s >>= 1) {
        if (threadIdx.x < s) {
            rn[threadIdx.x] += rn[threadIdx.x + s];
            rm[threadIdx.x] += rm[threadIdx.x + s];
        }
        __syncthreads();
    }
    if (threadIdx.x == 0) out[0] = (float)(rn[0] / rm[0]);
}

// ---------------------------------------------------------------------------
// Launch
// ---------------------------------------------------------------------------
extern "C" void kernel_launch(void* const* d_in, const int* in_sizes, int n_in,
                              void* d_out, int out_size)
{
    const float* x      = (const float*)d_in[0];
    const int*   atomtr = (const int*)d_in[1];
    const void*  mask   = d_in[2];
    const float* emb    = (const float*)d_in[3];
    const float* W_ih   = (const float*)d_in[4];
    const float* W_hh   = (const float*)d_in[5];
    const float* b_ih   = (const float*)d_in[6];
    const float* b_hh   = (const float*)d_in[7];
    const float* W_out  = (const float*)d_in[8];
    const float* b_out  = (const float*)d_in[9];
    const float* h0     = (const float*)d_in[10];
    const float* c0     = (const float*)d_in[11];

    float* sc = nullptr;
    cudaGetSymbolAddress((void**)&sc, g_scratch);
    float* xpart   = sc + 0;
    float* embproj = sc + 1048576;
    float* logits  = sc + 3407872;
    float* rownll  = sc + 11796480;
    float* rowmask = sc + 11812864;
    __nv_bfloat16* bb = (__nv_bfloat16*)(sc + 11829248);
    __nv_bfloat16* whh_hi  = bb + 0;
    __nv_bfloat16* whh_lo  = bb + 4194304;
    __nv_bfloat16* wout_hi = bb + 8388608;
    __nv_bfloat16* wout_lo = bb + 8912896;
    __nv_bfloat16* hA_hi   = bb + 9437184;
    __nv_bfloat16* hA_lo   = bb + 9699328;
    __nv_bfloat16* hB_hi   = bb + 9961472;
    __nv_bfloat16* hB_lo   = bb + 10223616;
    __nv_bfloat16* hs_hi   = bb + 10485760;
    __nv_bfloat16* hs_lo   = bb + 27262976;

    const int DSMEM_LOG = 3 * 30720;    // 92160
    static int attr_done = 0;
    if (!attr_done) {
        cudaFuncSetAttribute(lstm_seq,   cudaFuncAttributeMaxDynamicSharedMemorySize, DSMEM_LSTM);
        cudaFuncSetAttribute(logits_mma, cudaFuncAttributeMaxDynamicSharedMemorySize, DSMEM_LOG);
        attr_done = 1;
    }

    detect_mask<<<1, 256>>>((const unsigned*)mask);
    init_bar<<<1, 1>>>();

    // one-time weight / state splits
    split_whh<<<4096, 256>>>(W_hh, whh_hi, whh_lo);
    split_plain<<<512, 256>>>(W_out, wout_hi, wout_lo);
    split_plain<<<256, 256>>>(h0, hA_hi, hA_lo);

    // xpart = x @ W_ih[:, :512]^T + b_ih + b_hh   [256, 4096]
    sgemm2<<<dim3(G4 / 64, Bsz / 128), 256>>>(x, Xdim, W_ih, DIN, xpart, G4, Xdim, b_ih, b_hh);
    // embproj = emb @ W_ih[:, 512:768]^T          [512, 4096]
    sgemm2<<<dim3(G4 / 64, NTAG / 128), 256>>>(emb, Edim, W_ih + Xdim, DIN, embproj, G4, Edim, nullptr, nullptr);

    // all 64 LSTM steps in one persistent kernel (tcgen05 or mma.sync path)
    lstm_seq<<<128, 256, DSMEM_LSTM>>>(
        hA_hi, hA_lo, hB_hi, hB_lo, c0, xpart, embproj,
        hs_hi, hs_lo, whh_hi, whh_lo, atomtr);

    // logits = hs @ W_out^T + b_out   [16384, 512]
    logits_mma<<<dim3(NTAG / 128, (Tlen * Bsz) / 64), 256, DSMEM_LOG>>>(
        hs_hi, hs_lo, wout_hi, wout_lo, logits, b_out);

    nll_rows<<<Tlen * Bsz, 128>>>(logits, atomtr, mask, rownll, rowmask);
    final_reduce<<<1, 256>>>(rownll, rowmask, (float*)d_out);
}

// round 10
// speedup vs baseline: 3.2879x; 1.0028x over previous
#include <cuda_runtime.h>
#include <cuda_bf16.h>
#include <math.h>

#define Bsz  256
#define Tlen 64
#define Hdim 1024
#define Xdim 512
#define Edim 256
#define DIN  768
#define G4   4096
#define NTAG 512

// ---- scratch layout ----
// floats:
//   xpart   @0          (1,048,576)
//   embproj @1,048,576  (2,097,152)
//   logits  @3,407,872  (8,388,608)
//   rownll  @11,796,480 (16,384)
//   rowmask @11,812,864 (16,384)
// bf16 region at float offset 11,829,248 (bf16-element offsets):
//   whh_hi 0            whh_lo 4,194,304
//   wout_hi 8,388,608   wout_lo 8,912,896
//   hA_hi 9,437,184  hA_lo 9,699,328  hB_hi 9,961,472  hB_lo 10,223,616
//   hs_hi 10,485,760 (16,777,216)   hs_lo 27,262,976 (16,777,216)
__device__ float g_scratch[33849344];
__device__ int   g_mask_mode;
__device__ unsigned g_bar_arrive;
__device__ unsigned g_bar_gen;

// ---------------------------------------------------------------------------
// PTX helpers (portable: mma.sync / ldmatrix / cp.async)
// ---------------------------------------------------------------------------
#define MMA4(c, a, b0_, b1_) \
    asm volatile("mma.sync.aligned.m16n8k16.row.col.f32.bf16.bf16.f32 " \
                 "{%0,%1,%2,%3},{%4,%5,%6,%7},{%8,%9},{%0,%1,%2,%3};" \
                 : "+f"((c)[0]), "+f"((c)[1]), "+f"((c)[2]), "+f"((c)[3]) \
                 : "r"((a)[0]), "r"((a)[1]), "r"((a)[2]), "r"((a)[3]), \
                   "r"(b0_), "r"(b1_))

#define LDSM4(r, addr) \
    asm volatile("ldmatrix.sync.aligned.m8n8.x4.shared.b16 {%0,%1,%2,%3}, [%4];" \
                 : "=r"((r)[0]), "=r"((r)[1]), "=r"((r)[2]), "=r"((r)[3]) \
                 : "r"(addr))

#define CP16(dst, src) \
    asm volatile("cp.async.cg.shared.global [%0], [%1], 16;" :: "r"(dst), "l"(src))
#define CPCOMMIT() asm volatile("cp.async.commit_group;" ::: "memory")
#define CPWAIT(n)  asm volatile("cp.async.wait_group %0;" :: "n"(n) : "memory")

#define FFMA2(d, a, b) asm("fma.rn.f32x2 %0, %1, %2, %0;" : "+l"(d) : "l"(a), "l"(b))
union F2U { unsigned long long u; float2 f; };
__device__ __forceinline__ unsigned long long dup2(float a) {
    unsigned x = __float_as_uint(a);
    return ((unsigned long long)x << 32) | (unsigned long long)x;
}

__device__ __forceinline__ void bf16split(float v, __nv_bfloat16& hi, __nv_bfloat16& lo) {
    hi = __float2bfloat16_rn(v);
    lo = __float2bfloat16_rn(v - __bfloat162float(hi));
}

__device__ __forceinline__ unsigned smem_u32(const void* p) {
    return (unsigned)__cvta_generic_to_shared(p);
}

// ---------------------------------------------------------------------------
// tcgen05 helpers — ONLY compiled on the sm_100a ("arch-accelerated") pass.
// ---------------------------------------------------------------------------
#if defined(__CUDA_ARCH_FEAT_SM100_ALL)
__device__ __forceinline__ bool elect1() {
    unsigned p;
    asm volatile("{\n\t.reg .pred p;\n\telect.sync _|p, 0xFFFFFFFF;\n\tselp.b32 %0,1,0,p;\n\t}"
                 : "=r"(p));
    return p != 0;
}
__device__ __forceinline__ unsigned long long mk_desc(unsigned addr) {
    // SW128, version=1 (Blackwell), SBO=64, LBO=1 (K-major, 128B rows)
    return 0x4000404000010000ULL | ((unsigned long long)(addr >> 4) & 0x3FFF);
}
__device__ __forceinline__ void tc_mma_f16_ss(unsigned d, unsigned long long ad,
                                              unsigned long long bd, unsigned idesc,
                                              unsigned en)
{
    asm volatile(
        "{\n\t.reg .pred p;\n\tsetp.ne.u32 p, %5, 0;\n\t"
        "tcgen05.mma.cta_group::1.kind::f16 [%0], %1, %2, %3, {%4, %4, %4, %4}, p;\n\t}"
        :: "r"(d), "l"(ad), "l"(bd), "r"(idesc), "r"(0u), "r"(en)
        : "memory");
}
#define TC_ALLOC(smaddr, n) \
    asm volatile("tcgen05.alloc.cta_group::1.sync.aligned.shared::cta.b32 [%0], %1;" \
                 :: "r"(smaddr), "r"((unsigned)(n)) : "memory")
#define TC_DEALLOC(base, n) \
    asm volatile("tcgen05.dealloc.cta_group::1.sync.aligned.b32 %0, %1;" \
                 :: "r"(base), "r"((unsigned)(n)))
#define TC_COMMIT(mb) \
    asm volatile("tcgen05.commit.cta_group::1.mbarrier::arrive::one.shared::cluster.b64 [%0];" \
                 :: "r"(mb) : "memory")
#define TC_FENCE_AFTER()  asm volatile("tcgen05.fence::after_thread_sync;" ::: "memory")
#define TC_FENCE_BEFORE() asm volatile("tcgen05.fence::before_thread_sync;" ::: "memory")
#define TC_WAIT_LD()      asm volatile("tcgen05.wait::ld.sync.aligned;" ::: "memory")

#define MBAR_INIT(mb, cnt) \
    asm volatile("mbarrier.init.shared.b64 [%0], %1;" :: "r"(mb), "r"((unsigned)(cnt)) : "memory")
#define MBAR_WAIT(mb, par) do { \
    unsigned _m = (mb), _p = (par), _d; \
    asm volatile("{\n\t.reg .pred p;\n\t" \
                 "mbarrier.try_wait.parity.acquire.cta.shared::cta.b64 p, [%1], %2;\n\t" \
                 "selp.b32 %0,1,0,p;\n\t}" : "=r"(_d) : "r"(_m), "r"(_p) : "memory"); \
    if (!_d) { \
        asm volatile("{\n\t.reg .pred P1;\n\t" \
                     "WL%=:\n\t" \
                     "mbarrier.try_wait.parity.acquire.cta.shared::cta.b64 P1, [%0], %1, 0x989680;\n\t" \
                     "@P1 bra.uni WD%=;\n\tbra.uni WL%=;\n\tWD%=:\n\t}" \
                     :: "r"(_m), "r"(_p) : "memory"); \
    } \
} while(0)

#define TC_LD32(r, addr) \
    asm volatile("tcgen05.ld.sync.aligned.32x32b.x32.b32 " \
        "{%0,%1,%2,%3,%4,%5,%6,%7,%8,%9,%10,%11,%12,%13,%14,%15," \
        "%16,%17,%18,%19,%20,%21,%22,%23,%24,%25,%26,%27,%28,%29,%30,%31}, [%32];" \
        : "=r"((r)[0]),"=r"((r)[1]),"=r"((r)[2]),"=r"((r)[3]), \
          "=r"((r)[4]),"=r"((r)[5]),"=r"((r)[6]),"=r"((r)[7]), \
          "=r"((r)[8]),"=r"((r)[9]),"=r"((r)[10]),"=r"((r)[11]), \
          "=r"((r)[12]),"=r"((r)[13]),"=r"((r)[14]),"=r"((r)[15]), \
          "=r"((r)[16]),"=r"((r)[17]),"=r"((r)[18]),"=r"((r)[19]), \
          "=r"((r)[20]),"=r"((r)[21]),"=r"((r)[22]),"=r"((r)[23]), \
          "=r"((r)[24]),"=r"((r)[25]),"=r"((r)[26]),"=r"((r)[27]), \
          "=r"((r)[28]),"=r"((r)[29]),"=r"((r)[30]),"=r"((r)[31]) \
        : "r"(addr))

// idesc: f32 accum, bf16 a/b, M=128, N=64
#define TC_IDESC 0x08100490u
#endif // __CUDA_ARCH_FEAT_SM100_ALL

// ---------------------------------------------------------------------------
// Split kernels
// ---------------------------------------------------------------------------
__global__ void split_whh(const float* __restrict__ W,
                          __nv_bfloat16* __restrict__ hi,
                          __nv_bfloat16* __restrict__ lo)
{
    int c = blockIdx.x;
    int j = c >> 2, g = c & 3;
    const float* src = W + (size_t)(g * Hdim + j) * Hdim;
    int k = threadIdx.x * 4;
    float4 v = *(const float4*)&src[k];
    size_t o = (size_t)c * Hdim + k;
    float a[4] = {v.x, v.y, v.z, v.w};
    #pragma unroll
    for (int q = 0; q < 4; q++) bf16split(a[q], hi[o + q], lo[o + q]);
}

__global__ void split_plain(const float* __restrict__ W,
                            __nv_bfloat16* __restrict__ hi,
                            __nv_bfloat16* __restrict__ lo)
{
    int r = blockIdx.x;
    const float* src = W + (size_t)r * Hdim;
    int k = threadIdx.x * 4;
    float4 v = *(const float4*)&src[k];
    size_t o = (size_t)r * Hdim + k;
    float a[4] = {v.x, v.y, v.z, v.w};
    #pragma unroll
    for (int q = 0; q < 4; q++) bf16split(a[q], hi[o + q], lo[o + q]);
}

// ---------------------------------------------------------------------------
// f32x2 SGEMM (xpart / embproj): C[M,N] = A[M,K] @ B[N,K]^T (+b0)(+b1)
// ---------------------------------------------------------------------------
__global__ __launch_bounds__(256) void sgemm2(
    const float* __restrict__ A, int lda,
    const float* __restrict__ Bm, int ldb,
    float* __restrict__ C, int ldc, int K,
    const float* __restrict__ bias0,
    const float* __restrict__ bias1)
{
    __shared__ unsigned long long As2[16][128];
    __shared__ float Bs[16][64];
    const int m0 = blockIdx.y * 128;
    const int n0 = blockIdx.x * 64;
    const int tid = threadIdx.x;
    const int rg = tid >> 4;
    const int cg = tid & 15;
    unsigned long long acc[8][2];
    #pragma unroll
    for (int i = 0; i < 8; i++) { acc[i][0] = 0ull; acc[i][1] = 0ull; }
    const int fm = tid >> 2;
    const int fk = (tid & 3) * 4;

    for (int k0 = 0; k0 < K; k0 += 16) {
        __syncthreads();
        #pragma unroll
        for (int half = 0; half < 2; half++) {
            int m = fm + half * 64;
            float4 v = *(const float4*)&A[(size_t)(m0 + m) * lda + k0 + fk];
            As2[fk + 0][m] = dup2(v.x);
            As2[fk + 1][m] = dup2(v.y);
            As2[fk + 2][m] = dup2(v.z);
            As2[fk + 3][m] = dup2(v.w);
        }
        {
            float4 v = *(const float4*)&Bm[(size_t)(n0 + fm) * ldb + k0 + fk];
            Bs[fk + 0][fm] = v.x; Bs[fk + 1][fm] = v.y;
            Bs[fk + 2][fm] = v.z; Bs[fk + 3][fm] = v.w;
        }
        __syncthreads();
        #pragma unroll
        for (int k = 0; k < 16; k++) {
            const ulonglong2* ap = (const ulonglong2*)&As2[k][rg * 8];
            ulonglong2 bv = *(const ulonglong2*)&Bs[k][cg * 4];
            #pragma unroll
            for (int i2 = 0; i2 < 4; i2++) {
                ulonglong2 a = ap[i2];
                FFMA2(acc[2 * i2 + 0][0], a.x, bv.x);
                FFMA2(acc[2 * i2 + 0][1], a.x, bv.y);
                FFMA2(acc[2 * i2 + 1][0], a.y, bv.x);
                FFMA2(acc[2 * i2 + 1][1], a.y, bv.y);
            }
        }
    }
    #pragma unroll
    for (int i = 0; i < 8; i++) {
        int m = m0 + rg * 8 + i;
        #pragma unroll
        for (int p = 0; p < 2; p++) {
            int n = n0 + cg * 4 + p * 2;
            F2U u; u.u = acc[i][p];
            float v0 = u.f.x, v1 = u.f.y;
            if (bias0) { v0 += bias0[n]; v1 += bias0[n + 1]; }
            if (bias1) { v0 += bias1[n]; v1 += bias1[n + 1]; }
            *(float2*)&C[(size_t)m * ldc + n] = make_float2(v0, v1);
        }
    }
}

// ---------------------------------------------------------------------------
// mma.sync mainloop (logits GEMM + LSTM fallback path)
// ---------------------------------------------------------------------------
__device__ __forceinline__ void mma_mainloop(
    const __nv_bfloat16* __restrict__ gAh, const __nv_bfloat16* __restrict__ gAl,
    const __nv_bfloat16* __restrict__ gBh, const __nv_bfloat16* __restrict__ gBl,
    unsigned smem_u, int tid, float acc[2][4][4])
{
    const int lane = tid & 31, w = tid >> 5;
    const int wm = w & 1, wn = w >> 1;
    const int lrow = (lane & 7) + ((lane >> 3) & 1) * 8;
    const int lcol = (lane >> 4) * 8;
    const unsigned aoff = ((wm * 32 + lrow) * 40 + lcol) * 2;
    const unsigned boff = ((wn * 32 + lrow) * 40 + lcol) * 2;

    const int ar = tid >> 2;
    const int br = tid >> 1;
    const unsigned dA  = (ar * 40 + (tid & 3) * 8) * 2;
    const unsigned dB0 = (br * 40 + (tid & 1) * 16) * 2;
    const unsigned dB1 = dB0 + 16;

    #pragma unroll
    for (int s = 0; s < 2; s++) {
        unsigned sb = smem_u + s * 30720;
        int k0 = s * 32;
        CP16(sb + dA,          gAh + k0);
        CP16(sb + 5120  + dA,  gAl + k0);
        CP16(sb + 10240 + dB0, gBh + k0);
        CP16(sb + 10240 + dB1, gBh + k0 + 8);
        CP16(sb + 20480 + dB0, gBl + k0);
        CP16(sb + 20480 + dB1, gBl + k0 + 8);
        CPCOMMIT();
    }

    for (int i = 0; i < 32; i++) {
        if (i < 31) { CPWAIT(1); } else { CPWAIT(0); }
        __syncthreads();
        if (i + 2 < 32) {
            unsigned sb = smem_u + ((i + 2) % 3) * 30720;
            int k0 = (i + 2) * 32;
            CP16(sb + dA,          gAh + k0);
            CP16(sb + 5120  + dA,  gAl + k0);
            CP16(sb + 10240 + dB0, gBh + k0);
            CP16(sb + 10240 + dB1, gBh + k0 + 8);
            CP16(sb + 20480 + dB0, gBl + k0);
            CP16(sb + 20480 + dB1, gBl + k0 + 8);
            CPCOMMIT();
        }
        unsigned sb = smem_u + (i % 3) * 30720;
        #pragma unroll
        for (int kh = 0; kh < 2; kh++) {
            const unsigned kb = kh * 32;
            unsigned a0[4], a1[4], l0[4], l1[4];
            LDSM4(a0, sb + aoff + kb);
            LDSM4(a1, sb + aoff + 1280 + kb);
            LDSM4(l0, sb + 5120 + aoff + kb);
            LDSM4(l1, sb + 5120 + aoff + 1280 + kb);
            unsigned bh0[4], bh1[4], bl0[4], bl1[4];
            LDSM4(bh0, sb + 10240 + boff + kb);
            LDSM4(bh1, sb + 10240 + boff + 1280 + kb);
            LDSM4(bl0, sb + 20480 + boff + kb);
            LDSM4(bl1, sb + 20480 + boff + 1280 + kb);
            #pragma unroll
            for (int nt = 0; nt < 4; nt++) {
                const unsigned* bhp = (nt < 2) ? bh0 : bh1;
                const unsigned* blp = (nt < 2) ? bl0 : bl1;
                unsigned h0v = bhp[nt & 1], h1v = bhp[(nt & 1) + 2];
                unsigned l0v = blp[nt & 1], l1v = blp[(nt & 1) + 2];
                MMA4(acc[0][nt], a0, h0v, h1v);
                MMA4(acc[0][nt], a0, l0v, l1v);
                MMA4(acc[0][nt], l0, h0v, h1v);
                MMA4(acc[1][nt], a1, h0v, h1v);
                MMA4(acc[1][nt], a1, l0v, l1v);
                MMA4(acc[1][nt], l1, h0v, h1v);
            }
        }
    }
}

// ---------------------------------------------------------------------------
// Grid barrier
// ---------------------------------------------------------------------------
__global__ void init_bar() { g_bar_arrive = 0; g_bar_gen = 0; }

__device__ __forceinline__ void grid_sync(int tid, unsigned gen)
{
    __syncthreads();
    if (tid == 0) {
        __threadfence();
        unsigned a = atomicAdd(&g_bar_arrive, 1);
        if (a == 127) {
            g_bar_arrive = 0;
            __threadfence();
            atomicExch(&g_bar_gen, gen);
        } else {
            while (atomicAdd(&g_bar_gen, 0u) < gen) __nanosleep(64);
            __threadfence();
        }
    }
    __syncthreads();
}

#define STG_SZ 49152   // tcgen05 stage: Ahi 16K @0, Alo @16384, Bhi 8K @32768, Blo @40960
#define DSMEM_LSTM (4 * STG_SZ)   // 196608

// ---------------------------------------------------------------------------
// Persistent LSTM sequence kernel — dual path:
//   sm_100a pass:   tcgen05 SS-MMA with TMEM accumulators
//   plain pass:     mma.sync fallback (proven R7 body)
// Launch: grid=128, block=256, dsmem=196608 for BOTH paths.
// ---------------------------------------------------------------------------
__global__ __launch_bounds__(256, 1) void lstm_seq(
    __nv_bfloat16* hA_hi, __nv_bfloat16* hA_lo,
    __nv_bfloat16* hB_hi, __nv_bfloat16* hB_lo,
    const float* __restrict__ c0,
    const float* __restrict__ xpart,
    const float* __restrict__ embproj,
    __nv_bfloat16* __restrict__ hshi,
    __nv_bfloat16* __restrict__ hslo,
    const __nv_bfloat16* __restrict__ whhhi,
    const __nv_bfloat16* __restrict__ whhlo,
    const int* __restrict__ atom_truth)
{
#if defined(__CUDA_ARCH_FEAT_SM100_ALL)
    // ======================= tcgen05 path =======================
    // Block bx: mt=bx>>6 (batch tile of 128), ntb=bx&63 (64 gate-cols =
    // 16 j x 4 gates, W rows pre-interleaved c=j*4+g).
    extern __shared__ __align__(1024) unsigned char dsm[];
    __shared__ unsigned s_tmem;
    __shared__ __align__(8) unsigned long long s_mbar[4];

    const unsigned smem_u = smem_u32(dsm);
    const int tid = threadIdx.x;
    const int wid = tid >> 5, lane = tid & 31;
    const int bx = blockIdx.x;
    const int b0 = (bx >> 6) * 128;
    const int ntb = bx & 63;
    const int c0g = ntb * 64;
    const int jb = ntb * 16;

    if (tid == 0) {
        #pragma unroll
        for (int i = 0; i < 4; i++) MBAR_INIT(smem_u32(&s_mbar[i]), 1);
    }
    __syncthreads();
    if (wid == 0) TC_ALLOC(smem_u32(&s_tmem), 512);
    __syncthreads();
    const unsigned tmem = s_tmem;
    unsigned mbu[4];
    #pragma unroll
    for (int i = 0; i < 4; i++) mbu[i] = smem_u32(&s_mbar[i]);
    int ph[4] = {0, 0, 0, 0};

    // fill geometry (256 threads, 12 CP16/thread/stage)
    const int ra = tid >> 1, ca = (tid & 1) * 4;       // A: row, 4 chunks
    const int rb = tid >> 2, cbb = (tid & 3) * 2;      // B: row, 2 chunks
    const int ram = ra & 7, rbm = rb & 7;
    const __nv_bfloat16* Bsrc_h = whhhi + (size_t)(c0g + rb) * Hdim;
    const __nv_bfloat16* Bsrc_l = whhlo + (size_t)(c0g + rb) * Hdim;

    // epilogue geometry: warp w -> rows (w&3)*32+lane, j-half (w>>2)*8
    const int b = b0 + (wid & 3) * 32 + lane;
    const int jh = (wid >> 2) * 8;
    float creg[8];
    {
        const float* cp = c0 + (size_t)b * Hdim + jb + jh;
        float4 v0 = *(const float4*)&cp[0];
        float4 v1 = *(const float4*)&cp[4];
        creg[0] = v0.x; creg[1] = v0.y; creg[2] = v0.z; creg[3] = v0.w;
        creg[4] = v1.x; creg[5] = v1.y; creg[6] = v1.z; creg[7] = v1.w;
    }

    for (int t = 0; t < Tlen; t++) {
        const __nv_bfloat16* hih = (t & 1) ? hB_hi : hA_hi;
        const __nv_bfloat16* hil = (t & 1) ? hB_lo : hA_lo;
        __nv_bfloat16* hoh = (t & 1) ? hA_hi : hB_hi;
        __nv_bfloat16* hol = (t & 1) ? hA_lo : hB_lo;
        const __nv_bfloat16* Asrc_h = hih + (size_t)(b0 + ra) * Hdim;
        const __nv_bfloat16* Asrc_l = hil + (size_t)(b0 + ra) * Hdim;

        #define FILL(kc_, st_) do { \
            unsigned ab = smem_u + (st_) * STG_SZ; \
            const __nv_bfloat16* sh = Asrc_h + (kc_) * 64; \
            const __nv_bfloat16* sl = Asrc_l + (kc_) * 64; \
            _Pragma("unroll") \
            for (int c = 0; c < 4; c++) { \
                int cc = ca + c; \
                unsigned d = ra * 128 + ((cc ^ ram) * 16); \
                CP16(ab + d,          sh + cc * 8); \
                CP16(ab + 16384 + d,  sl + cc * 8); \
            } \
            const __nv_bfloat16* bh = Bsrc_h + (kc_) * 64; \
            const __nv_bfloat16* bl = Bsrc_l + (kc_) * 64; \
            _Pragma("unroll") \
            for (int c = 0; c < 2; c++) { \
                int cc = cbb + c; \
                unsigned d = rb * 128 + ((cc ^ rbm) * 16); \
                CP16(ab + 32768 + d,  bh + cc * 8); \
                CP16(ab + 40960 + d,  bl + cc * 8); \
            } \
            CPCOMMIT(); \
        } while (0)

        FILL(0, 0); FILL(1, 1); FILL(2, 2);

        for (int kc = 0; kc < 16; kc++) {
            if (kc <= 13) { CPWAIT(2); } else if (kc == 14) { CPWAIT(1); } else { CPWAIT(0); }
            __syncthreads();
            if (wid == 0 && elect1()) {
                unsigned sb = smem_u + (kc & 3) * STG_SZ;
                unsigned long long adh = mk_desc(sb);
                unsigned long long adl = mk_desc(sb + 16384);
                unsigned long long bdh = mk_desc(sb + 32768);
                unsigned long long bdl = mk_desc(sb + 40960);
                #pragma unroll
                for (int ks = 0; ks < 4; ks++) {
                    unsigned en0 = (kc == 0 && ks == 0) ? 0u : 1u;
                    tc_mma_f16_ss(tmem, adh + ks * 2, bdh + ks * 2, TC_IDESC, en0);
                    tc_mma_f16_ss(tmem, adh + ks * 2, bdl + ks * 2, TC_IDESC, 1u);
                    tc_mma_f16_ss(tmem, adl + ks * 2, bdh + ks * 2, TC_IDESC, 1u);
                }
                TC_COMMIT(mbu[kc & 3]);
            }
            if (kc + 3 < 16) {
                if (kc >= 1) {
                    int s = (kc - 1) & 3;
                    MBAR_WAIT(mbu[s], (unsigned)(ph[s] & 1));
                    ph[s]++;
                }
                FILL(kc + 3, (kc + 3) & 3);
            }
        }
        #pragma unroll
        for (int c = 12; c < 16; c++) {
            int s = c & 3;
            MBAR_WAIT(mbu[s], (unsigned)(ph[s] & 1));
            ph[s]++;
        }
        TC_FENCE_AFTER();

        // epilogue: warp reads its 32 cols (j-half) of D
        unsigned dr[32];
        TC_LD32(dr, tmem + (wid >> 2) * 32);
        TC_WAIT_LD();
        TC_FENCE_BEFORE();

        int tok = (t == 0) ? 0 : atom_truth[b * Tlen + (t - 1)];
        const float* xp = xpart + (size_t)b * G4;
        const float* ep = embproj + (size_t)tok * G4;
        __nv_bfloat16 hh[8], hl[8];
        #pragma unroll
        for (int jl = 0; jl < 8; jl++) {
            int j = jb + jh + jl;
            float ig = __uint_as_float(dr[4 * jl + 0]) + xp[j]            + ep[j];
            float fg = __uint_as_float(dr[4 * jl + 1]) + xp[Hdim + j]     + ep[Hdim + j];
            float gg = __uint_as_float(dr[4 * jl + 2]) + xp[2 * Hdim + j] + ep[2 * Hdim + j];
            float og = __uint_as_float(dr[4 * jl + 3]) + xp[3 * Hdim + j] + ep[3 * Hdim + j];
            ig = 1.f / (1.f + expf(-ig));
            fg = 1.f / (1.f + expf(-fg));
            og = 1.f / (1.f + expf(-og));
            gg = tanhf(gg);
            float cv = fg * creg[jl] + ig * gg;
            creg[jl] = cv;
            float hv = og * tanhf(cv);
            bf16split(hv, hh[jl], hl[jl]);
        }
        {
            size_t o = (size_t)b * Hdim + jb + jh;
            *(uint4*)&hoh[o] = *(uint4*)&hh[0];
            *(uint4*)&hol[o] = *(uint4*)&hl[0];
            size_t ho = ((size_t)t * Bsz + b) * Hdim + jb + jh;
            *(uint4*)&hshi[ho] = *(uint4*)&hh[0];
            *(uint4*)&hslo[ho] = *(uint4*)&hl[0];
        }

        if (t < Tlen - 1) grid_sync(tid, (unsigned)(t + 1));
        #undef FILL
    }

    __syncthreads();
    if (wid == 0) TC_DEALLOC(tmem, 512);

#else
    // ======================= mma.sync fallback (R7 body) =======================
    extern __shared__ __align__(1024) unsigned char dsm[];
    unsigned smem_u = smem_u32(dsm);
    float* Gs = (float*)dsm;     // [64][132], aliases stage buffers after loop

    const int bx = blockIdx.x;
    const int j0 = (bx & 31) * 32;
    const int b0 = (bx >> 5) * 64;
    const int gcol0 = j0 * 4;
    const int tid = threadIdx.x;
    const int lane = tid & 31, w = tid >> 5;
    const int wm = w & 1, wn = w >> 1;
    const int qr = lane >> 2, qk = (lane & 3) * 2;
    const int ar = tid >> 2, akc = (tid & 3) * 8;
    const int br = tid >> 1, bkc = (tid & 1) * 16;

    const __nv_bfloat16* gBh = whhhi + (size_t)(gcol0 + br) * Hdim + bkc;
    const __nv_bfloat16* gBl = whhlo + (size_t)(gcol0 + br) * Hdim + bkc;

    float creg[8];
    #pragma unroll
    for (int i = 0; i < 8; i++) {
        int idx = tid + i * 256;
        creg[i] = c0[(b0 + (idx >> 5)) * Hdim + j0 + (idx & 31)];
    }

    for (int t = 0; t < Tlen; t++) {
        const __nv_bfloat16* hih = (t & 1) ? hB_hi : hA_hi;
        const __nv_bfloat16* hil = (t & 1) ? hB_lo : hA_lo;
        __nv_bfloat16* hoh = (t & 1) ? hA_hi : hB_hi;
        __nv_bfloat16* hol = (t & 1) ? hA_lo : hB_lo;

        float acc[2][4][4];
        #pragma unroll
        for (int mt = 0; mt < 2; mt++)
            #pragma unroll
            for (int nt = 0; nt < 4; nt++)
                #pragma unroll
                for (int q = 0; q < 4; q++) acc[mt][nt][q] = 0.f;

        mma_mainloop(hih + (size_t)(b0 + ar) * Hdim + akc,
                     hil + (size_t)(b0 + ar) * Hdim + akc,
                     gBh, gBl, smem_u, tid, acc);

        __syncthreads();
        #pragma unroll
        for (int mt = 0; mt < 2; mt++)
            #pragma unroll
            for (int nt = 0; nt < 4; nt++) {
                int r = wm * 32 + mt * 16 + qr;
                int cc = wn * 32 + nt * 8 + qk;
                *(float2*)&Gs[r * 132 + cc]       = make_float2(acc[mt][nt][0], acc[mt][nt][1]);
                *(float2*)&Gs[(r + 8) * 132 + cc] = make_float2(acc[mt][nt][2], acc[mt][nt][3]);
            }
        __syncthreads();

        #pragma unroll
        for (int i = 0; i < 8; i++) {
            int idx = tid + i * 256;
            int bl = idx >> 5, jj = idx & 31;
            float4 gv = *(const float4*)&Gs[bl * 132 + jj * 4];
            int b = b0 + bl, j = j0 + jj;
            int tok = (t == 0) ? 0 : atom_truth[b * Tlen + (t - 1)];
            const float* xp = xpart + (size_t)b * G4 + j;
            const float* ep = embproj + (size_t)tok * G4 + j;
            float ig = gv.x + xp[0]        + ep[0];
            float fg = gv.y + xp[Hdim]     + ep[Hdim];
            float gg = gv.z + xp[2 * Hdim] + ep[2 * Hdim];
            float og = gv.w + xp[3 * Hdim] + ep[3 * Hdim];
            ig = 1.f / (1.f + expf(-ig));
            fg = 1.f / (1.f + expf(-fg));
            og = 1.f / (1.f + expf(-og));
            gg = tanhf(gg);
            float cv = fg * creg[i] + ig * gg;
            creg[i] = cv;
            float hv = og * tanhf(cv);
            __nv_bfloat16 hh, hl;
            bf16split(hv, hh, hl);
            hoh[b * Hdim + j] = hh;
            hol[b * Hdim + j] = hl;
            size_t ho = ((size_t)t * Bsz + b) * Hdim + j;
            hshi[ho] = hh;
            hslo[ho] = hl;
        }

        if (t < Tlen - 1) grid_sync(tid, (unsigned)(t + 1));
    }
#endif
}

// ---------------------------------------------------------------------------
// Logits GEMM (mma.sync path): C[16384,512] = hs @ W_out^T + b_out.
// ---------------------------------------------------------------------------
__global__ __launch_bounds__(256) void logits_mma(
    const __nv_bfloat16* __restrict__ Ahi_g,
    const __nv_bfloat16* __restrict__ Alo_g,
    const __nv_bfloat16* __restrict__ Bhi_g,
    const __nv_bfloat16* __restrict__ Blo_g,
    float* __restrict__ C,
    const float* __restrict__ bias)
{
    extern __shared__ __align__(16) unsigned char dsm2[];
    unsigned smem_u = (unsigned)__cvta_generic_to_shared(dsm2);

    const int n0 = blockIdx.x * 128;
    const int m0 = blockIdx.y * 64;
    const int tid = threadIdx.x;
    const int lane = tid & 31, w = tid >> 5;
    const int wm = w & 1, wn = w >> 1;
    const int qr = lane >> 2, qk = (lane & 3) * 2;
    const int ar = tid >> 2, akc = (tid & 3) * 8;
    const int br = tid >> 1, bkc = (tid & 1) * 16;

    float acc[2][4][4];
    #pragma unroll
    for (int mt = 0; mt < 2; mt++)
        #pragma unroll
        for (int nt = 0; nt < 4; nt++)
            #pragma unroll
            for (int q = 0; q < 4; q++) acc[mt][nt][q] = 0.f;

    mma_mainloop(Ahi_g + (size_t)(m0 + ar) * Hdim + akc,
                 Alo_g + (size_t)(m0 + ar) * Hdim + akc,
                 Bhi_g + (size_t)(n0 + br) * Hdim + bkc,
                 Blo_g + (size_t)(n0 + br) * Hdim + bkc,
                 smem_u, tid, acc);

    #pragma unroll
    for (int mt = 0; mt < 2; mt++)
        #pragma unroll
        for (int nt = 0; nt < 4; nt++) {
            int m = m0 + wm * 32 + mt * 16 + qr;
            int n = n0 + wn * 32 + nt * 8 + qk;
            float b0v = bias[n], b1v = bias[n + 1];
            *(float2*)&C[(size_t)m * NTAG + n] =
                make_float2(acc[mt][nt][0] + b0v, acc[mt][nt][1] + b1v);
            *(float2*)&C[(size_t)(m + 8) * NTAG + n] =
                make_float2(acc[mt][nt][2] + b0v, acc[mt][nt][3] + b1v);
        }
}

// ---------------------------------------------------------------------------
// Mask detection / NLL / reduction
// ---------------------------------------------------------------------------
__global__ void detect_mask(const unsigned* __restrict__ m)
{
    __shared__ int isByte, isFloat;
    if (threadIdx.x == 0) { isByte = 0; isFloat = 0; }
    __syncthreads();
    for (int i = threadIdx.x; i < (Bsz * Tlen) / 4; i += blockDim.x) {
        unsigned v = m[i];
        if (v == 0x3F800000u) isFloat = 1;
        else if (v > 1u) isByte = 1;
    }
    __syncthreads();
    if (threadIdx.x == 0) g_mask_mode = isFloat ? 2 : (isByte ? 1 : 0);
}

__global__ __launch_bounds__(128) void nll_rows(
    const float* __restrict__ logits,
    const int* __restrict__ atom_truth,
    const void* __restrict__ atom_mask,
    float* __restrict__ rownll,
    float* __restrict__ rowmask)
{
    const int r = blockIdx.x;
    const int t = r >> 8;
    const int b = r & 255;
    const float* row = logits + (size_t)r * NTAG;
    const int tid = threadIdx.x;
    __shared__ float red[128];

    float mx = -1e30f;
    for (int i = tid; i < NTAG; i += 128) mx = fmaxf(mx, row[i]);
    red[tid] = mx; __syncthreads();
    for (int s = 64; s > 0; s >>= 1) {
        if (tid < s) red[tid] = fmaxf(red[tid], red[tid + s]);
        __syncthreads();
    }
    mx = red[0]; __syncthreads();

    float sm = 0.f;
    for (int i = tid; i < NTAG; i += 128) sm += expf(row[i] - mx);
    red[tid] = sm; __syncthreads();
    for (int s = 64; s > 0; s >>= 1) {
        if (tid < s) red[tid] += red[tid + s];
        __syncthreads();
    }

    if (tid == 0) {
        int tgt = atom_truth[b * Tlen + t];
        float lp = row[tgt] - mx - logf(red[0]);
        int mode = g_mask_mode;
        float m;
        if (mode == 2)      m = (((const float*)atom_mask)[b * Tlen + t] != 0.f) ? 1.f : 0.f;
        else if (mode == 1) m = (((const unsigned char*)atom_mask)[b * Tlen + t] != 0) ? 1.f : 0.f;
        else                m = (((const int*)atom_mask)[b * Tlen + t] != 0) ? 1.f : 0.f;
        rownll[r]  = -lp * m;
        rowmask[r] = m;
    }
}

__global__ __launch_bounds__(256) void final_reduce(
    const float* __restrict__ rownll,
    const float* __restrict__ rowmask,
    float* __restrict__ out)
{
    __shared__ double rn[256], rm[256];
    double sn = 0.0, sm = 0.0;
    for (int i = threadIdx.x; i < Tlen * Bsz; i += 256) {
        sn += (double)rownll[i];
        sm += (double)rowmask[i];
    }
    rn[threadIdx.x] = sn; rm[threadIdx.x] = sm;
    __syncthreads();
    for (int s = 128; s > 0; s >>= 1) {
        if (threadIdx.x < s) {
            rn[threadIdx.x] += rn[threadIdx.x + s];
            rm[threadIdx.x] += rm[threadIdx.x + s];
        }
        __syncthreads();
    }
    if (threadIdx.x == 0) out[0] = (float)(rn[0] / rm[0]);
}

// ---------------------------------------------------------------------------
// Launch
// ---------------------------------------------------------------------------
extern "C" void kernel_launch(void* const* d_in, const int* in_sizes, int n_in,
                              void* d_out, int out_size)
{
    const float* x      = (const float*)d_in[0];
    const int*   atomtr = (const int*)d_in[1];
    const void*  mask   = d_in[2];
    const float* emb    = (const float*)d_in[3];
    const float* W_ih   = (const float*)d_in[4];
    const float* W_hh   = (const float*)d_in[5];
    const float* b_ih   = (const float*)d_in[6];
    const float* b_hh   = (const float*)d_in[7];
    const float* W_out  = (const float*)d_in[8];
    const float* b_out  = (const float*)d_in[9];
    const float* h0     = (const float*)d_in[10];
    const float* c0     = (const float*)d_in[11];

    float* sc = nullptr;
    cudaGetSymbolAddress((void**)&sc, g_scratch);
    float* xpart   = sc + 0;
    float* embproj = sc + 1048576;
    float* logits  = sc + 3407872;
    float* rownll  = sc + 11796480;
    float* rowmask = sc + 11812864;
    __nv_bfloat16* bb = (__nv_bfloat16*)(sc + 11829248);
    __nv_bfloat16* whh_hi  = bb + 0;
    __nv_bfloat16* whh_lo  = bb + 4194304;
    __nv_bfloat16* wout_hi = bb + 8388608;
    __nv_bfloat16* wout_lo = bb + 8912896;
    __nv_bfloat16* hA_hi   = bb + 9437184;
    __nv_bfloat16* hA_lo   = bb + 9699328;
    __nv_bfloat16* hB_hi   = bb + 9961472;
    __nv_bfloat16* hB_lo   = bb + 10223616;
    __nv_bfloat16* hs_hi   = bb + 10485760;
    __nv_bfloat16* hs_lo   = bb + 27262976;

    const int DSMEM_LOG = 3 * 30720;    // 92160
    static int attr_done = 0;
    if (!attr_done) {
        cudaFuncSetAttribute(lstm_seq,   cudaFuncAttributeMaxDynamicSharedMemorySize, DSMEM_LSTM);
        cudaFuncSetAttribute(logits_mma, cudaFuncAttributeMaxDynamicSharedMemorySize, DSMEM_LOG);
        attr_done = 1;
    }

    detect_mask<<<1, 256>>>((const unsigned*)mask);
    init_bar<<<1, 1>>>();

    // one-time weight / state splits
    split_whh<<<4096, 256>>>(W_hh, whh_hi, whh_lo);
    split_plain<<<512, 256>>>(W_out, wout_hi, wout_lo);
    split_plain<<<256, 256>>>(h0, hA_hi, hA_lo);

    // xpart = x @ W_ih[:, :512]^T + b_ih + b_hh   [256, 4096]
    sgemm2<<<dim3(G4 / 64, Bsz / 128), 256>>>(x, Xdim, W_ih, DIN, xpart, G4, Xdim, b_ih, b_hh);
    // embproj = emb @ W_ih[:, 512:768]^T          [512, 4096]
    sgemm2<<<dim3(G4 / 64, NTAG / 128), 256>>>(emb, Edim, W_ih + Xdim, DIN, embproj, G4, Edim, nullptr, nullptr);

    // all 64 LSTM steps in one persistent kernel (tcgen05 or mma.sync path)
    lstm_seq<<<128, 256, DSMEM_LSTM>>>(
        hA_hi, hA_lo, hB_hi, hB_lo, c0, xpart, embproj,
        hs_hi, hs_lo, whh_hi, whh_lo, atomtr);

    // logits = hs @ W_out^T + b_out   [16384, 512]
    logits_mma<<<dim3(NTAG / 128, (Tlen * Bsz) / 64), 256, DSMEM_LOG>>>(
        hs_hi, hs_lo, wout_hi, wout_lo, logits, b_out);

    nll_rows<<<Tlen * Bsz, 128>>>(logits, atomtr, mask, rownll, rowmask);
    final_reduce<<<1, 256>>>(rownll, rowmask, (float*)d_out);
}

// round 11
// speedup vs baseline: 4.4001x; 1.3383x over previous
#include <cuda_runtime.h>
#include <cuda_bf16.h>
#include <math.h>

#define Bsz  256
#define Tlen 64
#define Hdim 1024
#define Xdim 512
#define Edim 256
#define DIN  768
#define G4   4096
#define NTAG 512

// ---- scratch layout ----
// floats:
//   xpart   @0          (1,048,576)
//   embproj @1,048,576  (2,097,152)
//   logits  @3,407,872  (8,388,608)
//   rownll  @11,796,480 (16,384)
//   rowmask @11,812,864 (16,384)
// bf16 region at float offset 11,829,248 (bf16-element offsets):
//   whh_hi 0            whh_lo 4,194,304
//   wout_hi 8,388,608   wout_lo 8,912,896
//   hA_hi 9,437,184  hA_lo 9,699,328  hB_hi 9,961,472  hB_lo 10,223,616
//   hs_hi 10,485,760 (16,777,216)   hs_lo 27,262,976 (16,777,216)
__device__ float g_scratch[33849344];
__device__ int   g_mask_mode;
__device__ unsigned g_bar_arrive;
__device__ unsigned g_bar_gen;
__device__ unsigned g_arr2[2];
__device__ unsigned g_gen2[2];
__device__ int      g_use_tc;

// ---------------------------------------------------------------------------
// PTX helpers (portable: mma.sync / ldmatrix / cp.async)
// ---------------------------------------------------------------------------
#define MMA4(c, a, b0_, b1_) \
    asm volatile("mma.sync.aligned.m16n8k16.row.col.f32.bf16.bf16.f32 " \
                 "{%0,%1,%2,%3},{%4,%5,%6,%7},{%8,%9},{%0,%1,%2,%3};" \
                 : "+f"((c)[0]), "+f"((c)[1]), "+f"((c)[2]), "+f"((c)[3]) \
                 : "r"((a)[0]), "r"((a)[1]), "r"((a)[2]), "r"((a)[3]), \
                   "r"(b0_), "r"(b1_))

#define LDSM4(r, addr) \
    asm volatile("ldmatrix.sync.aligned.m8n8.x4.shared.b16 {%0,%1,%2,%3}, [%4];" \
                 : "=r"((r)[0]), "=r"((r)[1]), "=r"((r)[2]), "=r"((r)[3]) \
                 : "r"(addr))

#define CP16(dst, src) \
    asm volatile("cp.async.cg.shared.global [%0], [%1], 16;" :: "r"(dst), "l"(src))
#define CPCOMMIT() asm volatile("cp.async.commit_group;" ::: "memory")
#define CPWAIT(n)  asm volatile("cp.async.wait_group %0;" :: "n"(n) : "memory")

#define FFMA2(d, a, b) asm("fma.rn.f32x2 %0, %1, %2, %0;" : "+l"(d) : "l"(a), "l"(b))
union F2U { unsigned long long u; float2 f; };
__device__ __forceinline__ unsigned long long dup2(float a) {
    unsigned x = __float_as_uint(a);
    return ((unsigned long long)x << 32) | (unsigned long long)x;
}

__device__ __forceinline__ void bf16split(float v, __nv_bfloat16& hi, __nv_bfloat16& lo) {
    hi = __float2bfloat16_rn(v);
    lo = __float2bfloat16_rn(v - __bfloat162float(hi));
}

__device__ __forceinline__ unsigned smem_u32(const void* p) {
    return (unsigned)__cvta_generic_to_shared(p);
}

// ---------------------------------------------------------------------------
// tcgen05 helpers — ONLY compiled on the sm_100a pass.
// ---------------------------------------------------------------------------
#if defined(__CUDA_ARCH_FEAT_SM100_ALL)
__device__ __forceinline__ bool elect1() {
    unsigned p;
    asm volatile("{\n\t.reg .pred p;\n\telect.sync _|p, 0xFFFFFFFF;\n\tselp.b32 %0,1,0,p;\n\t}"
                 : "=r"(p));
    return p != 0;
}
__device__ __forceinline__ unsigned long long mk_desc(unsigned addr) {
    // SW128, version=1 (Blackwell), SBO=64, LBO=1 (K-major, 128B rows)
    return 0x4000404000010000ULL | ((unsigned long long)(addr >> 4) & 0x3FFF);
}
__device__ __forceinline__ void tc_mma_f16_ss(unsigned d, unsigned long long ad,
                                              unsigned long long bd, unsigned idesc,
                                              unsigned en)
{
    asm volatile(
        "{\n\t.reg .pred p;\n\tsetp.ne.u32 p, %5, 0;\n\t"
        "tcgen05.mma.cta_group::1.kind::f16 [%0], %1, %2, %3, {%4, %4, %4, %4}, p;\n\t}"
        :: "r"(d), "l"(ad), "l"(bd), "r"(idesc), "r"(0u), "r"(en)
        : "memory");
}
#define TC_ALLOC(smaddr, n) \
    asm volatile("tcgen05.alloc.cta_group::1.sync.aligned.shared::cta.b32 [%0], %1;" \
                 :: "r"(smaddr), "r"((unsigned)(n)) : "memory")
#define TC_DEALLOC(base, n) \
    asm volatile("tcgen05.dealloc.cta_group::1.sync.aligned.b32 %0, %1;" \
                 :: "r"(base), "r"((unsigned)(n)))
#define TC_COMMIT(mb) \
    asm volatile("tcgen05.commit.cta_group::1.mbarrier::arrive::one.shared::cluster.b64 [%0];" \
                 :: "r"(mb) : "memory")
#define TC_FENCE_AFTER()  asm volatile("tcgen05.fence::after_thread_sync;" ::: "memory")
#define TC_FENCE_BEFORE() asm volatile("tcgen05.fence::before_thread_sync;" ::: "memory")
#define TC_WAIT_LD()      asm volatile("tcgen05.wait::ld.sync.aligned;" ::: "memory")

#define MBAR_INIT(mb, cnt) \
    asm volatile("mbarrier.init.shared.b64 [%0], %1;" :: "r"(mb), "r"((unsigned)(cnt)) : "memory")
#define MBAR_WAIT(mb, par) do { \
    unsigned _m = (mb), _p = (par), _d; \
    asm volatile("{\n\t.reg .pred p;\n\t" \
                 "mbarrier.try_wait.parity.acquire.cta.shared::cta.b64 p, [%1], %2;\n\t" \
                 "selp.b32 %0,1,0,p;\n\t}" : "=r"(_d) : "r"(_m), "r"(_p) : "memory"); \
    if (!_d) { \
        asm volatile("{\n\t.reg .pred P1;\n\t" \
                     "WL%=:\n\t" \
                     "mbarrier.try_wait.parity.acquire.cta.shared::cta.b64 P1, [%0], %1, 0x989680;\n\t" \
                     "@P1 bra.uni WD%=;\n\tbra.uni WL%=;\n\tWD%=:\n\t}" \
                     :: "r"(_m), "r"(_p) : "memory"); \
    } \
} while(0)

#define TC_LD32(r, addr) \
    asm volatile("tcgen05.ld.sync.aligned.32x32b.x32.b32 " \
        "{%0,%1,%2,%3,%4,%5,%6,%7,%8,%9,%10,%11,%12,%13,%14,%15," \
        "%16,%17,%18,%19,%20,%21,%22,%23,%24,%25,%26,%27,%28,%29,%30,%31}, [%32];" \
        : "=r"((r)[0]),"=r"((r)[1]),"=r"((r)[2]),"=r"((r)[3]), \
          "=r"((r)[4]),"=r"((r)[5]),"=r"((r)[6]),"=r"((r)[7]), \
          "=r"((r)[8]),"=r"((r)[9]),"=r"((r)[10]),"=r"((r)[11]), \
          "=r"((r)[12]),"=r"((r)[13]),"=r"((r)[14]),"=r"((r)[15]), \
          "=r"((r)[16]),"=r"((r)[17]),"=r"((r)[18]),"=r"((r)[19]), \
          "=r"((r)[20]),"=r"((r)[21]),"=r"((r)[22]),"=r"((r)[23]), \
          "=r"((r)[24]),"=r"((r)[25]),"=r"((r)[26]),"=r"((r)[27]), \
          "=r"((r)[28]),"=r"((r)[29]),"=r"((r)[30]),"=r"((r)[31]) \
        : "r"(addr))

// idesc: f32 accum, bf16 a/b, M=128, N=64
#define TC_IDESC 0x08100490u
#endif // __CUDA_ARCH_FEAT_SM100_ALL

// fast activations (safe at +/-inf)
__device__ __forceinline__ float fsig(float x) {
    return __fdividef(1.f, 1.f + __expf(-x));
}
__device__ __forceinline__ float ftanh(float x) {
    return 1.f - __fdividef(2.f, __expf(2.f * x) + 1.f);
}

// ---------------------------------------------------------------------------
// Split kernels
// ---------------------------------------------------------------------------
__global__ void split_whh(const float* __restrict__ W,
                          __nv_bfloat16* __restrict__ hi,
                          __nv_bfloat16* __restrict__ lo)
{
    int c = blockIdx.x;
    int j = c >> 2, g = c & 3;
    const float* src = W + (size_t)(g * Hdim + j) * Hdim;
    int k = threadIdx.x * 4;
    float4 v = *(const float4*)&src[k];
    size_t o = (size_t)c * Hdim + k;
    float a[4] = {v.x, v.y, v.z, v.w};
    #pragma unroll
    for (int q = 0; q < 4; q++) bf16split(a[q], hi[o + q], lo[o + q]);
}

__global__ void split_plain(const float* __restrict__ W,
                            __nv_bfloat16* __restrict__ hi,
                            __nv_bfloat16* __restrict__ lo)
{
    int r = blockIdx.x;
    const float* src = W + (size_t)r * Hdim;
    int k = threadIdx.x * 4;
    float4 v = *(const float4*)&src[k];
    size_t o = (size_t)r * Hdim + k;
    float a[4] = {v.x, v.y, v.z, v.w};
    #pragma unroll
    for (int q = 0; q < 4; q++) bf16split(a[q], hi[o + q], lo[o + q]);
}

// ---------------------------------------------------------------------------
// f32x2 SGEMM (xpart / embproj): C[M,N] = A[M,K] @ B[N,K]^T (+b0)(+b1)
// ---------------------------------------------------------------------------
__global__ __launch_bounds__(256) void sgemm2(
    const float* __restrict__ A, int lda,
    const float* __restrict__ Bm, int ldb,
    float* __restrict__ C, int ldc, int K,
    const float* __restrict__ bias0,
    const float* __restrict__ bias1)
{
    __shared__ unsigned long long As2[16][128];
    __shared__ float Bs[16][64];
    const int m0 = blockIdx.y * 128;
    const int n0 = blockIdx.x * 64;
    const int tid = threadIdx.x;
    const int rg = tid >> 4;
    const int cg = tid & 15;
    unsigned long long acc[8][2];
    #pragma unroll
    for (int i = 0; i < 8; i++) { acc[i][0] = 0ull; acc[i][1] = 0ull; }
    const int fm = tid >> 2;
    const int fk = (tid & 3) * 4;

    for (int k0 = 0; k0 < K; k0 += 16) {
        __syncthreads();
        #pragma unroll
        for (int half = 0; half < 2; half++) {
            int m = fm + half * 64;
            float4 v = *(const float4*)&A[(size_t)(m0 + m) * lda + k0 + fk];
            As2[fk + 0][m] = dup2(v.x);
            As2[fk + 1][m] = dup2(v.y);
            As2[fk + 2][m] = dup2(v.z);
            As2[fk + 3][m] = dup2(v.w);
        }
        {
            float4 v = *(const float4*)&Bm[(size_t)(n0 + fm) * ldb + k0 + fk];
            Bs[fk + 0][fm] = v.x; Bs[fk + 1][fm] = v.y;
            Bs[fk + 2][fm] = v.z; Bs[fk + 3][fm] = v.w;
        }
        __syncthreads();
        #pragma unroll
        for (int k = 0; k < 16; k++) {
            const ulonglong2* ap = (const ulonglong2*)&As2[k][rg * 8];
            ulonglong2 bv = *(const ulonglong2*)&Bs[k][cg * 4];
            #pragma unroll
            for (int i2 = 0; i2 < 4; i2++) {
                ulonglong2 a = ap[i2];
                FFMA2(acc[2 * i2 + 0][0], a.x, bv.x);
                FFMA2(acc[2 * i2 + 0][1], a.x, bv.y);
                FFMA2(acc[2 * i2 + 1][0], a.y, bv.x);
                FFMA2(acc[2 * i2 + 1][1], a.y, bv.y);
            }
        }
    }
    #pragma unroll
    for (int i = 0; i < 8; i++) {
        int m = m0 + rg * 8 + i;
        #pragma unroll
        for (int p = 0; p < 2; p++) {
            int n = n0 + cg * 4 + p * 2;
            F2U u; u.u = acc[i][p];
            float v0 = u.f.x, v1 = u.f.y;
            if (bias0) { v0 += bias0[n]; v1 += bias0[n + 1]; }
            if (bias1) { v0 += bias1[n]; v1 += bias1[n + 1]; }
            *(float2*)&C[(size_t)m * ldc + n] = make_float2(v0, v1);
        }
    }
}

// ---------------------------------------------------------------------------
// mma.sync mainloop (logits fallback + LSTM fallback path)
// ---------------------------------------------------------------------------
__device__ __forceinline__ void mma_mainloop(
    const __nv_bfloat16* __restrict__ gAh, const __nv_bfloat16* __restrict__ gAl,
    const __nv_bfloat16* __restrict__ gBh, const __nv_bfloat16* __restrict__ gBl,
    unsigned smem_u, int tid, float acc[2][4][4])
{
    const int lane = tid & 31, w = tid >> 5;
    const int wm = w & 1, wn = w >> 1;
    const int lrow = (lane & 7) + ((lane >> 3) & 1) * 8;
    const int lcol = (lane >> 4) * 8;
    const unsigned aoff = ((wm * 32 + lrow) * 40 + lcol) * 2;
    const unsigned boff = ((wn * 32 + lrow) * 40 + lcol) * 2;

    const int ar = tid >> 2;
    const int br = tid >> 1;
    const unsigned dA  = (ar * 40 + (tid & 3) * 8) * 2;
    const unsigned dB0 = (br * 40 + (tid & 1) * 16) * 2;
    const unsigned dB1 = dB0 + 16;

    #pragma unroll
    for (int s = 0; s < 2; s++) {
        unsigned sb = smem_u + s * 30720;
        int k0 = s * 32;
        CP16(sb + dA,          gAh + k0);
        CP16(sb + 5120  + dA,  gAl + k0);
        CP16(sb + 10240 + dB0, gBh + k0);
        CP16(sb + 10240 + dB1, gBh + k0 + 8);
        CP16(sb + 20480 + dB0, gBl + k0);
        CP16(sb + 20480 + dB1, gBl + k0 + 8);
        CPCOMMIT();
    }

    for (int i = 0; i < 32; i++) {
        if (i < 31) { CPWAIT(1); } else { CPWAIT(0); }
        __syncthreads();
        if (i + 2 < 32) {
            unsigned sb = smem_u + ((i + 2) % 3) * 30720;
            int k0 = (i + 2) * 32;
            CP16(sb + dA,          gAh + k0);
            CP16(sb + 5120  + dA,  gAl + k0);
            CP16(sb + 10240 + dB0, gBh + k0);
            CP16(sb + 10240 + dB1, gBh + k0 + 8);
            CP16(sb + 20480 + dB0, gBl + k0);
            CP16(sb + 20480 + dB1, gBl + k0 + 8);
            CPCOMMIT();
        }
        unsigned sb = smem_u + (i % 3) * 30720;
        #pragma unroll
        for (int kh = 0; kh < 2; kh++) {
            const unsigned kb = kh * 32;
            unsigned a0[4], a1[4], l0[4], l1[4];
            LDSM4(a0, sb + aoff + kb);
            LDSM4(a1, sb + aoff + 1280 + kb);
            LDSM4(l0, sb + 5120 + aoff + kb);
            LDSM4(l1, sb + 5120 + aoff + 1280 + kb);
            unsigned bh0[4], bh1[4], bl0[4], bl1[4];
            LDSM4(bh0, sb + 10240 + boff + kb);
            LDSM4(bh1, sb + 10240 + boff + 1280 + kb);
            LDSM4(bl0, sb + 20480 + boff + kb);
            LDSM4(bl1, sb + 20480 + boff + 1280 + kb);
            #pragma unroll
            for (int nt = 0; nt < 4; nt++) {
                const unsigned* bhp = (nt < 2) ? bh0 : bh1;
                const unsigned* blp = (nt < 2) ? bl0 : bl1;
                unsigned h0v = bhp[nt & 1], h1v = bhp[(nt & 1) + 2];
                unsigned l0v = blp[nt & 1], l1v = blp[(nt & 1) + 2];
                MMA4(acc[0][nt], a0, h0v, h1v);
                MMA4(acc[0][nt], a0, l0v, l1v);
                MMA4(acc[0][nt], l0, h0v, h1v);
                MMA4(acc[1][nt], a1, h0v, h1v);
                MMA4(acc[1][nt], a1, l0v, l1v);
                MMA4(acc[1][nt], l1, h0v, h1v);
            }
        }
    }
}

// ---------------------------------------------------------------------------
// Barriers
// ---------------------------------------------------------------------------
__global__ void init_bar() {
    g_bar_arrive = 0; g_bar_gen = 0;
    g_arr2[0] = 0; g_arr2[1] = 0;
    g_gen2[0] = 0; g_gen2[1] = 0;
#if defined(__CUDA_ARCH_FEAT_SM100_ALL)
    g_use_tc = 1;
#else
    g_use_tc = 0;
#endif
}

__device__ __forceinline__ void grid_sync(int tid, unsigned gen)
{
    __syncthreads();
    if (tid == 0) {
        __threadfence();
        unsigned a = atomicAdd(&g_bar_arrive, 1);
        if (a == 127) {
            g_bar_arrive = 0;
            __threadfence();
            atomicExch(&g_bar_gen, gen);
        } else {
            while (atomicAdd(&g_bar_gen, 0u) < gen) __nanosleep(64);
            __threadfence();
        }
    }
    __syncthreads();
}

#define STG_SZ 49152   // tcgen05 stage: Ahi 16K @0, Alo @16384, Bhi 8K @32768, Blo @40960
#define DSMEM_LSTM (4 * STG_SZ)   // 196608

// ---------------------------------------------------------------------------
// Persistent LSTM sequence kernel — dual path.
// ---------------------------------------------------------------------------
__global__ __launch_bounds__(256, 1) void lstm_seq(
    __nv_bfloat16* hA_hi, __nv_bfloat16* hA_lo,
    __nv_bfloat16* hB_hi, __nv_bfloat16* hB_lo,
    const float* __restrict__ c0,
    const float* __restrict__ xpart,
    const float* __restrict__ embproj,
    __nv_bfloat16* __restrict__ hshi,
    __nv_bfloat16* __restrict__ hslo,
    const __nv_bfloat16* __restrict__ whhhi,
    const __nv_bfloat16* __restrict__ whhlo,
    const int* __restrict__ atom_truth)
{
#if defined(__CUDA_ARCH_FEAT_SM100_ALL)
    // ======================= tcgen05 path =======================
    extern __shared__ __align__(1024) unsigned char dsm[];
    __shared__ unsigned s_tmem;
    __shared__ __align__(8) unsigned long long s_mbar[4];

    const unsigned smem_u = smem_u32(dsm);
    const int tid = threadIdx.x;
    const int wid = tid >> 5, lane = tid & 31;
    const int bx = blockIdx.x;
    const int half = bx >> 6;            // batch half 0/1
    const int b0 = half * 128;
    const int ntb = bx & 63;
    const int c0g = ntb * 64;            // gate-col base (rows pre-interleaved j*4+g)
    const int jb = ntb * 16;

    if (tid == 0) {
        #pragma unroll
        for (int i = 0; i < 4; i++) MBAR_INIT(smem_u32(&s_mbar[i]), 1);
    }
    __syncthreads();
    if (wid == 0) TC_ALLOC(smem_u32(&s_tmem), 512);
    __syncthreads();
    const unsigned tmem = s_tmem;
    unsigned mbu[4];
    #pragma unroll
    for (int i = 0; i < 4; i++) mbu[i] = smem_u32(&s_mbar[i]);
    int ph[4] = {0, 0, 0, 0};

    // fill geometry (256 threads)
    const int ra = tid >> 1, ca = (tid & 1) * 4;       // A: row, 4 chunks of 16B
    const int rb = tid >> 2, cbb = (tid & 3) * 2;      // B: row, 2 chunks
    const int ram = ra & 7, rbm = rb & 7;
    const __nv_bfloat16* Bsrc_h = whhhi + (size_t)(c0g + rb) * Hdim;
    const __nv_bfloat16* Bsrc_l = whhlo + (size_t)(c0g + rb) * Hdim;

    // epilogue geometry: warp w -> rows (w&3)*32+lane, j-half (w>>2)*8
    const int b = b0 + (wid & 3) * 32 + lane;
    const int jh = (wid >> 2) * 8;
    float creg[8];
    {
        const float* cp = c0 + (size_t)b * Hdim + jb + jh;
        float4 v0 = *(const float4*)&cp[0];
        float4 v1 = *(const float4*)&cp[4];
        creg[0] = v0.x; creg[1] = v0.y; creg[2] = v0.z; creg[3] = v0.w;
        creg[4] = v1.x; creg[5] = v1.y; creg[6] = v1.z; creg[7] = v1.w;
    }

    // B fill (one commit group): W chunk kc_ into stage st_
    #define FILL_B(kc_, st_) do { \
        unsigned ab = smem_u + (st_) * STG_SZ; \
        const __nv_bfloat16* bh = Bsrc_h + (kc_) * 64; \
        const __nv_bfloat16* bl = Bsrc_l + (kc_) * 64; \
        _Pragma("unroll") \
        for (int c = 0; c < 2; c++) { \
            int cc = cbb + c; \
            unsigned d = rb * 128 + ((cc ^ rbm) * 16); \
            CP16(ab + 32768 + d, bh + cc * 8); \
            CP16(ab + 40960 + d, bl + cc * 8); \
        } \
        CPCOMMIT(); \
    } while (0)

    // A fill (one commit group)
    #define FILL_A(kc_, st_) do { \
        unsigned ab = smem_u + (st_) * STG_SZ; \
        const __nv_bfloat16* sh = Asrc_h + (kc_) * 64; \
        const __nv_bfloat16* sl = Asrc_l + (kc_) * 64; \
        _Pragma("unroll") \
        for (int c = 0; c < 4; c++) { \
            int cc = ca + c; \
            unsigned d = ra * 128 + ((cc ^ ram) * 16); \
            CP16(ab + d,          sh + cc * 8); \
            CP16(ab + 16384 + d,  sl + cc * 8); \
        } \
        CPCOMMIT(); \
    } while (0)

    // combined A+B fill (one commit group)
    #define FILL_AB(kc_, st_) do { \
        unsigned ab = smem_u + (st_) * STG_SZ; \
        const __nv_bfloat16* sh = Asrc_h + (kc_) * 64; \
        const __nv_bfloat16* sl = Asrc_l + (kc_) * 64; \
        _Pragma("unroll") \
        for (int c = 0; c < 4; c++) { \
            int cc = ca + c; \
            unsigned d = ra * 128 + ((cc ^ ram) * 16); \
            CP16(ab + d,          sh + cc * 8); \
            CP16(ab + 16384 + d,  sl + cc * 8); \
        } \
        const __nv_bfloat16* bh = Bsrc_h + (kc_) * 64; \
        const __nv_bfloat16* bl = Bsrc_l + (kc_) * 64; \
        _Pragma("unroll") \
        for (int c = 0; c < 2; c++) { \
            int cc = cbb + c; \
            unsigned d = rb * 128 + ((cc ^ rbm) * 16); \
            CP16(ab + 32768 + d, bh + cc * 8); \
            CP16(ab + 40960 + d, bl + cc * 8); \
        } \
        CPCOMMIT(); \
    } while (0)

    // W prefetch for step 0 (stages 0-2): groups 0,1,2
    FILL_B(0, 0); FILL_B(1, 1); FILL_B(2, 2);

    for (int t = 0; t < Tlen; t++) {
        const __nv_bfloat16* hih = (t & 1) ? hB_hi : hA_hi;
        const __nv_bfloat16* hil = (t & 1) ? hB_lo : hA_lo;
        __nv_bfloat16* hoh = (t & 1) ? hA_hi : hB_hi;
        __nv_bfloat16* hol = (t & 1) ? hA_lo : hB_lo;
        const __nv_bfloat16* Asrc_h = hih + (size_t)(b0 + ra) * Hdim;
        const __nv_bfloat16* Asrc_l = hil + (size_t)(b0 + ra) * Hdim;

        // A prologue: groups 3,4,5 (B 0-2 already in flight from prev step / init)
        FILL_A(0, 0); FILL_A(1, 1); FILL_A(2, 2);

        for (int kc = 0; kc < 16; kc++) {
            if (kc <= 13) { CPWAIT(2); } else if (kc == 14) { CPWAIT(1); } else { CPWAIT(0); }
            __syncthreads();
            if (wid == 0 && elect1()) {
                unsigned sb = smem_u + (kc & 3) * STG_SZ;
                unsigned long long adh = mk_desc(sb);
                unsigned long long adl = mk_desc(sb + 16384);
                unsigned long long bdh = mk_desc(sb + 32768);
                unsigned long long bdl = mk_desc(sb + 40960);
                #pragma unroll
                for (int ks = 0; ks < 4; ks++) {
                    unsigned en0 = (kc == 0 && ks == 0) ? 0u : 1u;
                    tc_mma_f16_ss(tmem, adh + ks * 2, bdh + ks * 2, TC_IDESC, en0);
                    tc_mma_f16_ss(tmem, adh + ks * 2, bdl + ks * 2, TC_IDESC, 1u);
                    tc_mma_f16_ss(tmem, adl + ks * 2, bdh + ks * 2, TC_IDESC, 1u);
                }
                TC_COMMIT(mbu[kc & 3]);
            }
            if (kc + 3 < 16) {
                if (kc >= 1) {
                    int s = (kc - 1) & 3;
                    MBAR_WAIT(mbu[s], (unsigned)(ph[s] & 1));
                    ph[s]++;
                }
                FILL_AB(kc + 3, (kc + 3) & 3);
            }
        }
        #pragma unroll
        for (int c = 12; c < 16; c++) {
            int s = c & 3;
            MBAR_WAIT(mbu[s], (unsigned)(ph[s] & 1));
            ph[s]++;
        }
        TC_FENCE_AFTER();

        // next step's W prefetch, overlapped with epilogue + barrier
        if (t < Tlen - 1) { FILL_B(0, 0); FILL_B(1, 1); FILL_B(2, 2); }

        // epilogue
        unsigned dr[32];
        TC_LD32(dr, tmem + (wid >> 2) * 32);
        TC_WAIT_LD();
        TC_FENCE_BEFORE();

        int tok = (t == 0) ? 0 : atom_truth[b * Tlen + (t - 1)];
        const float* xp = xpart + (size_t)b * G4 + jb + jh;
        const float* ep = embproj + (size_t)tok * G4 + jb + jh;
        float xg[4][8], eg[4][8];
        #pragma unroll
        for (int p = 0; p < 4; p++) {
            float4 a0 = *(const float4*)&xp[p * Hdim];
            float4 a1 = *(const float4*)&xp[p * Hdim + 4];
            float4 e0 = *(const float4*)&ep[p * Hdim];
            float4 e1 = *(const float4*)&ep[p * Hdim + 4];
            xg[p][0] = a0.x; xg[p][1] = a0.y; xg[p][2] = a0.z; xg[p][3] = a0.w;
            xg[p][4] = a1.x; xg[p][5] = a1.y; xg[p][6] = a1.z; xg[p][7] = a1.w;
            eg[p][0] = e0.x; eg[p][1] = e0.y; eg[p][2] = e0.z; eg[p][3] = e0.w;
            eg[p][4] = e1.x; eg[p][5] = e1.y; eg[p][6] = e1.z; eg[p][7] = e1.w;
        }
        __nv_bfloat16 hh[8], hl[8];
        #pragma unroll
        for (int jl = 0; jl < 8; jl++) {
            float ig = __uint_as_float(dr[4 * jl + 0]) + xg[0][jl] + eg[0][jl];
            float fg = __uint_as_float(dr[4 * jl + 1]) + xg[1][jl] + eg[1][jl];
            float gg = __uint_as_float(dr[4 * jl + 2]) + xg[2][jl] + eg[2][jl];
            float og = __uint_as_float(dr[4 * jl + 3]) + xg[3][jl] + eg[3][jl];
            ig = fsig(ig); fg = fsig(fg); og = fsig(og); gg = ftanh(gg);
            float cv = fg * creg[jl] + ig * gg;
            creg[jl] = cv;
            float hv = og * ftanh(cv);
            bf16split(hv, hh[jl], hl[jl]);
        }
        {
            size_t o = (size_t)b * Hdim + jb + jh;
            *(uint4*)&hoh[o] = *(uint4*)&hh[0];
            *(uint4*)&hol[o] = *(uint4*)&hl[0];
            size_t ho = ((size_t)t * Bsz + b) * Hdim + jb + jh;
            *(uint4*)&hshi[ho] = *(uint4*)&hh[0];
            *(uint4*)&hslo[ho] = *(uint4*)&hl[0];
        }

        // per-half grid barrier (64 blocks), arrive-early / wait-late
        if (t < Tlen - 1) {
            __syncthreads();
            if (tid == 0) {
                __threadfence();
                unsigned old = atomicAdd(&g_arr2[half], 1);
                if (old == 63) {
                    g_arr2[half] = 0;
                    asm volatile("st.release.gpu.b32 [%0], %1;"
                                 :: "l"(&g_gen2[half]), "r"((unsigned)(t + 1)) : "memory");
                } else {
                    unsigned g;
                    do {
                        asm volatile("ld.acquire.gpu.b32 %0, [%1];"
                                     : "=r"(g) : "l"(&g_gen2[half]) : "memory");
                    } while (g < (unsigned)(t + 1));
                }
            }
            __syncthreads();
        }
        #undef FILL_B
        #define FILL_B(kc_, st_) do { \
            unsigned ab = smem_u + (st_) * STG_SZ; \
            const __nv_bfloat16* bh = Bsrc_h + (kc_) * 64; \
            const __nv_bfloat16* bl = Bsrc_l + (kc_) * 64; \
            _Pragma("unroll") \
            for (int c = 0; c < 2; c++) { \
                int cc = cbb + c; \
                unsigned d = rb * 128 + ((cc ^ rbm) * 16); \
                CP16(ab + 32768 + d, bh + cc * 8); \
                CP16(ab + 40960 + d, bl + cc * 8); \
            } \
            CPCOMMIT(); \
        } while (0)
    }

    __syncthreads();
    if (wid == 0) TC_DEALLOC(tmem, 512);
    #undef FILL_B
    #undef FILL_A
    #undef FILL_AB

#else
    // ======================= mma.sync fallback (proven R7 body) =======================
    extern __shared__ __align__(1024) unsigned char dsm[];
    unsigned smem_u = smem_u32(dsm);
    float* Gs = (float*)dsm;

    const int bx = blockIdx.x;
    const int j0 = (bx & 31) * 32;
    const int b0 = (bx >> 5) * 64;
    const int gcol0 = j0 * 4;
    const int tid = threadIdx.x;
    const int lane = tid & 31, w = tid >> 5;
    const int wm = w & 1, wn = w >> 1;
    const int qr = lane >> 2, qk = (lane & 3) * 2;
    const int ar = tid >> 2, akc = (tid & 3) * 8;
    const int br = tid >> 1, bkc = (tid & 1) * 16;

    const __nv_bfloat16* gBh = whhhi + (size_t)(gcol0 + br) * Hdim + bkc;
    const __nv_bfloat16* gBl = whhlo + (size_t)(gcol0 + br) * Hdim + bkc;

    float creg[8];
    #pragma unroll
    for (int i = 0; i < 8; i++) {
        int idx = tid + i * 256;
        creg[i] = c0[(b0 + (idx >> 5)) * Hdim + j0 + (idx & 31)];
    }

    for (int t = 0; t < Tlen; t++) {
        const __nv_bfloat16* hih = (t & 1) ? hB_hi : hA_hi;
        const __nv_bfloat16* hil = (t & 1) ? hB_lo : hA_lo;
        __nv_bfloat16* hoh = (t & 1) ? hA_hi : hB_hi;
        __nv_bfloat16* hol = (t & 1) ? hA_lo : hB_lo;

        float acc[2][4][4];
        #pragma unroll
        for (int mt = 0; mt < 2; mt++)
            #pragma unroll
            for (int nt = 0; nt < 4; nt++)
                #pragma unroll
                for (int q = 0; q < 4; q++) acc[mt][nt][q] = 0.f;

        mma_mainloop(hih + (size_t)(b0 + ar) * Hdim + akc,
                     hil + (size_t)(b0 + ar) * Hdim + akc,
                     gBh, gBl, smem_u, tid, acc);

        __syncthreads();
        #pragma unroll
        for (int mt = 0; mt < 2; mt++)
            #pragma unroll
            for (int nt = 0; nt < 4; nt++) {
                int r = wm * 32 + mt * 16 + qr;
                int cc = wn * 32 + nt * 8 + qk;
                *(float2*)&Gs[r * 132 + cc]       = make_float2(acc[mt][nt][0], acc[mt][nt][1]);
                *(float2*)&Gs[(r + 8) * 132 + cc] = make_float2(acc[mt][nt][2], acc[mt][nt][3]);
            }
        __syncthreads();

        #pragma unroll
        for (int i = 0; i < 8; i++) {
            int idx = tid + i * 256;
            int bl = idx >> 5, jj = idx & 31;
            float4 gv = *(const float4*)&Gs[bl * 132 + jj * 4];
            int b = b0 + bl, j = j0 + jj;
            int tok = (t == 0) ? 0 : atom_truth[b * Tlen + (t - 1)];
            const float* xp = xpart + (size_t)b * G4 + j;
            const float* ep = embproj + (size_t)tok * G4 + j;
            float ig = gv.x + xp[0]        + ep[0];
            float fg = gv.y + xp[Hdim]     + ep[Hdim];
            float gg = gv.z + xp[2 * Hdim] + ep[2 * Hdim];
            float og = gv.w + xp[3 * Hdim] + ep[3 * Hdim];
            ig = 1.f / (1.f + expf(-ig));
            fg = 1.f / (1.f + expf(-fg));
            og = 1.f / (1.f + expf(-og));
            gg = tanhf(gg);
            float cv = fg * creg[i] + ig * gg;
            creg[i] = cv;
            float hv = og * tanhf(cv);
            __nv_bfloat16 hh, hl;
            bf16split(hv, hh, hl);
            hoh[b * Hdim + j] = hh;
            hol[b * Hdim + j] = hl;
            size_t ho = ((size_t)t * Bsz + b) * Hdim + j;
            hshi[ho] = hh;
            hslo[ho] = hl;
        }

        if (t < Tlen - 1) grid_sync(tid, (unsigned)(t + 1));
    }
#endif
}

// ---------------------------------------------------------------------------
// Logits GEMM, tcgen05 path: C[16384,512] = hs @ W_out^T + b_out.
// Tiles 128m x 64n x 1024k; grid (8, 128). No-ops if tc unavailable.
// ---------------------------------------------------------------------------
__global__ __launch_bounds__(256, 1) void logits_tc(
    const __nv_bfloat16* __restrict__ Ahi_g,
    const __nv_bfloat16* __restrict__ Alo_g,
    const __nv_bfloat16* __restrict__ Bhi_g,
    const __nv_bfloat16* __restrict__ Blo_g,
    float* __restrict__ C,
    const float* __restrict__ bias)
{
#if defined(__CUDA_ARCH_FEAT_SM100_ALL)
    extern __shared__ __align__(1024) unsigned char dsm[];
    __shared__ unsigned s_tmem;
    __shared__ __align__(8) unsigned long long s_mbar[4];

    const unsigned smem_u = smem_u32(dsm);
    const int tid = threadIdx.x;
    const int wid = tid >> 5, lane = tid & 31;
    const int n0 = blockIdx.x * 64;
    const int m0 = blockIdx.y * 128;

    if (tid == 0) {
        #pragma unroll
        for (int i = 0; i < 4; i++) MBAR_INIT(smem_u32(&s_mbar[i]), 1);
    }
    __syncthreads();
    if (wid == 0) TC_ALLOC(smem_u32(&s_tmem), 512);
    __syncthreads();
    const unsigned tmem = s_tmem;
    unsigned mbu[4];
    #pragma unroll
    for (int i = 0; i < 4; i++) mbu[i] = smem_u32(&s_mbar[i]);
    int ph[4] = {0, 0, 0, 0};

    const int ra = tid >> 1, ca = (tid & 1) * 4;
    const int rb = tid >> 2, cbb = (tid & 3) * 2;
    const int ram = ra & 7, rbm = rb & 7;
    const __nv_bfloat16* Asrc_h = Ahi_g + (size_t)(m0 + ra) * Hdim;
    const __nv_bfloat16* Asrc_l = Alo_g + (size_t)(m0 + ra) * Hdim;
    const __nv_bfloat16* Bsrc_h = Bhi_g + (size_t)(n0 + rb) * Hdim;
    const __nv_bfloat16* Bsrc_l = Blo_g + (size_t)(n0 + rb) * Hdim;

    #define LFILL(kc_, st_) do { \
        unsigned ab = smem_u + (st_) * STG_SZ; \
        const __nv_bfloat16* sh = Asrc_h + (kc_) * 64; \
        const __nv_bfloat16* sl = Asrc_l + (kc_) * 64; \
        _Pragma("unroll") \
        for (int c = 0; c < 4; c++) { \
            int cc = ca + c; \
            unsigned d = ra * 128 + ((cc ^ ram) * 16); \
            CP16(ab + d,          sh + cc * 8); \
            CP16(ab + 16384 + d,  sl + cc * 8); \
        } \
        const __nv_bfloat16* bh = Bsrc_h + (kc_) * 64; \
        const __nv_bfloat16* bl = Bsrc_l + (kc_) * 64; \
        _Pragma("unroll") \
        for (int c = 0; c < 2; c++) { \
            int cc = cbb + c; \
            unsigned d = rb * 128 + ((cc ^ rbm) * 16); \
            CP16(ab + 32768 + d, bh + cc * 8); \
            CP16(ab + 40960 + d, bl + cc * 8); \
        } \
        CPCOMMIT(); \
    } while (0)

    LFILL(0, 0); LFILL(1, 1); LFILL(2, 2);

    for (int kc = 0; kc < 16; kc++) {
        if (kc <= 13) { CPWAIT(2); } else if (kc == 14) { CPWAIT(1); } else { CPWAIT(0); }
        __syncthreads();
        if (wid == 0 && elect1()) {
            unsigned sb = smem_u + (kc & 3) * STG_SZ;
            unsigned long long adh = mk_desc(sb);
            unsigned long long adl = mk_desc(sb + 16384);
            unsigned long long bdh = mk_desc(sb + 32768);
            unsigned long long bdl = mk_desc(sb + 40960);
            #pragma unroll
            for (int ks = 0; ks < 4; ks++) {
                unsigned en0 = (kc == 0 && ks == 0) ? 0u : 1u;
                tc_mma_f16_ss(tmem, adh + ks * 2, bdh + ks * 2, TC_IDESC, en0);
                tc_mma_f16_ss(tmem, adh + ks * 2, bdl + ks * 2, TC_IDESC, 1u);
                tc_mma_f16_ss(tmem, adl + ks * 2, bdh + ks * 2, TC_IDESC, 1u);
            }
            TC_COMMIT(mbu[kc & 3]);
        }
        if (kc + 3 < 16) {
            if (kc >= 1) {
                int s = (kc - 1) & 3;
                MBAR_WAIT(mbu[s], (unsigned)(ph[s] & 1));
                ph[s]++;
            }
            LFILL(kc + 3, (kc + 3) & 3);
        }
    }
    #pragma unroll
    for (int c = 12; c < 16; c++) {
        int s = c & 3;
        MBAR_WAIT(mbu[s], (unsigned)(ph[s] & 1));
        ph[s]++;
    }
    TC_FENCE_AFTER();

    unsigned dr[32];
    TC_LD32(dr, tmem + (wid >> 2) * 32);
    TC_WAIT_LD();
    TC_FENCE_BEFORE();

    // stage to smem [128][65] then coalesced global write with bias
    float* S = (float*)dsm;
    {
        int r = (wid & 3) * 32 + lane;
        int cb2 = (wid >> 2) * 32;
        #pragma unroll
        for (int c = 0; c < 32; c++) S[r * 65 + cb2 + c] = __uint_as_float(dr[c]);
    }
    __syncthreads();
    #pragma unroll
    for (int q = 0; q < 8; q++) {
        int idx = tid + q * 256;           // 0..2047 float4 units
        int rr = idx >> 4, c4 = (idx & 15) * 4;
        float4 bv = *(const float4*)&bias[n0 + c4];
        float4 v;
        v.x = S[rr * 65 + c4 + 0] + bv.x;
        v.y = S[rr * 65 + c4 + 1] + bv.y;
        v.z = S[rr * 65 + c4 + 2] + bv.z;
        v.w = S[rr * 65 + c4 + 3] + bv.w;
        *(float4*)&C[(size_t)(m0 + rr) * NTAG + n0 + c4] = v;
    }
    __syncthreads();
    if (wid == 0) TC_DEALLOC(tmem, 512);
    #undef LFILL
#endif
}

// ---------------------------------------------------------------------------
// Logits GEMM fallback (mma.sync) — no-ops when tcgen05 cubin active.
// ---------------------------------------------------------------------------
__global__ __launch_bounds__(256) void logits_mma(
    const __nv_bfloat16* __restrict__ Ahi_g,
    const __nv_bfloat16* __restrict__ Alo_g,
    const __nv_bfloat16* __restrict__ Bhi_g,
    const __nv_bfloat16* __restrict__ Blo_g,
    float* __restrict__ C,
    const float* __restrict__ bias)
{
    if (g_use_tc) return;
    extern __shared__ __align__(16) unsigned char dsm2[];
    unsigned smem_u = (unsigned)__cvta_generic_to_shared(dsm2);

    const int n0 = blockIdx.x * 128;
    const int m0 = blockIdx.y * 64;
    const int tid = threadIdx.x;
    const int lane = tid & 31, w = tid >> 5;
    const int wm = w & 1, wn = w >> 1;
    const int qr = lane >> 2, qk = (lane & 3) * 2;
    const int ar = tid >> 2, akc = (tid & 3) * 8;
    const int br = tid >> 1, bkc = (tid & 1) * 16;

    float acc[2][4][4];
    #pragma unroll
    for (int mt = 0; mt < 2; mt++)
        #pragma unroll
        for (int nt = 0; nt < 4; nt++)
            #pragma unroll
            for (int q = 0; q < 4; q++) acc[mt][nt][q] = 0.f;

    mma_mainloop(Ahi_g + (size_t)(m0 + ar) * Hdim + akc,
                 Alo_g + (size_t)(m0 + ar) * Hdim + akc,
                 Bhi_g + (size_t)(n0 + br) * Hdim + bkc,
                 Blo_g + (size_t)(n0 + br) * Hdim + bkc,
                 smem_u, tid, acc);

    #pragma unroll
    for (int mt = 0; mt < 2; mt++)
        #pragma unroll
        for (int nt = 0; nt < 4; nt++) {
            int m = m0 + wm * 32 + mt * 16 + qr;
            int n = n0 + wn * 32 + nt * 8 + qk;
            float b0v = bias[n], b1v = bias[n + 1];
            *(float2*)&C[(size_t)m * NTAG + n] =
                make_float2(acc[mt][nt][0] + b0v, acc[mt][nt][1] + b1v);
            *(float2*)&C[(size_t)(m + 8) * NTAG + n] =
                make_float2(acc[mt][nt][2] + b0v, acc[mt][nt][3] + b1v);
        }
}

// ---------------------------------------------------------------------------
// Mask detection / NLL / reduction
// ---------------------------------------------------------------------------
__global__ void detect_mask(const unsigned* __restrict__ m)
{
    __shared__ int isByte, isFloat;
    if (threadIdx.x == 0) { isByte = 0; isFloat = 0; }
    __syncthreads();
    for (int i = threadIdx.x; i < (Bsz * Tlen) / 4; i += blockDim.x) {
        unsigned v = m[i];
        if (v == 0x3F800000u) isFloat = 1;
        else if (v > 1u) isByte = 1;
    }
    __syncthreads();
    if (threadIdx.x == 0) g_mask_mode = isFloat ? 2 : (isByte ? 1 : 0);
}

__global__ __launch_bounds__(128) void nll_rows(
    const float* __restrict__ logits,
    const int* __restrict__ atom_truth,
    const void* __restrict__ atom_mask,
    float* __restrict__ rownll,
    float* __restrict__ rowmask)
{
    const int r = blockIdx.x;
    const int t = r >> 8;
    const int b = r & 255;
    const float* row = logits + (size_t)r * NTAG;
    const int tid = threadIdx.x;
    __shared__ float red[128];

    float mx = -1e30f;
    for (int i = tid; i < NTAG; i += 128) mx = fmaxf(mx, row[i]);
    red[tid] = mx; __syncthreads();
    for (int s = 64; s > 0; s >>= 1) {
        if (tid < s) red[tid] = fmaxf(red[tid], red[tid + s]);
        __syncthreads();
    }
    mx = red[0]; __syncthreads();

    float sm = 0.f;
    for (int i = tid; i < NTAG; i += 128) sm += __expf(row[i] - mx);
    red[tid] = sm; __syncthreads();
    for (int s = 64; s > 0; s >>= 1) {
        if (tid < s) red[tid] += red[tid + s];
        __syncthreads();
    }

    if (tid == 0) {
        int tgt = atom_truth[b * Tlen + t];
        float lp = row[tgt] - mx - logf(red[0]);
        int mode = g_mask_mode;
        float m;
        if (mode == 2)      m = (((const float*)atom_mask)[b * Tlen + t] != 0.f) ? 1.f : 0.f;
        else if (mode == 1) m = (((const unsigned char*)atom_mask)[b * Tlen + t] != 0) ? 1.f : 0.f;
        else                m = (((const int*)atom_mask)[b * Tlen + t] != 0) ? 1.f : 0.f;
        rownll[r]  = -lp * m;
        rowmask[r] = m;
    }
}

__global__ __launch_bounds__(256) void final_reduce(
    const float* __restrict__ rownll,
    const float* __restrict__ rowmask,
    float* __restrict__ out)
{
    __shared__ double rn[256], rm[256];
    double sn = 0.0, sm = 0.0;
    for (int i = threadIdx.x; i < Tlen * Bsz; i += 256) {
        sn += (double)rownll[i];
        sm += (double)rowmask[i];
    }
    rn[threadIdx.x] = sn; rm[threadIdx.x] = sm;
    __syncthreads();
    for (int s = 128; s > 0; s >>= 1) {
        if (threadIdx.x < s) {
            rn[threadIdx.x] += rn[threadIdx.x + s];
            rm[threadIdx.x] += rm[threadIdx.x + s];
        }
        __syncthreads();
    }
    if (threadIdx.x == 0) out[0] = (float)(rn[0] / rm[0]);
}

// ---------------------------------------------------------------------------
// Launch
// ---------------------------------------------------------------------------
extern "C" void kernel_launch(void* const* d_in, const int* in_sizes, int n_in,
                              void* d_out, int out_size)
{
    const float* x      = (const float*)d_in[0];
    const int*   atomtr = (const int*)d_in[1];
    const void*  mask   = d_in[2];
    const float* emb    = (const float*)d_in[3];
    const float* W_ih   = (const float*)d_in[4];
    const float* W_hh   = (const float*)d_in[5];
    const float* b_ih   = (const float*)d_in[6];
    const float* b_hh   = (const float*)d_in[7];
    const float* W_out  = (const float*)d_in[8];
    const float* b_out  = (const float*)d_in[9];
    const float* h0     = (const float*)d_in[10];
    const float* c0     = (const float*)d_in[11];

    float* sc = nullptr;
    cudaGetSymbolAddress((void**)&sc, g_scratch);
    float* xpart   = sc + 0;
    float* embproj = sc + 1048576;
    float* logits  = sc + 3407872;
    float* rownll  = sc + 11796480;
    float* rowmask = sc + 11812864;
    __nv_bfloat16* bb = (__nv_bfloat16*)(sc + 11829248);
    __nv_bfloat16* whh_hi  = bb + 0;
    __nv_bfloat16* whh_lo  = bb + 4194304;
    __nv_bfloat16* wout_hi = bb + 8388608;
    __nv_bfloat16* wout_lo = bb + 8912896;
    __nv_bfloat16* hA_hi   = bb + 9437184;
    __nv_bfloat16* hA_lo   = bb + 9699328;
    __nv_bfloat16* hB_hi   = bb + 9961472;
    __nv_bfloat16* hB_lo   = bb + 10223616;
    __nv_bfloat16* hs_hi   = bb + 10485760;
    __nv_bfloat16* hs_lo   = bb + 27262976;

    const int DSMEM_LOG = 3 * 30720;    // 92160
    static int attr_done = 0;
    if (!attr_done) {
        cudaFuncSetAttribute(lstm_seq,   cudaFuncAttributeMaxDynamicSharedMemorySize, DSMEM_LSTM);
        cudaFuncSetAttribute(logits_tc,  cudaFuncAttributeMaxDynamicSharedMemorySize, DSMEM_LSTM);
        cudaFuncSetAttribute(logits_mma, cudaFuncAttributeMaxDynamicSharedMemorySize, DSMEM_LOG);
        attr_done = 1;
    }

    detect_mask<<<1, 256>>>((const unsigned*)mask);
    init_bar<<<1, 1>>>();

    // one-time weight / state splits
    split_whh<<<4096, 256>>>(W_hh, whh_hi, whh_lo);
    split_plain<<<512, 256>>>(W_out, wout_hi, wout_lo);
    split_plain<<<256, 256>>>(h0, hA_hi, hA_lo);

    // xpart = x @ W_ih[:, :512]^T + b_ih + b_hh   [256, 4096]
    sgemm2<<<dim3(G4 / 64, Bsz / 128), 256>>>(x, Xdim, W_ih, DIN, xpart, G4, Xdim, b_ih, b_hh);
    // embproj = emb @ W_ih[:, 512:768]^T          [512, 4096]
    sgemm2<<<dim3(G4 / 64, NTAG / 128), 256>>>(emb, Edim, W_ih + Xdim, DIN, embproj, G4, Edim, nullptr, nullptr);

    // all 64 LSTM steps in one persistent kernel (tcgen05 or mma.sync path)
    lstm_seq<<<128, 256, DSMEM_LSTM>>>(
        hA_hi, hA_lo, hB_hi, hB_lo, c0, xpart, embproj,
        hs_hi, hs_lo, whh_hi, whh_lo, atomtr);

    // logits = hs @ W_out^T + b_out   [16384, 512]  (exactly one of these runs)
    logits_tc<<<dim3(NTAG / 64, (Tlen * Bsz) / 128), 256, DSMEM_LSTM>>>(
        hs_hi, hs_lo, wout_hi, wout_lo, logits, b_out);
    logits_mma<<<dim3(NTAG / 128, (Tlen * Bsz) / 64), 256, DSMEM_LOG>>>(
        hs_hi, hs_lo, wout_hi, wout_lo, logits, b_out);

    nll_rows<<<Tlen * Bsz, 128>>>(logits, atomtr, mask, rownll, rowmask);
    final_reduce<<<1, 256>>>(rownll, rowmask, (float*)d_out);
}

// round 12
// speedup vs baseline: 5.2851x; 1.2011x over previous
#include <cuda_runtime.h>
#include <cuda_fp16.h>
#include <math.h>

#define Bsz  256
#define Tlen 64
#define Hdim 1024
#define Xdim 512
#define Edim 256
#define DIN  768
#define G4   4096
#define NTAG 512

// ---- scratch layout ----
// floats:
//   xpart   @0          (1,048,576)
//   embproj @1,048,576  (2,097,152)
//   logits  @3,407,872  (8,388,608)
//   rownll  @11,796,480 (16,384)
//   rowmask @11,812,864 (16,384)
// fp16 region at float offset 11,829,248 (half-element offsets):
//   whh_hi 0            whh_lo 4,194,304
//   wout_hi 8,388,608   wout_lo 8,912,896
//   hA 9,437,184  hB 9,699,328
//   hs 9,961,472 (16,777,216)
__device__ float g_scratch[33849344];
__device__ int   g_mask_mode;
__device__ unsigned g_bar_arrive;
__device__ unsigned g_bar_gen;
__device__ unsigned g_arr2[2];
__device__ unsigned g_gen2[2];
__device__ int      g_use_tc;

// ---------------------------------------------------------------------------
// PTX helpers (portable)
// ---------------------------------------------------------------------------
#define MMA4F(c, a, b0_, b1_) \
    asm volatile("mma.sync.aligned.m16n8k16.row.col.f32.f16.f16.f32 " \
                 "{%0,%1,%2,%3},{%4,%5,%6,%7},{%8,%9},{%0,%1,%2,%3};" \
                 : "+f"((c)[0]), "+f"((c)[1]), "+f"((c)[2]), "+f"((c)[3]) \
                 : "r"((a)[0]), "r"((a)[1]), "r"((a)[2]), "r"((a)[3]), \
                   "r"(b0_), "r"(b1_))

#define LDSM4(r, addr) \
    asm volatile("ldmatrix.sync.aligned.m8n8.x4.shared.b16 {%0,%1,%2,%3}, [%4];" \
                 : "=r"((r)[0]), "=r"((r)[1]), "=r"((r)[2]), "=r"((r)[3]) \
                 : "r"(addr))

#define CP16(dst, src) \
    asm volatile("cp.async.cg.shared.global [%0], [%1], 16;" :: "r"(dst), "l"(src))
#define CPCOMMIT() asm volatile("cp.async.commit_group;" ::: "memory")
#define CPWAIT(n)  asm volatile("cp.async.wait_group %0;" :: "n"(n) : "memory")

#define FFMA2(d, a, b) asm("fma.rn.f32x2 %0, %1, %2, %0;" : "+l"(d) : "l"(a), "l"(b))
union F2U { unsigned long long u; float2 f; };
__device__ __forceinline__ unsigned long long dup2(float a) {
    unsigned x = __float_as_uint(a);
    return ((unsigned long long)x << 32) | (unsigned long long)x;
}

__device__ __forceinline__ void f16split(float v, __half& hi, __half& lo) {
    hi = __float2half_rn(v);
    lo = __float2half_rn(v - __half2float(hi));
}

__device__ __forceinline__ unsigned smem_u32(const void* p) {
    return (unsigned)__cvta_generic_to_shared(p);
}

// fast activations (safe at +/-inf)
__device__ __forceinline__ float fsig(float x) {
    return __fdividef(1.f, 1.f + __expf(-x));
}
__device__ __forceinline__ float ftanh(float x) {
    return 1.f - __fdividef(2.f, __expf(2.f * x) + 1.f);
}

// ---------------------------------------------------------------------------
// tcgen05 helpers — ONLY compiled on the sm_100a pass.
// ---------------------------------------------------------------------------
#if defined(__CUDA_ARCH_FEAT_SM100_ALL)
__device__ __forceinline__ bool elect1() {
    unsigned p;
    asm volatile("{\n\t.reg .pred p;\n\telect.sync _|p, 0xFFFFFFFF;\n\tselp.b32 %0,1,0,p;\n\t}"
                 : "=r"(p));
    return p != 0;
}
__device__ __forceinline__ unsigned long long mk_desc(unsigned addr) {
    // SW128, version=1 (Blackwell), SBO=64, LBO=1 (K-major, 128B rows)
    return 0x4000404000010000ULL | ((unsigned long long)(addr >> 4) & 0x3FFF);
}
__device__ __forceinline__ void tc_mma_f16_ss(unsigned d, unsigned long long ad,
                                              unsigned long long bd, unsigned idesc,
                                              unsigned en)
{
    asm volatile(
        "{\n\t.reg .pred p;\n\tsetp.ne.u32 p, %5, 0;\n\t"
        "tcgen05.mma.cta_group::1.kind::f16 [%0], %1, %2, %3, {%4, %4, %4, %4}, p;\n\t}"
        :: "r"(d), "l"(ad), "l"(bd), "r"(idesc), "r"(0u), "r"(en)
        : "memory");
}
#define TC_ALLOC(smaddr, n) \
    asm volatile("tcgen05.alloc.cta_group::1.sync.aligned.shared::cta.b32 [%0], %1;" \
                 :: "r"(smaddr), "r"((unsigned)(n)) : "memory")
#define TC_DEALLOC(base, n) \
    asm volatile("tcgen05.dealloc.cta_group::1.sync.aligned.b32 %0, %1;" \
                 :: "r"(base), "r"((unsigned)(n)))
#define TC_COMMIT(mb) \
    asm volatile("tcgen05.commit.cta_group::1.mbarrier::arrive::one.shared::cluster.b64 [%0];" \
                 :: "r"(mb) : "memory")
#define TC_FENCE_AFTER()  asm volatile("tcgen05.fence::after_thread_sync;" ::: "memory")
#define TC_FENCE_BEFORE() asm volatile("tcgen05.fence::before_thread_sync;" ::: "memory")
#define TC_WAIT_LD()      asm volatile("tcgen05.wait::ld.sync.aligned;" ::: "memory")

#define MBAR_INIT(mb, cnt) \
    asm volatile("mbarrier.init.shared.b64 [%0], %1;" :: "r"(mb), "r"((unsigned)(cnt)) : "memory")
#define MBAR_WAIT(mb, par) do { \
    unsigned _m = (mb), _p = (par), _d; \
    asm volatile("{\n\t.reg .pred p;\n\t" \
                 "mbarrier.try_wait.parity.acquire.cta.shared::cta.b64 p, [%1], %2;\n\t" \
                 "selp.b32 %0,1,0,p;\n\t}" : "=r"(_d) : "r"(_m), "r"(_p) : "memory"); \
    if (!_d) { \
        asm volatile("{\n\t.reg .pred P1;\n\t" \
                     "WL%=:\n\t" \
                     "mbarrier.try_wait.parity.acquire.cta.shared::cta.b64 P1, [%0], %1, 0x989680;\n\t" \
                     "@P1 bra.uni WD%=;\n\tbra.uni WL%=;\n\tWD%=:\n\t}" \
                     :: "r"(_m), "r"(_p) : "memory"); \
    } \
} while(0)

#define TC_LD32(r, addr) \
    asm volatile("tcgen05.ld.sync.aligned.32x32b.x32.b32 " \
        "{%0,%1,%2,%3,%4,%5,%6,%7,%8,%9,%10,%11,%12,%13,%14,%15," \
        "%16,%17,%18,%19,%20,%21,%22,%23,%24,%25,%26,%27,%28,%29,%30,%31}, [%32];" \
        : "=r"((r)[0]),"=r"((r)[1]),"=r"((r)[2]),"=r"((r)[3]), \
          "=r"((r)[4]),"=r"((r)[5]),"=r"((r)[6]),"=r"((r)[7]), \
          "=r"((r)[8]),"=r"((r)[9]),"=r"((r)[10]),"=r"((r)[11]), \
          "=r"((r)[12]),"=r"((r)[13]),"=r"((r)[14]),"=r"((r)[15]), \
          "=r"((r)[16]),"=r"((r)[17]),"=r"((r)[18]),"=r"((r)[19]), \
          "=r"((r)[20]),"=r"((r)[21]),"=r"((r)[22]),"=r"((r)[23]), \
          "=r"((r)[24]),"=r"((r)[25]),"=r"((r)[26]),"=r"((r)[27]), \
          "=r"((r)[28]),"=r"((r)[29]),"=r"((r)[30]),"=r"((r)[31]) \
        : "r"(addr))

// idesc: f32 accum, f16 a/b, M=128, N=64
#define IDESC_F16 0x08100010u
#endif // __CUDA_ARCH_FEAT_SM100_ALL

// ---------------------------------------------------------------------------
// Split / convert kernels (fp16)
// ---------------------------------------------------------------------------
__global__ void split_whh(const float* __restrict__ W,
                          __half* __restrict__ hi, __half* __restrict__ lo)
{
    int c = blockIdx.x;                 // gate-interleaved row c = j*4 + g
    int j = c >> 2, g = c & 3;
    const float* src = W + (size_t)(g * Hdim + j) * Hdim;
    int k = threadIdx.x * 4;
    float4 v = *(const float4*)&src[k];
    size_t o = (size_t)c * Hdim + k;
    float a[4] = {v.x, v.y, v.z, v.w};
    #pragma unroll
    for (int q = 0; q < 4; q++) f16split(a[q], hi[o + q], lo[o + q]);
}

__global__ void split_plain(const float* __restrict__ W,
                            __half* __restrict__ hi, __half* __restrict__ lo)
{
    int r = blockIdx.x;
    const float* src = W + (size_t)r * Hdim;
    int k = threadIdx.x * 4;
    float4 v = *(const float4*)&src[k];
    size_t o = (size_t)r * Hdim + k;
    float a[4] = {v.x, v.y, v.z, v.w};
    #pragma unroll
    for (int q = 0; q < 4; q++) f16split(a[q], hi[o + q], lo[o + q]);
}

__global__ void conv16(const float* __restrict__ src, __half* __restrict__ dst)
{
    int i = (blockIdx.x * 256 + threadIdx.x) * 4;
    float4 v = *(const float4*)&src[i];
    dst[i + 0] = __float2half_rn(v.x);
    dst[i + 1] = __float2half_rn(v.y);
    dst[i + 2] = __float2half_rn(v.z);
    dst[i + 3] = __float2half_rn(v.w);
}

// ---------------------------------------------------------------------------
// f32x2 SGEMM (xpart / embproj): C[M,N] = A[M,K] @ B[N,K]^T (+b0)(+b1)
// ---------------------------------------------------------------------------
__global__ __launch_bounds__(256) void sgemm2(
    const float* __restrict__ A, int lda,
    const float* __restrict__ Bm, int ldb,
    float* __restrict__ C, int ldc, int K,
    const float* __restrict__ bias0,
    const float* __restrict__ bias1)
{
    __shared__ unsigned long long As2[16][128];
    __shared__ float Bs[16][64];
    const int m0 = blockIdx.y * 128;
    const int n0 = blockIdx.x * 64;
    const int tid = threadIdx.x;
    const int rg = tid >> 4;
    const int cg = tid & 15;
    unsigned long long acc[8][2];
    #pragma unroll
    for (int i = 0; i < 8; i++) { acc[i][0] = 0ull; acc[i][1] = 0ull; }
    const int fm = tid >> 2;
    const int fk = (tid & 3) * 4;

    for (int k0 = 0; k0 < K; k0 += 16) {
        __syncthreads();
        #pragma unroll
        for (int half = 0; half < 2; half++) {
            int m = fm + half * 64;
            float4 v = *(const float4*)&A[(size_t)(m0 + m) * lda + k0 + fk];
            As2[fk + 0][m] = dup2(v.x);
            As2[fk + 1][m] = dup2(v.y);
            As2[fk + 2][m] = dup2(v.z);
            As2[fk + 3][m] = dup2(v.w);
        }
        {
            float4 v = *(const float4*)&Bm[(size_t)(n0 + fm) * ldb + k0 + fk];
            Bs[fk + 0][fm] = v.x; Bs[fk + 1][fm] = v.y;
            Bs[fk + 2][fm] = v.z; Bs[fk + 3][fm] = v.w;
        }
        __syncthreads();
        #pragma unroll
        for (int k = 0; k < 16; k++) {
            const ulonglong2* ap = (const ulonglong2*)&As2[k][rg * 8];
            ulonglong2 bv = *(const ulonglong2*)&Bs[k][cg * 4];
            #pragma unroll
            for (int i2 = 0; i2 < 4; i2++) {
                ulonglong2 a = ap[i2];
                FFMA2(acc[2 * i2 + 0][0], a.x, bv.x);
                FFMA2(acc[2 * i2 + 0][1], a.x, bv.y);
                FFMA2(acc[2 * i2 + 1][0], a.y, bv.x);
                FFMA2(acc[2 * i2 + 1][1], a.y, bv.y);
            }
        }
    }
    #pragma unroll
    for (int i = 0; i < 8; i++) {
        int m = m0 + rg * 8 + i;
        #pragma unroll
        for (int p = 0; p < 2; p++) {
            int n = n0 + cg * 4 + p * 2;
            F2U u; u.u = acc[i][p];
            float v0 = u.f.x, v1 = u.f.y;
            if (bias0) { v0 += bias0[n]; v1 += bias0[n + 1]; }
            if (bias1) { v0 += bias1[n]; v1 += bias1[n + 1]; }
            *(float2*)&C[(size_t)m * ldc + n] = make_float2(v0, v1);
        }
    }
}

// ---------------------------------------------------------------------------
// mma.sync fallback mainloop: 2-term fp16 (A single, B hi/lo). 64m x 128n.
// 3 stages x 25600 B: A[64][40]@0, Bh[128][40]@5120, Bl@15360.
// ---------------------------------------------------------------------------
__device__ __forceinline__ void mma_mainloop2(
    const __half* __restrict__ gA,
    const __half* __restrict__ gBh, const __half* __restrict__ gBl,
    unsigned smem_u, int tid, float acc[2][4][4])
{
    const int lane = tid & 31, w = tid >> 5;
    const int wm = w & 1, wn = w >> 1;
    const int lrow = (lane & 7) + ((lane >> 3) & 1) * 8;
    const int lcol = (lane >> 4) * 8;
    const unsigned aoff = ((wm * 32 + lrow) * 40 + lcol) * 2;
    const unsigned boff = ((wn * 32 + lrow) * 40 + lcol) * 2;

    const int ar = tid >> 2;
    const int br = tid >> 1;
    const unsigned dA  = (ar * 40 + (tid & 3) * 8) * 2;
    const unsigned dB0 = (br * 40 + (tid & 1) * 16) * 2;
    const unsigned dB1 = dB0 + 16;

    #pragma unroll
    for (int s = 0; s < 2; s++) {
        unsigned sb = smem_u + s * 25600;
        int k0 = s * 32;
        CP16(sb + dA,          gA + k0);
        CP16(sb + 5120  + dB0, gBh + k0);
        CP16(sb + 5120  + dB1, gBh + k0 + 8);
        CP16(sb + 15360 + dB0, gBl + k0);
        CP16(sb + 15360 + dB1, gBl + k0 + 8);
        CPCOMMIT();
    }

    for (int i = 0; i < 32; i++) {
        if (i < 31) { CPWAIT(1); } else { CPWAIT(0); }
        __syncthreads();
        if (i + 2 < 32) {
            unsigned sb = smem_u + ((i + 2) % 3) * 25600;
            int k0 = (i + 2) * 32;
            CP16(sb + dA,          gA + k0);
            CP16(sb + 5120  + dB0, gBh + k0);
            CP16(sb + 5120  + dB1, gBh + k0 + 8);
            CP16(sb + 15360 + dB0, gBl + k0);
            CP16(sb + 15360 + dB1, gBl + k0 + 8);
            CPCOMMIT();
        }
        unsigned sb = smem_u + (i % 3) * 25600;
        #pragma unroll
        for (int kh = 0; kh < 2; kh++) {
            const unsigned kb = kh * 32;
            unsigned a0[4], a1[4];
            LDSM4(a0, sb + aoff + kb);
            LDSM4(a1, sb + aoff + 1280 + kb);
            unsigned bh0[4], bh1[4], bl0[4], bl1[4];
            LDSM4(bh0, sb + 5120 + boff + kb);
            LDSM4(bh1, sb + 5120 + boff + 1280 + kb);
            LDSM4(bl0, sb + 15360 + boff + kb);
            LDSM4(bl1, sb + 15360 + boff + 1280 + kb);
            #pragma unroll
            for (int nt = 0; nt < 4; nt++) {
                const unsigned* bhp = (nt < 2) ? bh0 : bh1;
                const unsigned* blp = (nt < 2) ? bl0 : bl1;
                unsigned h0v = bhp[nt & 1], h1v = bhp[(nt & 1) + 2];
                unsigned l0v = blp[nt & 1], l1v = blp[(nt & 1) + 2];
                MMA4F(acc[0][nt], a0, h0v, h1v);
                MMA4F(acc[0][nt], a0, l0v, l1v);
                MMA4F(acc[1][nt], a1, h0v, h1v);
                MMA4F(acc[1][nt], a1, l0v, l1v);
            }
        }
    }
}

// ---------------------------------------------------------------------------
// Barriers
// ---------------------------------------------------------------------------
__global__ void init_bar() {
    g_bar_arrive = 0; g_bar_gen = 0;
    g_arr2[0] = 0; g_arr2[1] = 0;
    g_gen2[0] = 0; g_gen2[1] = 0;
#if defined(__CUDA_ARCH_FEAT_SM100_ALL)
    g_use_tc = 1;
#else
    g_use_tc = 0;
#endif
}

__device__ __forceinline__ void grid_sync(int tid, unsigned gen)
{
    __syncthreads();
    if (tid == 0) {
        __threadfence();
        unsigned a = atomicAdd(&g_bar_arrive, 1);
        if (a == 127) {
            g_bar_arrive = 0;
            __threadfence();
            atomicExch(&g_bar_gen, gen);
        } else {
            while (atomicAdd(&g_bar_gen, 0u) < gen) __nanosleep(64);
            __threadfence();
        }
    }
    __syncthreads();
}

#define STG_SZ 32768     // tcgen05 stage: A 16K @0, Bhi 8K @16384, Blo 8K @24576
#define N_STG  6
#define DSMEM_LSTM (N_STG * STG_SZ)   // 196608

// ---------------------------------------------------------------------------
// Persistent LSTM sequence kernel — dual path.
// tcgen05: block = 128 batch x 64 gate-cols (16 j x 4 gates, rows j*4+g),
// A = h fp16 single, B = W fp16 pair, 2 MMA terms, 6-stage pipeline.
// ---------------------------------------------------------------------------
__global__ __launch_bounds__(256, 1) void lstm_seq(
    __half* hA, __half* hB,
    const float* __restrict__ c0,
    const float* __restrict__ xpart,
    const float* __restrict__ embproj,
    __half* __restrict__ hs,
    const __half* __restrict__ whhhi,
    const __half* __restrict__ whhlo,
    const int* __restrict__ atom_truth)
{
#if defined(__CUDA_ARCH_FEAT_SM100_ALL)
    extern __shared__ __align__(1024) unsigned char dsm[];
    __shared__ unsigned s_tmem;
    __shared__ __align__(8) unsigned long long s_mbar[N_STG];

    const unsigned smem_u = smem_u32(dsm);
    const int tid = threadIdx.x;
    const int wid = tid >> 5, lane = tid & 31;
    const int bx = blockIdx.x;
    const int half = bx >> 6;
    const int b0 = half * 128;
    const int ntb = bx & 63;
    const int c0g = ntb * 64;
    const int jb = ntb * 16;

    if (tid == 0) {
        #pragma unroll
        for (int i = 0; i < N_STG; i++) MBAR_INIT(smem_u32(&s_mbar[i]), 1);
    }
    __syncthreads();
    if (wid == 0) TC_ALLOC(smem_u32(&s_tmem), 512);
    __syncthreads();
    const unsigned tmem = s_tmem;
    unsigned mbu[N_STG];
    #pragma unroll
    for (int i = 0; i < N_STG; i++) mbu[i] = smem_u32(&s_mbar[i]);
    int ph[N_STG] = {0, 0, 0, 0, 0, 0};

    // fill geometry
    const int ra = tid >> 1, ca = (tid & 1) * 4;       // A: row, 4 x 16B chunks
    const int rb = tid >> 2, cb2 = (tid & 3) * 2;      // B: row, 2 chunks
    const int ram = ra & 7, rbm = rb & 7;
    const __half* Bsrc_h = whhhi + (size_t)(c0g + rb) * Hdim;
    const __half* Bsrc_l = whhlo + (size_t)(c0g + rb) * Hdim;
    const __half* Asrc;   // set per step

    // epilogue geometry
    const int b = b0 + (wid & 3) * 32 + lane;
    const int jh = (wid >> 2) * 8;
    float creg[8];
    {
        const float* cp = c0 + (size_t)b * Hdim + jb + jh;
        float4 v0 = *(const float4*)&cp[0];
        float4 v1 = *(const float4*)&cp[4];
        creg[0] = v0.x; creg[1] = v0.y; creg[2] = v0.z; creg[3] = v0.w;
        creg[4] = v1.x; creg[5] = v1.y; creg[6] = v1.z; creg[7] = v1.w;
    }

    #define FILL_B(kc_, st_) do { \
        unsigned ab = smem_u + (st_) * STG_SZ; \
        const __half* bh = Bsrc_h + (kc_) * 64; \
        const __half* bl = Bsrc_l + (kc_) * 64; \
        _Pragma("unroll") \
        for (int c = 0; c < 2; c++) { \
            int cc = cb2 + c; \
            unsigned d = rb * 128 + ((cc ^ rbm) * 16); \
            CP16(ab + 16384 + d, bh + cc * 8); \
            CP16(ab + 24576 + d, bl + cc * 8); \
        } \
        CPCOMMIT(); \
    } while (0)

    #define FILL_A(kc_, st_) do { \
        unsigned ab = smem_u + (st_) * STG_SZ; \
        const __half* sh = Asrc + (kc_) * 64; \
        _Pragma("unroll") \
        for (int c = 0; c < 4; c++) { \
            int cc = ca + c; \
            unsigned d = ra * 128 + ((cc ^ ram) * 16); \
            CP16(ab + d, sh + cc * 8); \
        } \
        CPCOMMIT(); \
    } while (0)

    #define FILL_AB(kc_, st_) do { \
        unsigned ab = smem_u + (st_) * STG_SZ; \
        const __half* sh = Asrc + (kc_) * 64; \
        _Pragma("unroll") \
        for (int c = 0; c < 4; c++) { \
            int cc = ca + c; \
            unsigned d = ra * 128 + ((cc ^ ram) * 16); \
            CP16(ab + d, sh + cc * 8); \
        } \
        const __half* bh = Bsrc_h + (kc_) * 64; \
        const __half* bl = Bsrc_l + (kc_) * 64; \
        _Pragma("unroll") \
        for (int c = 0; c < 2; c++) { \
            int cc = cb2 + c; \
            unsigned d = rb * 128 + ((cc ^ rbm) * 16); \
            CP16(ab + 16384 + d, bh + cc * 8); \
            CP16(ab + 24576 + d, bl + cc * 8); \
        } \
        CPCOMMIT(); \
    } while (0)

    // W prefetch for step 0: stages 0..4
    FILL_B(0, 0); FILL_B(1, 1); FILL_B(2, 2); FILL_B(3, 3); FILL_B(4, 4);

    for (int t = 0; t < Tlen; t++) {
        const __half* hin = (t & 1) ? hB : hA;
        __half* hout      = (t & 1) ? hA : hB;
        Asrc = hin + (size_t)(b0 + ra) * Hdim;

        FILL_A(0, 0); FILL_A(1, 1); FILL_A(2, 2); FILL_A(3, 3); FILL_A(4, 4);

        for (int kc = 0; kc < 16; kc++) {
            if (kc <= 11)      { CPWAIT(4); }
            else if (kc == 12) { CPWAIT(3); }
            else if (kc == 13) { CPWAIT(2); }
            else if (kc == 14) { CPWAIT(1); }
            else               { CPWAIT(0); }
            __syncthreads();
            if (wid == 0 && elect1()) {
                unsigned sb = smem_u + (kc % N_STG) * STG_SZ;
                unsigned long long ad  = mk_desc(sb);
                unsigned long long bdh = mk_desc(sb + 16384);
                unsigned long long bdl = mk_desc(sb + 24576);
                #pragma unroll
                for (int ks = 0; ks < 4; ks++) {
                    unsigned en0 = (kc == 0 && ks == 0) ? 0u : 1u;
                    tc_mma_f16_ss(tmem, ad + ks * 2, bdh + ks * 2, IDESC_F16, en0);
                    tc_mma_f16_ss(tmem, ad + ks * 2, bdl + ks * 2, IDESC_F16, 1u);
                }
                TC_COMMIT(mbu[kc % N_STG]);
            }
            if (kc + 5 < 16) {
                if (kc >= 1) {
                    int s = (kc - 1) % N_STG;
                    MBAR_WAIT(mbu[s], (unsigned)(ph[s] & 1));
                    ph[s]++;
                }
                FILL_AB(kc + 5, (kc + 5) % N_STG);
            }
        }

        // prefetch epilogue operands while tail MMAs drain
        int tok = (t == 0) ? 0 : atom_truth[b * Tlen + (t - 1)];
        const float* xp = xpart + (size_t)b * G4 + jb + jh;
        const float* ep = embproj + (size_t)tok * G4 + jb + jh;
        float xg[4][8], eg[4][8];
        #pragma unroll
        for (int p = 0; p < 4; p++) {
            float4 a0 = *(const float4*)&xp[p * Hdim];
            float4 a1 = *(const float4*)&xp[p * Hdim + 4];
            float4 e0 = *(const float4*)&ep[p * Hdim];
            float4 e1 = *(const float4*)&ep[p * Hdim + 4];
            xg[p][0] = a0.x; xg[p][1] = a0.y; xg[p][2] = a0.z; xg[p][3] = a0.w;
            xg[p][4] = a1.x; xg[p][5] = a1.y; xg[p][6] = a1.z; xg[p][7] = a1.w;
            eg[p][0] = e0.x; eg[p][1] = e0.y; eg[p][2] = e0.z; eg[p][3] = e0.w;
            eg[p][4] = e1.x; eg[p][5] = e1.y; eg[p][6] = e1.z; eg[p][7] = e1.w;
        }

        // tail waits: chunks 10..15
        #pragma unroll
        for (int c = 10; c < 16; c++) {
            int s = c % N_STG;
            MBAR_WAIT(mbu[s], (unsigned)(ph[s] & 1));
            ph[s]++;
        }
        TC_FENCE_AFTER();

        // next step's W prefetch, overlapped with epilogue + barrier
        if (t < Tlen - 1) {
            FILL_B(0, 0); FILL_B(1, 1); FILL_B(2, 2); FILL_B(3, 3); FILL_B(4, 4);
        }

        unsigned dr[32];
        TC_LD32(dr, tmem + (wid >> 2) * 32);
        TC_WAIT_LD();
        TC_FENCE_BEFORE();

        __half hh[8];
        #pragma unroll
        for (int jl = 0; jl < 8; jl++) {
            float ig = __uint_as_float(dr[4 * jl + 0]) + xg[0][jl] + eg[0][jl];
            float fg = __uint_as_float(dr[4 * jl + 1]) + xg[1][jl] + eg[1][jl];
            float gg = __uint_as_float(dr[4 * jl + 2]) + xg[2][jl] + eg[2][jl];
            float og = __uint_as_float(dr[4 * jl + 3]) + xg[3][jl] + eg[3][jl];
            ig = fsig(ig); fg = fsig(fg); og = fsig(og); gg = ftanh(gg);
            float cv = fg * creg[jl] + ig * gg;
            creg[jl] = cv;
            hh[jl] = __float2half_rn(og * ftanh(cv));
        }
        {
            size_t o = (size_t)b * Hdim + jb + jh;
            *(uint4*)&hout[o] = *(uint4*)&hh[0];
            size_t ho = ((size_t)t * Bsz + b) * Hdim + jb + jh;
            *(uint4*)&hs[ho] = *(uint4*)&hh[0];
        }

        if (t < Tlen - 1) {
            __syncthreads();
            if (tid == 0) {
                __threadfence();
                unsigned old = atomicAdd(&g_arr2[half], 1);
                if (old == 63) {
                    g_arr2[half] = 0;
                    asm volatile("st.release.gpu.b32 [%0], %1;"
                                 :: "l"(&g_gen2[half]), "r"((unsigned)(t + 1)) : "memory");
                } else {
                    unsigned g;
                    do {
                        asm volatile("ld.acquire.gpu.b32 %0, [%1];"
                                     : "=r"(g) : "l"(&g_gen2[half]) : "memory");
                        if (g < (unsigned)(t + 1)) __nanosleep(32);
                    } while (g < (unsigned)(t + 1));
                }
            }
            __syncthreads();
        }
    }

    __syncthreads();
    if (wid == 0) TC_DEALLOC(tmem, 512);
    #undef FILL_B
    #undef FILL_A
    #undef FILL_AB

#else
    // ===================== mma.sync fallback (fp16 2-term) =====================
    extern __shared__ __align__(1024) unsigned char dsm[];
    unsigned smem_u = smem_u32(dsm);
    float* Gs = (float*)dsm;

    const int bx = blockIdx.x;
    const int j0 = (bx & 31) * 32;
    const int b0 = (bx >> 5) * 64;
    const int gcol0 = j0 * 4;
    const int tid = threadIdx.x;
    const int lane = tid & 31, w = tid >> 5;
    const int wm = w & 1, wn = w >> 1;
    const int qr = lane >> 2, qk = (lane & 3) * 2;
    const int ar = tid >> 2, akc = (tid & 3) * 8;
    const int br = tid >> 1, bkc = (tid & 1) * 16;

    const __half* gBh = whhhi + (size_t)(gcol0 + br) * Hdim + bkc;
    const __half* gBl = whhlo + (size_t)(gcol0 + br) * Hdim + bkc;

    float creg[8];
    #pragma unroll
    for (int i = 0; i < 8; i++) {
        int idx = tid + i * 256;
        creg[i] = c0[(b0 + (idx >> 5)) * Hdim + j0 + (idx & 31)];
    }

    for (int t = 0; t < Tlen; t++) {
        const __half* hin = (t & 1) ? hB : hA;
        __half* hout      = (t & 1) ? hA : hB;

        float acc[2][4][4];
        #pragma unroll
        for (int mt = 0; mt < 2; mt++)
            #pragma unroll
            for (int nt = 0; nt < 4; nt++)
                #pragma unroll
                for (int q = 0; q < 4; q++) acc[mt][nt][q] = 0.f;

        mma_mainloop2(hin + (size_t)(b0 + ar) * Hdim + akc, gBh, gBl,
                      smem_u, tid, acc);

        __syncthreads();
        #pragma unroll
        for (int mt = 0; mt < 2; mt++)
            #pragma unroll
            for (int nt = 0; nt < 4; nt++) {
                int r = wm * 32 + mt * 16 + qr;
                int cc = wn * 32 + nt * 8 + qk;
                *(float2*)&Gs[r * 132 + cc]       = make_float2(acc[mt][nt][0], acc[mt][nt][1]);
                *(float2*)&Gs[(r + 8) * 132 + cc] = make_float2(acc[mt][nt][2], acc[mt][nt][3]);
            }
        __syncthreads();

        #pragma unroll
        for (int i = 0; i < 8; i++) {
            int idx = tid + i * 256;
            int bl = idx >> 5, jj = idx & 31;
            float4 gv = *(const float4*)&Gs[bl * 132 + jj * 4];
            int b = b0 + bl, j = j0 + jj;
            int tok = (t == 0) ? 0 : atom_truth[b * Tlen + (t - 1)];
            const float* xp = xpart + (size_t)b * G4 + j;
            const float* ep = embproj + (size_t)tok * G4 + j;
            float ig = gv.x + xp[0]        + ep[0];
            float fg = gv.y + xp[Hdim]     + ep[Hdim];
            float gg = gv.z + xp[2 * Hdim] + ep[2 * Hdim];
            float og = gv.w + xp[3 * Hdim] + ep[3 * Hdim];
            ig = fsig(ig); fg = fsig(fg); og = fsig(og); gg = ftanh(gg);
            float cv = fg * creg[i] + ig * gg;
            creg[i] = cv;
            __half hv = __float2half_rn(og * ftanh(cv));
            hout[b * Hdim + j] = hv;
            hs[((size_t)t * Bsz + b) * Hdim + j] = hv;
        }

        if (t < Tlen - 1) grid_sync(tid, (unsigned)(t + 1));
    }
#endif
}

// ---------------------------------------------------------------------------
// Logits GEMM, tcgen05: C[16384,512] = hs @ W_out^T + b_out.
// A = hs fp16 single, B = wout pair. Tiles 128m x 64n; grid (8, 128).
// ---------------------------------------------------------------------------
__global__ __launch_bounds__(256, 1) void logits_tc(
    const __half* __restrict__ A_g,
    const __half* __restrict__ Bhi_g,
    const __half* __restrict__ Blo_g,
    float* __restrict__ C,
    const float* __restrict__ bias)
{
#if defined(__CUDA_ARCH_FEAT_SM100_ALL)
    extern __shared__ __align__(1024) unsigned char dsm[];
    __shared__ unsigned s_tmem;
    __shared__ __align__(8) unsigned long long s_mbar[N_STG];

    const unsigned smem_u = smem_u32(dsm);
    const int tid = threadIdx.x;
    const int wid = tid >> 5, lane = tid & 31;
    const int n0 = blockIdx.x * 64;
    const int m0 = blockIdx.y * 128;

    if (tid == 0) {
        #pragma unroll
        for (int i = 0; i < N_STG; i++) MBAR_INIT(smem_u32(&s_mbar[i]), 1);
    }
    __syncthreads();
    if (wid == 0) TC_ALLOC(smem_u32(&s_tmem), 512);
    __syncthreads();
    const unsigned tmem = s_tmem;
    unsigned mbu[N_STG];
    #pragma unroll
    for (int i = 0; i < N_STG; i++) mbu[i] = smem_u32(&s_mbar[i]);
    int ph[N_STG] = {0, 0, 0, 0, 0, 0};

    const int ra = tid >> 1, ca = (tid & 1) * 4;
    const int rb = tid >> 2, cb2 = (tid & 3) * 2;
    const int ram = ra & 7, rbm = rb & 7;
    const __half* Asrc   = A_g   + (size_t)(m0 + ra) * Hdim;
    const __half* Bsrc_h = Bhi_g + (size_t)(n0 + rb) * Hdim;
    const __half* Bsrc_l = Blo_g + (size_t)(n0 + rb) * Hdim;

    #define LFILL(kc_, st_) do { \
        unsigned ab = smem_u + (st_) * STG_SZ; \
        const __half* sh = Asrc + (kc_) * 64; \
        _Pragma("unroll") \
        for (int c = 0; c < 4; c++) { \
            int cc = ca + c; \
            unsigned d = ra * 128 + ((cc ^ ram) * 16); \
            CP16(ab + d, sh + cc * 8); \
        } \
        const __half* bh = Bsrc_h + (kc_) * 64; \
        const __half* bl = Bsrc_l + (kc_) * 64; \
        _Pragma("unroll") \
        for (int c = 0; c < 2; c++) { \
            int cc = cb2 + c; \
            unsigned d = rb * 128 + ((cc ^ rbm) * 16); \
            CP16(ab + 16384 + d, bh + cc * 8); \
            CP16(ab + 24576 + d, bl + cc * 8); \
        } \
        CPCOMMIT(); \
    } while (0)

    LFILL(0, 0); LFILL(1, 1); LFILL(2, 2); LFILL(3, 3); LFILL(4, 4);

    for (int kc = 0; kc < 16; kc++) {
        if (kc <= 11)      { CPWAIT(4); }
        else if (kc == 12) { CPWAIT(3); }
        else if (kc == 13) { CPWAIT(2); }
        else if (kc == 14) { CPWAIT(1); }
        else               { CPWAIT(0); }
        __syncthreads();
        if (wid == 0 && elect1()) {
            unsigned sb = smem_u + (kc % N_STG) * STG_SZ;
            unsigned long long ad  = mk_desc(sb);
            unsigned long long bdh = mk_desc(sb + 16384);
            unsigned long long bdl = mk_desc(sb + 24576);
            #pragma unroll
            for (int ks = 0; ks < 4; ks++) {
                unsigned en0 = (kc == 0 && ks == 0) ? 0u : 1u;
                tc_mma_f16_ss(tmem, ad + ks * 2, bdh + ks * 2, IDESC_F16, en0);
                tc_mma_f16_ss(tmem, ad + ks * 2, bdl + ks * 2, IDESC_F16, 1u);
            }
            TC_COMMIT(mbu[kc % N_STG]);
        }
        if (kc + 5 < 16) {
            if (kc >= 1) {
                int s = (kc - 1) % N_STG;
                MBAR_WAIT(mbu[s], (unsigned)(ph[s] & 1));
                ph[s]++;
            }
            LFILL(kc + 5, (kc + 5) % N_STG);
        }
    }
    #pragma unroll
    for (int c = 10; c < 16; c++) {
        int s = c % N_STG;
        MBAR_WAIT(mbu[s], (unsigned)(ph[s] & 1));
        ph[s]++;
    }
    TC_FENCE_AFTER();

    unsigned dr[32];
    TC_LD32(dr, tmem + (wid >> 2) * 32);
    TC_WAIT_LD();
    TC_FENCE_BEFORE();

    // stage to smem [128][65] then coalesced write with bias
    float* S = (float*)dsm;
    {
        int r = (wid & 3) * 32 + lane;
        int cb = (wid >> 2) * 32;
        #pragma unroll
        for (int c = 0; c < 32; c++) S[r * 65 + cb + c] = __uint_as_float(dr[c]);
    }
    __syncthreads();
    #pragma unroll
    for (int q = 0; q < 8; q++) {
        int idx = tid + q * 256;
        int rr = idx >> 4, c4 = (idx & 15) * 4;
        float4 bv = *(const float4*)&bias[n0 + c4];
        float4 v;
        v.x = S[rr * 65 + c4 + 0] + bv.x;
        v.y = S[rr * 65 + c4 + 1] + bv.y;
        v.z = S[rr * 65 + c4 + 2] + bv.z;
        v.w = S[rr * 65 + c4 + 3] + bv.w;
        *(float4*)&C[(size_t)(m0 + rr) * NTAG + n0 + c4] = v;
    }
    __syncthreads();
    if (wid == 0) TC_DEALLOC(tmem, 512);
    #undef LFILL
#endif
}

// ---------------------------------------------------------------------------
// Logits fallback (mma.sync) — no-ops when tcgen05 cubin active.
// ---------------------------------------------------------------------------
__global__ __launch_bounds__(256) void logits_mma(
    const __half* __restrict__ A_g,
    const __half* __restrict__ Bhi_g,
    const __half* __restrict__ Blo_g,
    float* __restrict__ C,
    const float* __restrict__ bias)
{
    if (g_use_tc) return;
    extern __shared__ __align__(16) unsigned char dsm2[];
    unsigned smem_u = (unsigned)__cvta_generic_to_shared(dsm2);

    const int n0 = blockIdx.x * 128;
    const int m0 = blockIdx.y * 64;
    const int tid = threadIdx.x;
    const int lane = tid & 31, w = tid >> 5;
    const int wm = w & 1, wn = w >> 1;
    const int qr = lane >> 2, qk = (lane & 3) * 2;
    const int ar = tid >> 2, akc = (tid & 3) * 8;
    const int br = tid >> 1, bkc = (tid & 1) * 16;

    float acc[2][4][4];
    #pragma unroll
    for (int mt = 0; mt < 2; mt++)
        #pragma unroll
        for (int nt = 0; nt < 4; nt++)
            #pragma unroll
            for (int q = 0; q < 4; q++) acc[mt][nt][q] = 0.f;

    mma_mainloop2(A_g + (size_t)(m0 + ar) * Hdim + akc,
                  Bhi_g + (size_t)(n0 + br) * Hdim + bkc,
                  Blo_g + (size_t)(n0 + br) * Hdim + bkc,
                  smem_u, tid, acc);

    #pragma unroll
    for (int mt = 0; mt < 2; mt++)
        #pragma unroll
        for (int nt = 0; nt < 4; nt++) {
            int m = m0 + wm * 32 + mt * 16 + qr;
            int n = n0 + wn * 32 + nt * 8 + qk;
            float b0v = bias[n], b1v = bias[n + 1];
            *(float2*)&C[(size_t)m * NTAG + n] =
                make_float2(acc[mt][nt][0] + b0v, acc[mt][nt][1] + b1v);
            *(float2*)&C[(size_t)(m + 8) * NTAG + n] =
                make_float2(acc[mt][nt][2] + b0v, acc[mt][nt][3] + b1v);
        }
}

// ---------------------------------------------------------------------------
// Mask detection / NLL / reduction
// ---------------------------------------------------------------------------
__global__ void detect_mask(const unsigned* __restrict__ m)
{
    __shared__ int isByte, isFloat;
    if (threadIdx.x == 0) { isByte = 0; isFloat = 0; }
    __syncthreads();
    for (int i = threadIdx.x; i < (Bsz * Tlen) / 4; i += blockDim.x) {
        unsigned v = m[i];
        if (v == 0x3F800000u) isFloat = 1;
        else if (v > 1u) isByte = 1;
    }
    __syncthreads();
    if (threadIdx.x == 0) g_mask_mode = isFloat ? 2 : (isByte ? 1 : 0);
}

__global__ __launch_bounds__(128) void nll_rows(
    const float* __restrict__ logits,
    const int* __restrict__ atom_truth,
    const void* __restrict__ atom_mask,
    float* __restrict__ rownll,
    float* __restrict__ rowmask)
{
    const int r = blockIdx.x;
    const int t = r >> 8;
    const int b = r & 255;
    const float* row = logits + (size_t)r * NTAG;
    const int tid = threadIdx.x;
    __shared__ float red[128];

    float mx = -1e30f;
    for (int i = tid; i < NTAG; i += 128) mx = fmaxf(mx, row[i]);
    red[tid] = mx; __syncthreads();
    for (int s = 64; s > 0; s >>= 1) {
        if (tid < s) red[tid] = fmaxf(red[tid], red[tid + s]);
        __syncthreads();
    }
    mx = red[0]; __syncthreads();

    float sm = 0.f;
    for (int i = tid; i < NTAG; i += 128) sm += __expf(row[i] - mx);
    red[tid] = sm; __syncthreads();
    for (int s = 64; s > 0; s >>= 1) {
        if (tid < s) red[tid] += red[tid + s];
        __syncthreads();
    }

    if (tid == 0) {
        int tgt = atom_truth[b * Tlen + t];
        float lp = row[tgt] - mx - logf(red[0]);
        int mode = g_mask_mode;
        float m;
        if (mode == 2)      m = (((const float*)atom_mask)[b * Tlen + t] != 0.f) ? 1.f : 0.f;
        else if (mode == 1) m = (((const unsigned char*)atom_mask)[b * Tlen + t] != 0) ? 1.f : 0.f;
        else                m = (((const int*)atom_mask)[b * Tlen + t] != 0) ? 1.f : 0.f;
        rownll[r]  = -lp * m;
        rowmask[r] = m;
    }
}

__global__ __launch_bounds__(256) void final_reduce(
    const float* __restrict__ rownll,
    const float* __restrict__ rowmask,
    float* __restrict__ out)
{
    __shared__ double rn[256], rm[256];
    double sn = 0.0, sm = 0.0;
    for (int i = threadIdx.x; i < Tlen * Bsz; i += 256) {
        sn += (double)rownll[i];
        sm += (double)rowmask[i];
    }
    rn[threadIdx.x] = sn; rm[threadIdx.x] = sm;
    __syncthreads();
    for (int s = 128; s > 0; s >>= 1) {
        if (threadIdx.x < s) {
            rn[threadIdx.x] += rn[threadIdx.x + s];
            rm[threadIdx.x] += rm[threadIdx.x + s];
        }
        __syncthreads();
    }
    if (threadIdx.x == 0) out[0] = (float)(rn[0] / rm[0]);
}

// ---------------------------------------------------------------------------
// Launch
// ---------------------------------------------------------------------------
extern "C" void kernel_launch(void* const* d_in, const int* in_sizes, int n_in,
                              void* d_out, int out_size)
{
    const float* x      = (const float*)d_in[0];
    const int*   atomtr = (const int*)d_in[1];
    const void*  mask   = d_in[2];
    const float* emb    = (const float*)d_in[3];
    const float* W_ih   = (const float*)d_in[4];
    const float* W_hh   = (const float*)d_in[5];
    const float* b_ih   = (const float*)d_in[6];
    const float* b_hh   = (const float*)d_in[7];
    const float* W_out  = (const float*)d_in[8];
    const float* b_out  = (const float*)d_in[9];
    const float* h0     = (const float*)d_in[10];
    const float* c0     = (const float*)d_in[11];

    float* sc = nullptr;
    cudaGetSymbolAddress((void**)&sc, g_scratch);
    float* xpart   = sc + 0;
    float* embproj = sc + 1048576;
    float* logits  = sc + 3407872;
    float* rownll  = sc + 11796480;
    float* rowmask = sc + 11812864;
    __half* hb = (__half*)(sc + 11829248);
    __half* whh_hi  = hb + 0;
    __half* whh_lo  = hb + 4194304;
    __half* wout_hi = hb + 8388608;
    __half* wout_lo = hb + 8912896;
    __half* hA      = hb + 9437184;
    __half* hB      = hb + 9699328;
    __half* hs      = hb + 9961472;

    const int DSMEM_LOG = 3 * 25600;   // fallback logits: 76800
    static int attr_done = 0;
    if (!attr_done) {
        cudaFuncSetAttribute(lstm_seq,   cudaFuncAttributeMaxDynamicSharedMemorySize, DSMEM_LSTM);
        cudaFuncSetAttribute(logits_tc,  cudaFuncAttributeMaxDynamicSharedMemorySize, DSMEM_LSTM);
        cudaFuncSetAttribute(logits_mma, cudaFuncAttributeMaxDynamicSharedMemorySize, DSMEM_LOG);
        attr_done = 1;
    }

    detect_mask<<<1, 256>>>((const unsigned*)mask);
    init_bar<<<1, 1>>>();

    // one-time weight / state conversions
    split_whh<<<4096, 256>>>(W_hh, whh_hi, whh_lo);
    split_plain<<<512, 256>>>(W_out, wout_hi, wout_lo);
    conv16<<<256, 256>>>(h0, hA);

    // xpart = x @ W_ih[:, :512]^T + b_ih + b_hh   [256, 4096]
    sgemm2<<<dim3(G4 / 64, Bsz / 128), 256>>>(x, Xdim, W_ih, DIN, xpart, G4, Xdim, b_ih, b_hh);
    // embproj = emb @ W_ih[:, 512:768]^T          [512, 4096]
    sgemm2<<<dim3(G4 / 64, NTAG / 128), 256>>>(emb, Edim, W_ih + Xdim, DIN, embproj, G4, Edim, nullptr, nullptr);

    // all 64 LSTM steps in one persistent kernel
    lstm_seq<<<128, 256, DSMEM_LSTM>>>(
        hA, hB, c0, xpart, embproj, hs, whh_hi, whh_lo, atomtr);

    // logits = hs @ W_out^T + b_out   [16384, 512]  (exactly one of these runs)
    logits_tc<<<dim3(NTAG / 64, (Tlen * Bsz) / 128), 256, DSMEM_LSTM>>>(
        hs, wout_hi, wout_lo, logits, b_out);
    logits_mma<<<dim3(NTAG / 128, (Tlen * Bsz) / 64), 256, DSMEM_LOG>>>(
        hs, wout_hi, wout_lo, logits, b_out);

    nll_rows<<<Tlen * Bsz, 128>>>(logits, atomtr, mask, rownll, rowmask);
    final_reduce<<<1, 256>>>(rownll, rowmask, (float*)d_out);
}

// round 13
// speedup vs baseline: 5.6918x; 1.0769x over previous
#include <cuda_runtime.h>
#include <cuda_fp16.h>
#include <math.h>

#define Bsz  256
#define Tlen 64
#define Hdim 1024
#define Xdim 512
#define Edim 256
#define DIN  768
#define G4   4096
#define NTAG 512

// ---- scratch layout ----
// floats:
//   xpart   @0          (1,048,576)
//   embproj @1,048,576  (2,097,152)
//   logits  @3,407,872  (8,388,608)
//   rownll  @11,796,480 (16,384)
//   rowmask @11,812,864 (16,384)
// fp16 region at float offset 11,829,248 (half-element offsets):
//   whh 0 (4,194,304)   wout 8,388,608 (524,288)
//   hA 9,437,184  hB 9,699,328
//   hs 9,961,472 (16,777,216)
__device__ float g_scratch[33849344];
__device__ int   g_mask_mode;
__device__ unsigned g_bar_arrive;
__device__ unsigned g_bar_gen;
__device__ unsigned g_arr2[2];
__device__ unsigned g_gen2[2];
__device__ int      g_use_tc;

// ---------------------------------------------------------------------------
// PTX helpers (portable)
// ---------------------------------------------------------------------------
#define MMA4F(c, a, b0_, b1_) \
    asm volatile("mma.sync.aligned.m16n8k16.row.col.f32.f16.f16.f32 " \
                 "{%0,%1,%2,%3},{%4,%5,%6,%7},{%8,%9},{%0,%1,%2,%3};" \
                 : "+f"((c)[0]), "+f"((c)[1]), "+f"((c)[2]), "+f"((c)[3]) \
                 : "r"((a)[0]), "r"((a)[1]), "r"((a)[2]), "r"((a)[3]), \
                   "r"(b0_), "r"(b1_))

#define LDSM4(r, addr) \
    asm volatile("ldmatrix.sync.aligned.m8n8.x4.shared.b16 {%0,%1,%2,%3}, [%4];" \
                 : "=r"((r)[0]), "=r"((r)[1]), "=r"((r)[2]), "=r"((r)[3]) \
                 : "r"(addr))

#define CP16(dst, src) \
    asm volatile("cp.async.cg.shared.global [%0], [%1], 16;" :: "r"(dst), "l"(src))
#define CPCOMMIT() asm volatile("cp.async.commit_group;" ::: "memory")
#define CPWAIT(n)  asm volatile("cp.async.wait_group %0;" :: "n"(n) : "memory")

#define FFMA2(d, a, b) asm("fma.rn.f32x2 %0, %1, %2, %0;" : "+l"(d) : "l"(a), "l"(b))
union F2U { unsigned long long u; float2 f; };
__device__ __forceinline__ unsigned long long dup2(float a) {
    unsigned x = __float_as_uint(a);
    return ((unsigned long long)x << 32) | (unsigned long long)x;
}

__device__ __forceinline__ unsigned smem_u32(const void* p) {
    return (unsigned)__cvta_generic_to_shared(p);
}

// fast activations (safe at +/-inf)
__device__ __forceinline__ float fsig(float x) {
    return __fdividef(1.f, 1.f + __expf(-x));
}
__device__ __forceinline__ float ftanh(float x) {
    return 1.f - __fdividef(2.f, __expf(2.f * x) + 1.f);
}

// ---------------------------------------------------------------------------
// tcgen05 helpers — ONLY compiled on the sm_100a pass.
// ---------------------------------------------------------------------------
#if defined(__CUDA_ARCH_FEAT_SM100_ALL)
__device__ __forceinline__ bool elect1() {
    unsigned p;
    asm volatile("{\n\t.reg .pred p;\n\telect.sync _|p, 0xFFFFFFFF;\n\tselp.b32 %0,1,0,p;\n\t}"
                 : "=r"(p));
    return p != 0;
}
__device__ __forceinline__ unsigned long long mk_desc(unsigned addr) {
    // SW128, version=1 (Blackwell), SBO=64, LBO=1 (K-major, 128B rows)
    return 0x4000404000010000ULL | ((unsigned long long)(addr >> 4) & 0x3FFF);
}
__device__ __forceinline__ void tc_mma_f16_ss(unsigned d, unsigned long long ad,
                                              unsigned long long bd, unsigned idesc,
                                              unsigned en)
{
    asm volatile(
        "{\n\t.reg .pred p;\n\tsetp.ne.u32 p, %5, 0;\n\t"
        "tcgen05.mma.cta_group::1.kind::f16 [%0], %1, %2, %3, {%4, %4, %4, %4}, p;\n\t}"
        :: "r"(d), "l"(ad), "l"(bd), "r"(idesc), "r"(0u), "r"(en)
        : "memory");
}
#define TC_ALLOC(smaddr, n) \
    asm volatile("tcgen05.alloc.cta_group::1.sync.aligned.shared::cta.b32 [%0], %1;" \
                 :: "r"(smaddr), "r"((unsigned)(n)) : "memory")
#define TC_DEALLOC(base, n) \
    asm volatile("tcgen05.dealloc.cta_group::1.sync.aligned.b32 %0, %1;" \
                 :: "r"(base), "r"((unsigned)(n)))
#define TC_COMMIT(mb) \
    asm volatile("tcgen05.commit.cta_group::1.mbarrier::arrive::one.shared::cluster.b64 [%0];" \
                 :: "r"(mb) : "memory")
#define TC_FENCE_AFTER()  asm volatile("tcgen05.fence::after_thread_sync;" ::: "memory")
#define TC_FENCE_BEFORE() asm volatile("tcgen05.fence::before_thread_sync;" ::: "memory")
#define TC_WAIT_LD()      asm volatile("tcgen05.wait::ld.sync.aligned;" ::: "memory")

#define MBAR_INIT(mb, cnt) \
    asm volatile("mbarrier.init.shared.b64 [%0], %1;" :: "r"(mb), "r"((unsigned)(cnt)) : "memory")
#define MBAR_WAIT(mb, par) do { \
    unsigned _m = (mb), _p = (par), _d; \
    asm volatile("{\n\t.reg .pred p;\n\t" \
                 "mbarrier.try_wait.parity.acquire.cta.shared::cta.b64 p, [%1], %2;\n\t" \
                 "selp.b32 %0,1,0,p;\n\t}" : "=r"(_d) : "r"(_m), "r"(_p) : "memory"); \
    if (!_d) { \
        asm volatile("{\n\t.reg .pred P1;\n\t" \
                     "WL%=:\n\t" \
                     "mbarrier.try_wait.parity.acquire.cta.shared::cta.b64 P1, [%0], %1, 0x989680;\n\t" \
                     "@P1 bra.uni WD%=;\n\tbra.uni WL%=;\n\tWD%=:\n\t}" \
                     :: "r"(_m), "r"(_p) : "memory"); \
    } \
} while(0)

#define TC_LD32(r, addr) \
    asm volatile("tcgen05.ld.sync.aligned.32x32b.x32.b32 " \
        "{%0,%1,%2,%3,%4,%5,%6,%7,%8,%9,%10,%11,%12,%13,%14,%15," \
        "%16,%17,%18,%19,%20,%21,%22,%23,%24,%25,%26,%27,%28,%29,%30,%31}, [%32];" \
        : "=r"((r)[0]),"=r"((r)[1]),"=r"((r)[2]),"=r"((r)[3]), \
          "=r"((r)[4]),"=r"((r)[5]),"=r"((r)[6]),"=r"((r)[7]), \
          "=r"((r)[8]),"=r"((r)[9]),"=r"((r)[10]),"=r"((r)[11]), \
          "=r"((r)[12]),"=r"((r)[13]),"=r"((r)[14]),"=r"((r)[15]), \
          "=r"((r)[16]),"=r"((r)[17]),"=r"((r)[18]),"=r"((r)[19]), \
          "=r"((r)[20]),"=r"((r)[21]),"=r"((r)[22]),"=r"((r)[23]), \
          "=r"((r)[24]),"=r"((r)[25]),"=r"((r)[26]),"=r"((r)[27]), \
          "=r"((r)[28]),"=r"((r)[29]),"=r"((r)[30]),"=r"((r)[31]) \
        : "r"(addr))

// idesc: f32 accum, f16 a/b, M=128, N=64
#define IDESC_F16 0x08100010u
#endif // __CUDA_ARCH_FEAT_SM100_ALL

// ---------------------------------------------------------------------------
// Conversion kernels (single fp16)
// ---------------------------------------------------------------------------
__global__ void interleave_whh(const float* __restrict__ W, __half* __restrict__ out)
{
    int c = blockIdx.x;                 // gate-interleaved row c = j*4 + g
    int j = c >> 2, g = c & 3;
    const float* src = W + (size_t)(g * Hdim + j) * Hdim;
    int k = threadIdx.x * 4;
    float4 v = *(const float4*)&src[k];
    size_t o = (size_t)c * Hdim + k;
    out[o + 0] = __float2half_rn(v.x);
    out[o + 1] = __float2half_rn(v.y);
    out[o + 2] = __float2half_rn(v.z);
    out[o + 3] = __float2half_rn(v.w);
}

__global__ void conv16(const float* __restrict__ src, __half* __restrict__ dst)
{
    int i = (blockIdx.x * 256 + threadIdx.x) * 4;
    float4 v = *(const float4*)&src[i];
    dst[i + 0] = __float2half_rn(v.x);
    dst[i + 1] = __float2half_rn(v.y);
    dst[i + 2] = __float2half_rn(v.z);
    dst[i + 3] = __float2half_rn(v.w);
}

// ---------------------------------------------------------------------------
// f32x2 SGEMM (xpart / embproj): C[M,N] = A[M,K] @ B[N,K]^T (+b0)(+b1)
// ---------------------------------------------------------------------------
__global__ __launch_bounds__(256) void sgemm2(
    const float* __restrict__ A, int lda,
    const float* __restrict__ Bm, int ldb,
    float* __restrict__ C, int ldc, int K,
    const float* __restrict__ bias0,
    const float* __restrict__ bias1)
{
    __shared__ unsigned long long As2[16][128];
    __shared__ float Bs[16][64];
    const int m0 = blockIdx.y * 128;
    const int n0 = blockIdx.x * 64;
    const int tid = threadIdx.x;
    const int rg = tid >> 4;
    const int cg = tid & 15;
    unsigned long long acc[8][2];
    #pragma unroll
    for (int i = 0; i < 8; i++) { acc[i][0] = 0ull; acc[i][1] = 0ull; }
    const int fm = tid >> 2;
    const int fk = (tid & 3) * 4;

    for (int k0 = 0; k0 < K; k0 += 16) {
        __syncthreads();
        #pragma unroll
        for (int half = 0; half < 2; half++) {
            int m = fm + half * 64;
            float4 v = *(const float4*)&A[(size_t)(m0 + m) * lda + k0 + fk];
            As2[fk + 0][m] = dup2(v.x);
            As2[fk + 1][m] = dup2(v.y);
            As2[fk + 2][m] = dup2(v.z);
            As2[fk + 3][m] = dup2(v.w);
        }
        {
            float4 v = *(const float4*)&Bm[(size_t)(n0 + fm) * ldb + k0 + fk];
            Bs[fk + 0][fm] = v.x; Bs[fk + 1][fm] = v.y;
            Bs[fk + 2][fm] = v.z; Bs[fk + 3][fm] = v.w;
        }
        __syncthreads();
        #pragma unroll
        for (int k = 0; k < 16; k++) {
            const ulonglong2* ap = (const ulonglong2*)&As2[k][rg * 8];
            ulonglong2 bv = *(const ulonglong2*)&Bs[k][cg * 4];
            #pragma unroll
            for (int i2 = 0; i2 < 4; i2++) {
                ulonglong2 a = ap[i2];
                FFMA2(acc[2 * i2 + 0][0], a.x, bv.x);
                FFMA2(acc[2 * i2 + 0][1], a.x, bv.y);
                FFMA2(acc[2 * i2 + 1][0], a.y, bv.x);
                FFMA2(acc[2 * i2 + 1][1], a.y, bv.y);
            }
        }
    }
    #pragma unroll
    for (int i = 0; i < 8; i++) {
        int m = m0 + rg * 8 + i;
        #pragma unroll
        for (int p = 0; p < 2; p++) {
            int n = n0 + cg * 4 + p * 2;
            F2U u; u.u = acc[i][p];
            float v0 = u.f.x, v1 = u.f.y;
            if (bias0) { v0 += bias0[n]; v1 += bias0[n + 1]; }
            if (bias1) { v0 += bias1[n]; v1 += bias1[n + 1]; }
            *(float2*)&C[(size_t)m * ldc + n] = make_float2(v0, v1);
        }
    }
}

// ---------------------------------------------------------------------------
// mma.sync fallback mainloop: single-term fp16. 64m x 128n.
// 3 stages x 15360 B: A[64][40]@0, B[128][40]@5120.
// ---------------------------------------------------------------------------
__device__ __forceinline__ void mma_mainloop1(
    const __half* __restrict__ gA, const __half* __restrict__ gB,
    unsigned smem_u, int tid, float acc[2][4][4])
{
    const int lane = tid & 31, w = tid >> 5;
    const int wm = w & 1, wn = w >> 1;
    const int lrow = (lane & 7) + ((lane >> 3) & 1) * 8;
    const int lcol = (lane >> 4) * 8;
    const unsigned aoff = ((wm * 32 + lrow) * 40 + lcol) * 2;
    const unsigned boff = ((wn * 32 + lrow) * 40 + lcol) * 2;

    const int ar = tid >> 2;
    const int br = tid >> 1;
    const unsigned dA  = (ar * 40 + (tid & 3) * 8) * 2;
    const unsigned dB0 = (br * 40 + (tid & 1) * 16) * 2;
    const unsigned dB1 = dB0 + 16;

    #pragma unroll
    for (int s = 0; s < 2; s++) {
        unsigned sb = smem_u + s * 15360;
        int k0 = s * 32;
        CP16(sb + dA,         gA + k0);
        CP16(sb + 5120 + dB0, gB + k0);
        CP16(sb + 5120 + dB1, gB + k0 + 8);
        CPCOMMIT();
    }

    for (int i = 0; i < 32; i++) {
        if (i < 31) { CPWAIT(1); } else { CPWAIT(0); }
        __syncthreads();
        if (i + 2 < 32) {
            unsigned sb = smem_u + ((i + 2) % 3) * 15360;
            int k0 = (i + 2) * 32;
            CP16(sb + dA,         gA + k0);
            CP16(sb + 5120 + dB0, gB + k0);
            CP16(sb + 5120 + dB1, gB + k0 + 8);
            CPCOMMIT();
        }
        unsigned sb = smem_u + (i % 3) * 15360;
        #pragma unroll
        for (int kh = 0; kh < 2; kh++) {
            const unsigned kb = kh * 32;
            unsigned a0[4], a1[4];
            LDSM4(a0, sb + aoff + kb);
            LDSM4(a1, sb + aoff + 1280 + kb);
            unsigned bh0[4], bh1[4];
            LDSM4(bh0, sb + 5120 + boff + kb);
            LDSM4(bh1, sb + 5120 + boff + 1280 + kb);
            #pragma unroll
            for (int nt = 0; nt < 4; nt++) {
                const unsigned* bhp = (nt < 2) ? bh0 : bh1;
                unsigned h0v = bhp[nt & 1], h1v = bhp[(nt & 1) + 2];
                MMA4F(acc[0][nt], a0, h0v, h1v);
                MMA4F(acc[1][nt], a1, h0v, h1v);
            }
        }
    }
}

// ---------------------------------------------------------------------------
// Barriers
// ---------------------------------------------------------------------------
__global__ void init_bar() {
    g_bar_arrive = 0; g_bar_gen = 0;
    g_arr2[0] = 0; g_arr2[1] = 0;
    g_gen2[0] = 0; g_gen2[1] = 0;
#if defined(__CUDA_ARCH_FEAT_SM100_ALL)
    g_use_tc = 1;
#else
    g_use_tc = 0;
#endif
}

__device__ __forceinline__ void grid_sync(int tid, unsigned gen)
{
    __syncthreads();
    if (tid == 0) {
        __threadfence();
        unsigned a = atomicAdd(&g_bar_arrive, 1);
        if (a == 127) {
            g_bar_arrive = 0;
            __threadfence();
            atomicExch(&g_bar_gen, gen);
        } else {
            while (atomicAdd(&g_bar_gen, 0u) < gen) __nanosleep(64);
            __threadfence();
        }
    }
    __syncthreads();
}

#define STG_SZ 24576     // tcgen05 stage: A 16K @0, B 8K @16384
#define N_STG  8
#define DSMEM_LSTM (N_STG * STG_SZ)   // 196608

// ---------------------------------------------------------------------------
// Persistent LSTM sequence kernel — dual path.
// tcgen05: block = 128 batch x 64 gate-cols (16 j x 4 gates, rows j*4+g),
// A = h fp16, B = W fp16, 1 MMA term, 8-stage pipeline, W prefetch across steps.
// ---------------------------------------------------------------------------
__global__ __launch_bounds__(256, 1) void lstm_seq(
    __half* hA, __half* hB,
    const float* __restrict__ c0,
    const float* __restrict__ xpart,
    const float* __restrict__ embproj,
    __half* __restrict__ hs,
    const __half* __restrict__ whh,
    const int* __restrict__ atom_truth)
{
#if defined(__CUDA_ARCH_FEAT_SM100_ALL)
    extern __shared__ __align__(1024) unsigned char dsm[];
    __shared__ unsigned s_tmem;
    __shared__ __align__(8) unsigned long long s_mbar[N_STG];

    const unsigned smem_u = smem_u32(dsm);
    const int tid = threadIdx.x;
    const int wid = tid >> 5, lane = tid & 31;
    const int bx = blockIdx.x;
    const int half = bx >> 6;
    const int b0 = half * 128;
    const int ntb = bx & 63;
    const int c0g = ntb * 64;
    const int jb = ntb * 16;

    if (tid == 0) {
        #pragma unroll
        for (int i = 0; i < N_STG; i++) MBAR_INIT(smem_u32(&s_mbar[i]), 1);
    }
    __syncthreads();
    if (wid == 0) TC_ALLOC(smem_u32(&s_tmem), 512);
    __syncthreads();
    const unsigned tmem = s_tmem;
    unsigned mbu[N_STG];
    #pragma unroll
    for (int i = 0; i < N_STG; i++) mbu[i] = smem_u32(&s_mbar[i]);
    int ph[N_STG] = {0, 0, 0, 0, 0, 0, 0, 0};

    // fill geometry
    const int ra = tid >> 1, ca = (tid & 1) * 4;       // A: row, 4 x 16B chunks
    const int rb = tid >> 2, cb2 = (tid & 3) * 2;      // B: row, 2 x 16B chunks
    const int ram = ra & 7, rbm = rb & 7;
    const __half* Bsrc = whh + (size_t)(c0g + rb) * Hdim;
    const __half* Asrc;   // set per step

    // epilogue geometry
    const int b = b0 + (wid & 3) * 32 + lane;
    const int jh = (wid >> 2) * 8;
    float creg[8];
    {
        const float* cp = c0 + (size_t)b * Hdim + jb + jh;
        float4 v0 = *(const float4*)&cp[0];
        float4 v1 = *(const float4*)&cp[4];
        creg[0] = v0.x; creg[1] = v0.y; creg[2] = v0.z; creg[3] = v0.w;
        creg[4] = v1.x; creg[5] = v1.y; creg[6] = v1.z; creg[7] = v1.w;
    }

    #define FILL_B(kc_, st_) do { \
        unsigned ab = smem_u + (st_) * STG_SZ; \
        const __half* bs = Bsrc + (kc_) * 64; \
        _Pragma("unroll") \
        for (int c = 0; c < 2; c++) { \
            int cc = cb2 + c; \
            unsigned d = rb * 128 + ((cc ^ rbm) * 16); \
            CP16(ab + 16384 + d, bs + cc * 8); \
        } \
        CPCOMMIT(); \
    } while (0)

    #define FILL_A(kc_, st_) do { \
        unsigned ab = smem_u + (st_) * STG_SZ; \
        const __half* sh = Asrc + (kc_) * 64; \
        _Pragma("unroll") \
        for (int c = 0; c < 4; c++) { \
            int cc = ca + c; \
            unsigned d = ra * 128 + ((cc ^ ram) * 16); \
            CP16(ab + d, sh + cc * 8); \
        } \
        CPCOMMIT(); \
    } while (0)

    #define FILL_AB(kc_, st_) do { \
        unsigned ab = smem_u + (st_) * STG_SZ; \
        const __half* sh = Asrc + (kc_) * 64; \
        _Pragma("unroll") \
        for (int c = 0; c < 4; c++) { \
            int cc = ca + c; \
            unsigned d = ra * 128 + ((cc ^ ram) * 16); \
            CP16(ab + d, sh + cc * 8); \
        } \
        const __half* bs = Bsrc + (kc_) * 64; \
        _Pragma("unroll") \
        for (int c = 0; c < 2; c++) { \
            int cc = cb2 + c; \
            unsigned d = rb * 128 + ((cc ^ rbm) * 16); \
            CP16(ab + 16384 + d, bs + cc * 8); \
        } \
        CPCOMMIT(); \
    } while (0)

    // W prefetch for step 0: chunks 0..6 into stages 0..6
    FILL_B(0, 0); FILL_B(1, 1); FILL_B(2, 2); FILL_B(3, 3);
    FILL_B(4, 4); FILL_B(5, 5); FILL_B(6, 6);

    for (int t = 0; t < Tlen; t++) {
        const __half* hin = (t & 1) ? hB : hA;
        __half* hout      = (t & 1) ? hA : hB;
        Asrc = hin + (size_t)(b0 + ra) * Hdim;

        FILL_A(0, 0); FILL_A(1, 1); FILL_A(2, 2); FILL_A(3, 3);
        FILL_A(4, 4); FILL_A(5, 5); FILL_A(6, 6);

        for (int kc = 0; kc < 16; kc++) {
            if (kc <= 9)       { CPWAIT(6); }
            else if (kc == 10) { CPWAIT(5); }
            else if (kc == 11) { CPWAIT(4); }
            else if (kc == 12) { CPWAIT(3); }
            else if (kc == 13) { CPWAIT(2); }
            else if (kc == 14) { CPWAIT(1); }
            else               { CPWAIT(0); }
            __syncthreads();
            if (wid == 0 && elect1()) {
                unsigned sb = smem_u + (kc % N_STG) * STG_SZ;
                unsigned long long ad = mk_desc(sb);
                unsigned long long bd = mk_desc(sb + 16384);
                #pragma unroll
                for (int ks = 0; ks < 4; ks++) {
                    unsigned en0 = (kc == 0 && ks == 0) ? 0u : 1u;
                    tc_mma_f16_ss(tmem, ad + ks * 2, bd + ks * 2, IDESC_F16, en0);
                }
                TC_COMMIT(mbu[kc % N_STG]);
            }
            if (kc + 7 < 16) {
                if (kc >= 1) {
                    int s = (kc - 1) % N_STG;
                    MBAR_WAIT(mbu[s], (unsigned)(ph[s] & 1));
                    ph[s]++;
                }
                FILL_AB(kc + 7, (kc + 7) % N_STG);
            }
        }

        // prefetch epilogue operands while tail MMAs drain
        int tok = (t == 0) ? 0 : atom_truth[b * Tlen + (t - 1)];
        const float* xp = xpart + (size_t)b * G4 + jb + jh;
        const float* ep = embproj + (size_t)tok * G4 + jb + jh;
        float xg[4][8], eg[4][8];
        #pragma unroll
        for (int p = 0; p < 4; p++) {
            float4 a0 = *(const float4*)&xp[p * Hdim];
            float4 a1 = *(const float4*)&xp[p * Hdim + 4];
            float4 e0 = *(const float4*)&ep[p * Hdim];
            float4 e1 = *(const float4*)&ep[p * Hdim + 4];
            xg[p][0] = a0.x; xg[p][1] = a0.y; xg[p][2] = a0.z; xg[p][3] = a0.w;
            xg[p][4] = a1.x; xg[p][5] = a1.y; xg[p][6] = a1.z; xg[p][7] = a1.w;
            eg[p][0] = e0.x; eg[p][1] = e0.y; eg[p][2] = e0.z; eg[p][3] = e0.w;
            eg[p][4] = e1.x; eg[p][5] = e1.y; eg[p][6] = e1.z; eg[p][7] = e1.w;
        }

        // tail waits: chunks 8..15 (all 8 stages)
        #pragma unroll
        for (int c = 8; c < 16; c++) {
            int s = c % N_STG;
            MBAR_WAIT(mbu[s], (unsigned)(ph[s] & 1));
            ph[s]++;
        }
        TC_FENCE_AFTER();

        // next step's W prefetch, overlapped with epilogue + barrier
        if (t < Tlen - 1) {
            FILL_B(0, 0); FILL_B(1, 1); FILL_B(2, 2); FILL_B(3, 3);
            FILL_B(4, 4); FILL_B(5, 5); FILL_B(6, 6);
        }

        unsigned dr[32];
        TC_LD32(dr, tmem + (wid >> 2) * 32);
        TC_WAIT_LD();
        TC_FENCE_BEFORE();

        __half hh[8];
        #pragma unroll
        for (int jl = 0; jl < 8; jl++) {
            float ig = __uint_as_float(dr[4 * jl + 0]) + xg[0][jl] + eg[0][jl];
            float fg = __uint_as_float(dr[4 * jl + 1]) + xg[1][jl] + eg[1][jl];
            float gg = __uint_as_float(dr[4 * jl + 2]) + xg[2][jl] + eg[2][jl];
            float og = __uint_as_float(dr[4 * jl + 3]) + xg[3][jl] + eg[3][jl];
            ig = fsig(ig); fg = fsig(fg); og = fsig(og); gg = ftanh(gg);
            float cv = fg * creg[jl] + ig * gg;
            creg[jl] = cv;
            hh[jl] = __float2half_rn(og * ftanh(cv));
        }
        {
            size_t o = (size_t)b * Hdim + jb + jh;
            *(uint4*)&hout[o] = *(uint4*)&hh[0];
            size_t ho = ((size_t)t * Bsz + b) * Hdim + jb + jh;
            *(uint4*)&hs[ho] = *(uint4*)&hh[0];
        }

        if (t < Tlen - 1) {
            __syncthreads();
            if (tid == 0) {
                __threadfence();
                unsigned old = atomicAdd(&g_arr2[half], 1);
                if (old == 63) {
                    g_arr2[half] = 0;
                    asm volatile("st.release.gpu.b32 [%0], %1;"
                                 :: "l"(&g_gen2[half]), "r"((unsigned)(t + 1)) : "memory");
                } else {
                    unsigned g;
                    do {
                        asm volatile("ld.acquire.gpu.b32 %0, [%1];"
                                     : "=r"(g) : "l"(&g_gen2[half]) : "memory");
                        if (g < (unsigned)(t + 1)) __nanosleep(32);
                    } while (g < (unsigned)(t + 1));
                }
            }
            __syncthreads();
        }
    }

    __syncthreads();
    if (wid == 0) TC_DEALLOC(tmem, 512);
    #undef FILL_B
    #undef FILL_A
    #undef FILL_AB

#else
    // ===================== mma.sync fallback (fp16 single-term) =====================
    extern __shared__ __align__(1024) unsigned char dsm[];
    unsigned smem_u = smem_u32(dsm);
    float* Gs = (float*)dsm;

    const int bx = blockIdx.x;
    const int j0 = (bx & 31) * 32;
    const int b0 = (bx >> 5) * 64;
    const int gcol0 = j0 * 4;
    const int tid = threadIdx.x;
    const int lane = tid & 31, w = tid >> 5;
    const int wm = w & 1, wn = w >> 1;
    const int qr = lane >> 2, qk = (lane & 3) * 2;
    const int ar = tid >> 2, akc = (tid & 3) * 8;
    const int br = tid >> 1, bkc = (tid & 1) * 16;

    const __half* gB = whh + (size_t)(gcol0 + br) * Hdim + bkc;

    float creg[8];
    #pragma unroll
    for (int i = 0; i < 8; i++) {
        int idx = tid + i * 256;
        creg[i] = c0[(b0 + (idx >> 5)) * Hdim + j0 + (idx & 31)];
    }

    for (int t = 0; t < Tlen; t++) {
        const __half* hin = (t & 1) ? hB : hA;
        __half* hout      = (t & 1) ? hA : hB;

        float acc[2][4][4];
        #pragma unroll
        for (int mt = 0; mt < 2; mt++)
            #pragma unroll
            for (int nt = 0; nt < 4; nt++)
                #pragma unroll
                for (int q = 0; q < 4; q++) acc[mt][nt][q] = 0.f;

        mma_mainloop1(hin + (size_t)(b0 + ar) * Hdim + akc, gB, smem_u, tid, acc);

        __syncthreads();
        #pragma unroll
        for (int mt = 0; mt < 2; mt++)
            #pragma unroll
            for (int nt = 0; nt < 4; nt++) {
                int r = wm * 32 + mt * 16 + qr;
                int cc = wn * 32 + nt * 8 + qk;
                *(float2*)&Gs[r * 132 + cc]       = make_float2(acc[mt][nt][0], acc[mt][nt][1]);
                *(float2*)&Gs[(r + 8) * 132 + cc] = make_float2(acc[mt][nt][2], acc[mt][nt][3]);
            }
        __syncthreads();

        #pragma unroll
        for (int i = 0; i < 8; i++) {
            int idx = tid + i * 256;
            int bl = idx >> 5, jj = idx & 31;
            float4 gv = *(const float4*)&Gs[bl * 132 + jj * 4];
            int b = b0 + bl, j = j0 + jj;
            int tok = (t == 0) ? 0 : atom_truth[b * Tlen + (t - 1)];
            const float* xp = xpart + (size_t)b * G4 + j;
            const float* ep = embproj + (size_t)tok * G4 + j;
            float ig = gv.x + xp[0]        + ep[0];
            float fg = gv.y + xp[Hdim]     + ep[Hdim];
            float gg = gv.z + xp[2 * Hdim] + ep[2 * Hdim];
            float og = gv.w + xp[3 * Hdim] + ep[3 * Hdim];
            ig = fsig(ig); fg = fsig(fg); og = fsig(og); gg = ftanh(gg);
            float cv = fg * creg[i] + ig * gg;
            creg[i] = cv;
            __half hv = __float2half_rn(og * ftanh(cv));
            hout[b * Hdim + j] = hv;
            hs[((size_t)t * Bsz + b) * Hdim + j] = hv;
        }

        if (t < Tlen - 1) grid_sync(tid, (unsigned)(t + 1));
    }
#endif
}

// ---------------------------------------------------------------------------
// Logits GEMM, tcgen05: C[16384,512] = hs @ W_out^T + b_out.
// Single-term fp16. Tiles 128m x 64n; grid (8, 128).
// ---------------------------------------------------------------------------
__global__ __launch_bounds__(256, 1) void logits_tc(
    const __half* __restrict__ A_g,
    const __half* __restrict__ B_g,
    float* __restrict__ C,
    const float* __restrict__ bias)
{
#if defined(__CUDA_ARCH_FEAT_SM100_ALL)
    extern __shared__ __align__(1024) unsigned char dsm[];
    __shared__ unsigned s_tmem;
    __shared__ __align__(8) unsigned long long s_mbar[N_STG];

    const unsigned smem_u = smem_u32(dsm);
    const int tid = threadIdx.x;
    const int wid = tid >> 5, lane = tid & 31;
    const int n0 = blockIdx.x * 64;
    const int m0 = blockIdx.y * 128;

    if (tid == 0) {
        #pragma unroll
        for (int i = 0; i < N_STG; i++) MBAR_INIT(smem_u32(&s_mbar[i]), 1);
    }
    __syncthreads();
    if (wid == 0) TC_ALLOC(smem_u32(&s_tmem), 512);
    __syncthreads();
    const unsigned tmem = s_tmem;
    unsigned mbu[N_STG];
    #pragma unroll
    for (int i = 0; i < N_STG; i++) mbu[i] = smem_u32(&s_mbar[i]);
    int ph[N_STG] = {0, 0, 0, 0, 0, 0, 0, 0};

    const int ra = tid >> 1, ca = (tid & 1) * 4;
    const int rb = tid >> 2, cb2 = (tid & 3) * 2;
    const int ram = ra & 7, rbm = rb & 7;
    const __half* Asrc = A_g + (size_t)(m0 + ra) * Hdim;
    const __half* Bsrc = B_g + (size_t)(n0 + rb) * Hdim;

    #define LFILL(kc_, st_) do { \
        unsigned ab = smem_u + (st_) * STG_SZ; \
        const __half* sh = Asrc + (kc_) * 64; \
        _Pragma("unroll") \
        for (int c = 0; c < 4; c++) { \
            int cc = ca + c; \
            unsigned d = ra * 128 + ((cc ^ ram) * 16); \
            CP16(ab + d, sh + cc * 8); \
        } \
        const __half* bs = Bsrc + (kc_) * 64; \
        _Pragma("unroll") \
        for (int c = 0; c < 2; c++) { \
            int cc = cb2 + c; \
            unsigned d = rb * 128 + ((cc ^ rbm) * 16); \
            CP16(ab + 16384 + d, bs + cc * 8); \
        } \
        CPCOMMIT(); \
    } while (0)

    LFILL(0, 0); LFILL(1, 1); LFILL(2, 2); LFILL(3, 3);
    LFILL(4, 4); LFILL(5, 5); LFILL(6, 6);

    for (int kc = 0; kc < 16; kc++) {
        if (kc <= 9)       { CPWAIT(6); }
        else if (kc == 10) { CPWAIT(5); }
        else if (kc == 11) { CPWAIT(4); }
        else if (kc == 12) { CPWAIT(3); }
        else if (kc == 13) { CPWAIT(2); }
        else if (kc == 14) { CPWAIT(1); }
        else               { CPWAIT(0); }
        __syncthreads();
        if (wid == 0 && elect1()) {
            unsigned sb = smem_u + (kc % N_STG) * STG_SZ;
            unsigned long long ad = mk_desc(sb);
            unsigned long long bd = mk_desc(sb + 16384);
            #pragma unroll
            for (int ks = 0; ks < 4; ks++) {
                unsigned en0 = (kc == 0 && ks == 0) ? 0u : 1u;
                tc_mma_f16_ss(tmem, ad + ks * 2, bd + ks * 2, IDESC_F16, en0);
            }
            TC_COMMIT(mbu[kc % N_STG]);
        }
        if (kc + 7 < 16) {
            if (kc >= 1) {
                int s = (kc - 1) % N_STG;
                MBAR_WAIT(mbu[s], (unsigned)(ph[s] & 1));
                ph[s]++;
            }
            LFILL(kc + 7, (kc + 7) % N_STG);
        }
    }
    #pragma unroll
    for (int c = 8; c < 16; c++) {
        int s = c % N_STG;
        MBAR_WAIT(mbu[s], (unsigned)(ph[s] & 1));
        ph[s]++;
    }
    TC_FENCE_AFTER();

    unsigned dr[32];
    TC_LD32(dr, tmem + (wid >> 2) * 32);
    TC_WAIT_LD();
    TC_FENCE_BEFORE();

    // stage to smem [128][65] then coalesced write with bias
    float* S = (float*)dsm;
    {
        int r = (wid & 3) * 32 + lane;
        int cb = (wid >> 2) * 32;
        #pragma unroll
        for (int c = 0; c < 32; c++) S[r * 65 + cb + c] = __uint_as_float(dr[c]);
    }
    __syncthreads();
    #pragma unroll
    for (int q = 0; q < 8; q++) {
        int idx = tid + q * 256;
        int rr = idx >> 4, c4 = (idx & 15) * 4;
        float4 bv = *(const float4*)&bias[n0 + c4];
        float4 v;
        v.x = S[rr * 65 + c4 + 0] + bv.x;
        v.y = S[rr * 65 + c4 + 1] + bv.y;
        v.z = S[rr * 65 + c4 + 2] + bv.z;
        v.w = S[rr * 65 + c4 + 3] + bv.w;
        *(float4*)&C[(size_t)(m0 + rr) * NTAG + n0 + c4] = v;
    }
    __syncthreads();
    if (wid == 0) TC_DEALLOC(tmem, 512);
    #undef LFILL
#endif
}

// ---------------------------------------------------------------------------
// Logits fallback (mma.sync) — no-ops when tcgen05 cubin active.
// ---------------------------------------------------------------------------
__global__ __launch_bounds__(256) void logits_mma(
    const __half* __restrict__ A_g,
    const __half* __restrict__ B_g,
    float* __restrict__ C,
    const float* __restrict__ bias)
{
    if (g_use_tc) return;
    extern __shared__ __align__(16) unsigned char dsm2[];
    unsigned smem_u = (unsigned)__cvta_generic_to_shared(dsm2);

    const int n0 = blockIdx.x * 128;
    const int m0 = blockIdx.y * 64;
    const int tid = threadIdx.x;
    const int lane = tid & 31, w = tid >> 5;
    const int wm = w & 1, wn = w >> 1;
    const int qr = lane >> 2, qk = (lane & 3) * 2;
    const int ar = tid >> 2, akc = (tid & 3) * 8;
    const int br = tid >> 1, bkc = (tid & 1) * 16;

    float acc[2][4][4];
    #pragma unroll
    for (int mt = 0; mt < 2; mt++)
        #pragma unroll
        for (int nt = 0; nt < 4; nt++)
            #pragma unroll
            for (int q = 0; q < 4; q++) acc[mt][nt][q] = 0.f;

    mma_mainloop1(A_g + (size_t)(m0 + ar) * Hdim + akc,
                  B_g + (size_t)(n0 + br) * Hdim + bkc,
                  smem_u, tid, acc);

    #pragma unroll
    for (int mt = 0; mt < 2; mt++)
        #pragma unroll
        for (int nt = 0; nt < 4; nt++) {
            int m = m0 + wm * 32 + mt * 16 + qr;
            int n = n0 + wn * 32 + nt * 8 + qk;
            float b0v = bias[n], b1v = bias[n + 1];
            *(float2*)&C[(size_t)m * NTAG + n] =
                make_float2(acc[mt][nt][0] + b0v, acc[mt][nt][1] + b1v);
            *(float2*)&C[(size_t)(m + 8) * NTAG + n] =
                make_float2(acc[mt][nt][2] + b0v, acc[mt][nt][3] + b1v);
        }
}

// ---------------------------------------------------------------------------
// Mask detection / NLL / reduction
// ---------------------------------------------------------------------------
__global__ void detect_mask(const unsigned* __restrict__ m)
{
    __shared__ int isByte, isFloat;
    if (threadIdx.x == 0) { isByte = 0; isFloat = 0; }
    __syncthreads();
    for (int i = threadIdx.x; i < (Bsz * Tlen) / 4; i += blockDim.x) {
        unsigned v = m[i];
        if (v == 0x3F800000u) isFloat = 1;
        else if (v > 1u) isByte = 1;
    }
    __syncthreads();
    if (threadIdx.x == 0) g_mask_mode = isFloat ? 2 : (isByte ? 1 : 0);
}

__global__ __launch_bounds__(128) void nll_rows(
    const float* __restrict__ logits,
    const int* __restrict__ atom_truth,
    const void* __restrict__ atom_mask,
    float* __restrict__ rownll,
    float* __restrict__ rowmask)
{
    const int r = blockIdx.x;
    const int t = r >> 8;
    const int b = r & 255;
    const float* row = logits + (size_t)r * NTAG;
    const int tid = threadIdx.x;
    __shared__ float red[128];

    float mx = -1e30f;
    for (int i = tid; i < NTAG; i += 128) mx = fmaxf(mx, row[i]);
    red[tid] = mx; __syncthreads();
    for (int s = 64; s > 0; s >>= 1) {
        if (tid < s) red[tid] = fmaxf(red[tid], red[tid + s]);
        __syncthreads();
    }
    mx = red[0]; __syncthreads();

    float sm = 0.f;
    for (int i = tid; i < NTAG; i += 128) sm += __expf(row[i] - mx);
    red[tid] = sm; __syncthreads();
    for (int s = 64; s > 0; s >>= 1) {
        if (tid < s) red[tid] += red[tid + s];
        __syncthreads();
    }

    if (tid == 0) {
        int tgt = atom_truth[b * Tlen + t];
        float lp = row[tgt] - mx - logf(red[0]);
        int mode = g_mask_mode;
        float m;
        if (mode == 2)      m = (((const float*)atom_mask)[b * Tlen + t] != 0.f) ? 1.f : 0.f;
        else if (mode == 1) m = (((const unsigned char*)atom_mask)[b * Tlen + t] != 0) ? 1.f : 0.f;
        else                m = (((const int*)atom_mask)[b * Tlen + t] != 0) ? 1.f : 0.f;
        rownll[r]  = -lp * m;
        rowmask[r] = m;
    }
}

__global__ __launch_bounds__(256) void final_reduce(
    const float* __restrict__ rownll,
    const float* __restrict__ rowmask,
    float* __restrict__ out)
{
    __shared__ double rn[256], rm[256];
    double sn = 0.0, sm = 0.0;
    for (int i = threadIdx.x; i < Tlen * Bsz; i += 256) {
        sn += (double)rownll[i];
        sm += (double)rowmask[i];
    }
    rn[threadIdx.x] = sn; rm[threadIdx.x] = sm;
    __syncthreads();
    for (int s = 128; s > 0; s >>= 1) {
        if (threadIdx.x < s) {
            rn[threadIdx.x] += rn[threadIdx.x + s];
            rm[threadIdx.x] += rm[threadIdx.x + s];
        }
        __syncthreads();
    }
    if (threadIdx.x == 0) out[0] = (float)(rn[0] / rm[0]);
}

// ---------------------------------------------------------------------------
// Launch
// ---------------------------------------------------------------------------
extern "C" void kernel_launch(void* const* d_in, const int* in_sizes, int n_in,
                              void* d_out, int out_size)
{
    const float* x      = (const float*)d_in[0];
    const int*   atomtr = (const int*)d_in[1];
    const void*  mask   = d_in[2];
    const float* emb    = (const float*)d_in[3];
    const float* W_ih   = (const float*)d_in[4];
    const float* W_hh   = (const float*)d_in[5];
    const float* b_ih   = (const float*)d_in[6];
    const float* b_hh   = (const float*)d_in[7];
    const float* W_out  = (const float*)d_in[8];
    const float* b_out  = (const float*)d_in[9];
    const float* h0     = (const float*)d_in[10];
    const float* c0     = (const float*)d_in[11];

    float* sc = nullptr;
    cudaGetSymbolAddress((void**)&sc, g_scratch);
    float* xpart   = sc + 0;
    float* embproj = sc + 1048576;
    float* logits  = sc + 3407872;
    float* rownll  = sc + 11796480;
    float* rowmask = sc + 11812864;
    __half* hb = (__half*)(sc + 11829248);
    __half* whh  = hb + 0;
    __half* wout = hb + 8388608;
    __half* hA   = hb + 9437184;
    __half* hB   = hb + 9699328;
    __half* hs   = hb + 9961472;

    const int DSMEM_LOG = 3 * 15360;   // fallback logits: 46080
    static int attr_done = 0;
    if (!attr_done) {
        cudaFuncSetAttribute(lstm_seq,   cudaFuncAttributeMaxDynamicSharedMemorySize, DSMEM_LSTM);
        cudaFuncSetAttribute(logits_tc,  cudaFuncAttributeMaxDynamicSharedMemorySize, DSMEM_LSTM);
        cudaFuncSetAttribute(logits_mma, cudaFuncAttributeMaxDynamicSharedMemorySize, DSMEM_LOG);
        attr_done = 1;
    }

    detect_mask<<<1, 256>>>((const unsigned*)mask);
    init_bar<<<1, 1>>>();

    // one-time weight / state conversions (single fp16)
    interleave_whh<<<4096, 256>>>(W_hh, whh);
    conv16<<<512, 256>>>(W_out, wout);
    conv16<<<256, 256>>>(h0, hA);

    // xpart = x @ W_ih[:, :512]^T + b_ih + b_hh   [256, 4096]
    sgemm2<<<dim3(G4 / 64, Bsz / 128), 256>>>(x, Xdim, W_ih, DIN, xpart, G4, Xdim, b_ih, b_hh);
    // embproj = emb @ W_ih[:, 512:768]^T          [512, 4096]
    sgemm2<<<dim3(G4 / 64, NTAG / 128), 256>>>(emb, Edim, W_ih + Xdim, DIN, embproj, G4, Edim, nullptr, nullptr);

    // all 64 LSTM steps in one persistent kernel
    lstm_seq<<<128, 256, DSMEM_LSTM>>>(
        hA, hB, c0, xpart, embproj, hs, whh, atomtr);

    // logits = hs @ W_out^T + b_out   [16384, 512]  (exactly one of these runs)
    logits_tc<<<dim3(NTAG / 64, (Tlen * Bsz) / 128), 256, DSMEM_LSTM>>>(
        hs, wout, logits, b_out);
    logits_mma<<<dim3(NTAG / 128, (Tlen * Bsz) / 64), 256, DSMEM_LOG>>>(
        hs, wout, logits, b_out);

    nll_rows<<<Tlen * Bsz, 128>>>(logits, atomtr, mask, rownll, rowmask);
    final_reduce<<<1, 256>>>(rownll, rowmask, (float*)d_out);
}

// round 15
// speedup vs baseline: 7.2786x; 1.2788x over previous
#include <cuda_runtime.h>
#include <cuda_fp16.h>
#include <math.h>

#define Bsz  256
#define Tlen 64
#define Hdim 1024
#define Xdim 512
#define Edim 256
#define DIN  768
#define G4   4096
#define NTAG 512

// ---- scratch layout ----
// floats:
//   xpart   @0          (1,048,576)
//   embproj @1,048,576  (2,097,152)
//   logits  @3,407,872  (8,388,608)
//   rownll  @11,796,480 (16,384)
//   rowmask @11,812,864 (16,384)
// fp16 region at float offset 11,829,248 (half-element offsets):
//   whh 0 (4,194,304)   wout 8,388,608 (524,288)
//   hA 9,437,184  hB 9,699,328
//   hs 9,961,472 (16,777,216)
__device__ float g_scratch[33849344];
__device__ int   g_mask_mode;
__device__ unsigned g_bar_arrive;
__device__ unsigned g_bar_gen;
__device__ unsigned g_arr2[2];
__device__ unsigned g_gen2[2];
__device__ int      g_use_tc;

// ---------------------------------------------------------------------------
// PTX helpers (portable)
// ---------------------------------------------------------------------------
#define MMA4F(c, a, b0_, b1_) \
    asm volatile("mma.sync.aligned.m16n8k16.row.col.f32.f16.f16.f32 " \
                 "{%0,%1,%2,%3},{%4,%5,%6,%7},{%8,%9},{%0,%1,%2,%3};" \
                 : "+f"((c)[0]), "+f"((c)[1]), "+f"((c)[2]), "+f"((c)[3]) \
                 : "r"((a)[0]), "r"((a)[1]), "r"((a)[2]), "r"((a)[3]), \
                   "r"(b0_), "r"(b1_))

#define LDSM4(r, addr) \
    asm volatile("ldmatrix.sync.aligned.m8n8.x4.shared.b16 {%0,%1,%2,%3}, [%4];" \
                 : "=r"((r)[0]), "=r"((r)[1]), "=r"((r)[2]), "=r"((r)[3]) \
                 : "r"(addr))

#define CP16(dst, src) \
    asm volatile("cp.async.cg.shared.global [%0], [%1], 16;" :: "r"(dst), "l"(src))
#define CPCOMMIT() asm volatile("cp.async.commit_group;" ::: "memory")
#define CPWAIT(n)  asm volatile("cp.async.wait_group %0;" :: "n"(n) : "memory")

#define FFMA2(d, a, b) asm("fma.rn.f32x2 %0, %1, %2, %0;" : "+l"(d) : "l"(a), "l"(b))
union F2U { unsigned long long u; float2 f; };
__device__ __forceinline__ unsigned long long dup2(float a) {
    unsigned x = __float_as_uint(a);
    return ((unsigned long long)x << 32) | (unsigned long long)x;
}

__device__ __forceinline__ unsigned smem_u32(const void* p) {
    return (unsigned)__cvta_generic_to_shared(p);
}

// fast activations (safe at +/-inf)
__device__ __forceinline__ float fsig(float x) {
    return __fdividef(1.f, 1.f + __expf(-x));
}
__device__ __forceinline__ float ftanh(float x) {
    return 1.f - __fdividef(2.f, __expf(2.f * x) + 1.f);
}

// ---------------------------------------------------------------------------
// tcgen05 helpers — ONLY compiled on the sm_100a pass.
// ---------------------------------------------------------------------------
#if defined(__CUDA_ARCH_FEAT_SM100_ALL)
__device__ __forceinline__ bool elect1() {
    unsigned p;
    asm volatile("{\n\t.reg .pred p;\n\telect.sync _|p, 0xFFFFFFFF;\n\tselp.b32 %0,1,0,p;\n\t}"
                 : "=r"(p));
    return p != 0;
}
__device__ __forceinline__ unsigned long long mk_desc(unsigned addr) {
    // SW128, version=1 (Blackwell), SBO=64, LBO=1 (K-major, 128B rows)
    return 0x4000404000010000ULL | ((unsigned long long)(addr >> 4) & 0x3FFF);
}
__device__ __forceinline__ void tc_mma_f16_ss(unsigned d, unsigned long long ad,
                                              unsigned long long bd, unsigned idesc,
                                              unsigned en)
{
    asm volatile(
        "{\n\t.reg .pred p;\n\tsetp.ne.u32 p, %5, 0;\n\t"
        "tcgen05.mma.cta_group::1.kind::f16 [%0], %1, %2, %3, {%4, %4, %4, %4}, p;\n\t}"
        :: "r"(d), "l"(ad), "l"(bd), "r"(idesc), "r"(0u), "r"(en)
        : "memory");
}
#define TC_ALLOC(smaddr, n) \
    asm volatile("tcgen05.alloc.cta_group::1.sync.aligned.shared::cta.b32 [%0], %1;" \
                 :: "r"(smaddr), "r"((unsigned)(n)) : "memory")
#define TC_DEALLOC(base, n) \
    asm volatile("tcgen05.dealloc.cta_group::1.sync.aligned.b32 %0, %1;" \
                 :: "r"(base), "r"((unsigned)(n)))
#define TC_COMMIT(mb) \
    asm volatile("tcgen05.commit.cta_group::1.mbarrier::arrive::one.shared::cluster.b64 [%0];" \
                 :: "r"(mb) : "memory")
#define TC_FENCE_AFTER()  asm volatile("tcgen05.fence::after_thread_sync;" ::: "memory")
#define TC_FENCE_BEFORE() asm volatile("tcgen05.fence::before_thread_sync;" ::: "memory")
#define TC_WAIT_LD()      asm volatile("tcgen05.wait::ld.sync.aligned;" ::: "memory")

#define MBAR_INIT(mb, cnt) \
    asm volatile("mbarrier.init.shared.b64 [%0], %1;" :: "r"(mb), "r"((unsigned)(cnt)) : "memory")
#define MBAR_WAIT(mb, par) do { \
    unsigned _m = (mb), _p = (par), _d; \
    asm volatile("{\n\t.reg .pred p;\n\t" \
                 "mbarrier.try_wait.parity.acquire.cta.shared::cta.b64 p, [%1], %2;\n\t" \
                 "selp.b32 %0,1,0,p;\n\t}" : "=r"(_d) : "r"(_m), "r"(_p) : "memory"); \
    if (!_d) { \
        asm volatile("{\n\t.reg .pred P1;\n\t" \
                     "WL%=:\n\t" \
                     "mbarrier.try_wait.parity.acquire.cta.shared::cta.b64 P1, [%0], %1, 0x989680;\n\t" \
                     "@P1 bra.uni WD%=;\n\tbra.uni WL%=;\n\tWD%=:\n\t}" \
                     :: "r"(_m), "r"(_p) : "memory"); \
    } \
} while(0)

#define TC_LD32(r, addr) \
    asm volatile("tcgen05.ld.sync.aligned.32x32b.x32.b32 " \
        "{%0,%1,%2,%3,%4,%5,%6,%7,%8,%9,%10,%11,%12,%13,%14,%15," \
        "%16,%17,%18,%19,%20,%21,%22,%23,%24,%25,%26,%27,%28,%29,%30,%31}, [%32];" \
        : "=r"((r)[0]),"=r"((r)[1]),"=r"((r)[2]),"=r"((r)[3]), \
          "=r"((r)[4]),"=r"((r)[5]),"=r"((r)[6]),"=r"((r)[7]), \
          "=r"((r)[8]),"=r"((r)[9]),"=r"((r)[10]),"=r"((r)[11]), \
          "=r"((r)[12]),"=r"((r)[13]),"=r"((r)[14]),"=r"((r)[15]), \
          "=r"((r)[16]),"=r"((r)[17]),"=r"((r)[18]),"=r"((r)[19]), \
          "=r"((r)[20]),"=r"((r)[21]),"=r"((r)[22]),"=r"((r)[23]), \
          "=r"((r)[24]),"=r"((r)[25]),"=r"((r)[26]),"=r"((r)[27]), \
          "=r"((r)[28]),"=r"((r)[29]),"=r"((r)[30]),"=r"((r)[31]) \
        : "r"(addr))

// idesc: f32 accum, f16 a/b, M=128, N=64
#define IDESC_F16 0x08100010u
#endif // __CUDA_ARCH_FEAT_SM100_ALL

// ---------------------------------------------------------------------------
// Conversion kernels (single fp16)
// ---------------------------------------------------------------------------
__global__ void interleave_whh(const float* __restrict__ W, __half* __restrict__ out)
{
    int c = blockIdx.x;                 // gate-interleaved row c = j*4 + g
    int j = c >> 2, g = c & 3;
    const float* src = W + (size_t)(g * Hdim + j) * Hdim;
    int k = threadIdx.x * 4;
    float4 v = *(const float4*)&src[k];
    size_t o = (size_t)c * Hdim + k;
    out[o + 0] = __float2half_rn(v.x);
    out[o + 1] = __float2half_rn(v.y);
    out[o + 2] = __float2half_rn(v.z);
    out[o + 3] = __float2half_rn(v.w);
}

__global__ void conv16(const float* __restrict__ src, __half* __restrict__ dst)
{
    int i = (blockIdx.x * 256 + threadIdx.x) * 4;
    float4 v = *(const float4*)&src[i];
    dst[i + 0] = __float2half_rn(v.x);
    dst[i + 1] = __float2half_rn(v.y);
    dst[i + 2] = __float2half_rn(v.z);
    dst[i + 3] = __float2half_rn(v.w);
}

// ---------------------------------------------------------------------------
// Merged projection GEMM (f32x2): one launch computes
//   by<2 : xpart[m0..m0+127]   = x @ W_ih[:, :512]^T + b_ih + b_hh
//   by>=2: embproj[m0..m0+127] = emb @ W_ih[:, 512:768]^T
// Grid (64, 6), 256 threads.
// ---------------------------------------------------------------------------
__global__ __launch_bounds__(256) void proj_dual(
    const float* __restrict__ x,
    const float* __restrict__ emb,
    const float* __restrict__ W_ih,
    float* __restrict__ xpart,
    float* __restrict__ embproj,
    const float* __restrict__ b_ih,
    const float* __restrict__ b_hh)
{
    const int by = blockIdx.y;
    const float* A; const float* Bm; float* C;
    const float *bias0, *bias1;
    int lda, K, m0;
    if (by < 2) {
        A = x;  lda = Xdim; K = Xdim; m0 = by * 128;
        Bm = W_ih; C = xpart; bias0 = b_ih; bias1 = b_hh;
    } else {
        A = emb; lda = Edim; K = Edim; m0 = (by - 2) * 128;
        Bm = W_ih + Xdim; C = embproj; bias0 = nullptr; bias1 = nullptr;
    }
    const int ldb = DIN, ldc = G4;

    __shared__ unsigned long long As2[16][128];
    __shared__ float Bs[16][64];
    const int n0 = blockIdx.x * 64;
    const int tid = threadIdx.x;
    const int rg = tid >> 4;
    const int cg = tid & 15;
    unsigned long long acc[8][2];
    #pragma unroll
    for (int i = 0; i < 8; i++) { acc[i][0] = 0ull; acc[i][1] = 0ull; }
    const int fm = tid >> 2;
    const int fk = (tid & 3) * 4;

    for (int k0 = 0; k0 < K; k0 += 16) {
        __syncthreads();
        #pragma unroll
        for (int half = 0; half < 2; half++) {
            int m = fm + half * 64;
            float4 v = *(const float4*)&A[(size_t)(m0 + m) * lda + k0 + fk];
            As2[fk + 0][m] = dup2(v.x);
            As2[fk + 1][m] = dup2(v.y);
            As2[fk + 2][m] = dup2(v.z);
            As2[fk + 3][m] = dup2(v.w);
        }
        {
            float4 v = *(const float4*)&Bm[(size_t)(n0 + fm) * ldb + k0 + fk];
            Bs[fk + 0][fm] = v.x; Bs[fk + 1][fm] = v.y;
            Bs[fk + 2][fm] = v.z; Bs[fk + 3][fm] = v.w;
        }
        __syncthreads();
        #pragma unroll
        for (int k = 0; k < 16; k++) {
            const ulonglong2* ap = (const ulonglong2*)&As2[k][rg * 8];
            ulonglong2 bv = *(const ulonglong2*)&Bs[k][cg * 4];
            #pragma unroll
            for (int i2 = 0; i2 < 4; i2++) {
                ulonglong2 a = ap[i2];
                FFMA2(acc[2 * i2 + 0][0], a.x, bv.x);
                FFMA2(acc[2 * i2 + 0][1], a.x, bv.y);
                FFMA2(acc[2 * i2 + 1][0], a.y, bv.x);
                FFMA2(acc[2 * i2 + 1][1], a.y, bv.y);
            }
        }
    }
    #pragma unroll
    for (int i = 0; i < 8; i++) {
        int m = m0 + rg * 8 + i;
        #pragma unroll
        for (int p = 0; p < 2; p++) {
            int n = n0 + cg * 4 + p * 2;
            F2U u; u.u = acc[i][p];
            float v0 = u.f.x, v1 = u.f.y;
            if (bias0) { v0 += bias0[n]; v1 += bias0[n + 1]; }
            if (bias1) { v0 += bias1[n]; v1 += bias1[n + 1]; }
            *(float2*)&C[(size_t)m * ldc + n] = make_float2(v0, v1);
        }
    }
}

// ---------------------------------------------------------------------------
// mma.sync fallback mainloop: single-term fp16. 64m x 128n.
// 3 stages x 15360 B: A[64][40]@0, B[128][40]@5120.
// ---------------------------------------------------------------------------
__device__ __forceinline__ void mma_mainloop1(
    const __half* __restrict__ gA, const __half* __restrict__ gB,
    unsigned smem_u, int tid, float acc[2][4][4])
{
    const int lane = tid & 31, w = tid >> 5;
    const int wm = w & 1, wn = w >> 1;
    const int lrow = (lane & 7) + ((lane >> 3) & 1) * 8;
    const int lcol = (lane >> 4) * 8;
    const unsigned aoff = ((wm * 32 + lrow) * 40 + lcol) * 2;
    const unsigned boff = ((wn * 32 + lrow) * 40 + lcol) * 2;

    const int ar = tid >> 2;
    const int br = tid >> 1;
    const unsigned dA  = (ar * 40 + (tid & 3) * 8) * 2;
    const unsigned dB0 = (br * 40 + (tid & 1) * 16) * 2;
    const unsigned dB1 = dB0 + 16;

    #pragma unroll
    for (int s = 0; s < 2; s++) {
        unsigned sb = smem_u + s * 15360;
        int k0 = s * 32;
        CP16(sb + dA,         gA + k0);
        CP16(sb + 5120 + dB0, gB + k0);
        CP16(sb + 5120 + dB1, gB + k0 + 8);
        CPCOMMIT();
    }

    for (int i = 0; i < 32; i++) {
        if (i < 31) { CPWAIT(1); } else { CPWAIT(0); }
        __syncthreads();
        if (i + 2 < 32) {
            unsigned sb = smem_u + ((i + 2) % 3) * 15360;
            int k0 = (i + 2) * 32;
            CP16(sb + dA,         gA + k0);
            CP16(sb + 5120 + dB0, gB + k0);
            CP16(sb + 5120 + dB1, gB + k0 + 8);
            CPCOMMIT();
        }
        unsigned sb = smem_u + (i % 3) * 15360;
        #pragma unroll
        for (int kh = 0; kh < 2; kh++) {
            const unsigned kb = kh * 32;
            unsigned a0[4], a1[4];
            LDSM4(a0, sb + aoff + kb);
            LDSM4(a1, sb + aoff + 1280 + kb);
            unsigned bh0[4], bh1[4];
            LDSM4(bh0, sb + 5120 + boff + kb);
            LDSM4(bh1, sb + 5120 + boff + 1280 + kb);
            #pragma unroll
            for (int nt = 0; nt < 4; nt++) {
                const unsigned* bhp = (nt < 2) ? bh0 : bh1;
                unsigned h0v = bhp[nt & 1], h1v = bhp[(nt & 1) + 2];
                MMA4F(acc[0][nt], a0, h0v, h1v);
                MMA4F(acc[1][nt], a1, h0v, h1v);
            }
        }
    }
}

// ---------------------------------------------------------------------------
// Barriers
// ---------------------------------------------------------------------------
__global__ void init_bar() {
    g_bar_arrive = 0; g_bar_gen = 0;
    g_arr2[0] = 0; g_arr2[1] = 0;
    g_gen2[0] = 0; g_gen2[1] = 0;
#if defined(__CUDA_ARCH_FEAT_SM100_ALL)
    g_use_tc = 1;
#else
    g_use_tc = 0;
#endif
}

__device__ __forceinline__ void grid_sync(int tid, unsigned gen)
{
    __syncthreads();
    if (tid == 0) {
        __threadfence();
        unsigned a = atomicAdd(&g_bar_arrive, 1);
        if (a == 127) {
            g_bar_arrive = 0;
            __threadfence();
            atomicExch(&g_bar_gen, gen);
        } else {
            while (atomicAdd(&g_bar_gen, 0u) < gen) __nanosleep(64);
            __threadfence();
        }
    }
    __syncthreads();
}

// lstm tcgen05 stage: A0 16K @0, A1 @16384, B0 8K @32768, B1 @40960
#define LSTG 49152
#define LNS  4
#define DSMEM_LSTM (LNS * LSTG)   // 196608
// logits tcgen05 stage
#define STG_SZ 24576
#define N_STG  8

// ---------------------------------------------------------------------------
// Persistent LSTM sequence kernel — dual path.
// tcgen05: block = 128 batch x 64 gate-cols (16 j x 4 gates, rows j*4+g),
// K-chunk = 128 (2 sub-tiles), 4-stage pipeline, W prefetch across steps.
// cp.async group accounting (per step): prologue B0,B1,B2 then A0,A1,A2;
// steady-state AB groups. Needed-newest-pending: kc<=5 -> 2, kc==6 -> 1,
// kc==7 -> 0.
// ---------------------------------------------------------------------------
__global__ __launch_bounds__(256, 1) void lstm_seq(
    __half* hA, __half* hB,
    const float* __restrict__ c0,
    const float* __restrict__ xpart,
    const float* __restrict__ embproj,
    __half* __restrict__ hs,
    const __half* __restrict__ whh,
    const int* __restrict__ atom_truth)
{
#if defined(__CUDA_ARCH_FEAT_SM100_ALL)
    extern __shared__ __align__(1024) unsigned char dsm[];
    __shared__ unsigned s_tmem;
    __shared__ __align__(8) unsigned long long s_mbar[LNS];

    const unsigned smem_u = smem_u32(dsm);
    const int tid = threadIdx.x;
    const int wid = tid >> 5, lane = tid & 31;
    const int bx = blockIdx.x;
    const int half = bx >> 6;
    const int b0 = half * 128;
    const int ntb = bx & 63;
    const int c0g = ntb * 64;
    const int jb = ntb * 16;

    if (tid == 0) {
        #pragma unroll
        for (int i = 0; i < LNS; i++) MBAR_INIT(smem_u32(&s_mbar[i]), 1);
    }
    __syncthreads();
    if (wid == 0) TC_ALLOC(smem_u32(&s_tmem), 512);
    __syncthreads();
    const unsigned tmem = s_tmem;
    unsigned mbu[LNS];
    #pragma unroll
    for (int i = 0; i < LNS; i++) mbu[i] = smem_u32(&s_mbar[i]);
    int ph[LNS] = {0, 0, 0, 0};

    // fill geometry
    const int ra = tid >> 1, ca = (tid & 1) * 4;       // A: row, 4 x 16B per sub
    const int rb = tid >> 2, cb2 = (tid & 3) * 2;      // B: row, 2 x 16B per sub
    const int ram = ra & 7, rbm = rb & 7;
    const __half* Bsrc = whh + (size_t)(c0g + rb) * Hdim;
    const __half* Asrc;   // set per step

    // epilogue geometry
    const int b = b0 + (wid & 3) * 32 + lane;
    const int jh = (wid >> 2) * 8;
    float creg[8];
    {
        const float* cp = c0 + (size_t)b * Hdim + jb + jh;
        float4 v0 = *(const float4*)&cp[0];
        float4 v1 = *(const float4*)&cp[4];
        creg[0] = v0.x; creg[1] = v0.y; creg[2] = v0.z; creg[3] = v0.w;
        creg[4] = v1.x; creg[5] = v1.y; creg[6] = v1.z; creg[7] = v1.w;
    }

    // k-chunk = 128 elements; stage holds 2 sub-tiles of 64
    #define FILL_B(kc_, st_) do { \
        unsigned ab = smem_u + (st_) * LSTG + 32768; \
        const __half* bs = Bsrc + (kc_) * 128; \
        _Pragma("unroll") \
        for (int sub = 0; sub < 2; sub++) { \
            _Pragma("unroll") \
            for (int c = 0; c < 2; c++) { \
                int cc = cb2 + c; \
                unsigned d = rb * 128 + ((cc ^ rbm) * 16); \
                CP16(ab + sub * 8192 + d, bs + sub * 64 + cc * 8); \
            } \
        } \
        CPCOMMIT(); \
    } while (0)

    #define FILL_A(kc_, st_) do { \
        unsigned ab = smem_u + (st_) * LSTG; \
        const __half* sh = Asrc + (kc_) * 128; \
        _Pragma("unroll") \
        for (int sub = 0; sub < 2; sub++) { \
            _Pragma("unroll") \
            for (int c = 0; c < 4; c++) { \
                int cc = ca + c; \
                unsigned d = ra * 128 + ((cc ^ ram) * 16); \
                CP16(ab + sub * 16384 + d, sh + sub * 64 + cc * 8); \
            } \
        } \
        CPCOMMIT(); \
    } while (0)

    #define FILL_AB(kc_, st_) do { \
        unsigned ab = smem_u + (st_) * LSTG; \
        const __half* sh = Asrc + (kc_) * 128; \
        const __half* bs = Bsrc + (kc_) * 128; \
        _Pragma("unroll") \
        for (int sub = 0; sub < 2; sub++) { \
            _Pragma("unroll") \
            for (int c = 0; c < 4; c++) { \
                int cc = ca + c; \
                unsigned d = ra * 128 + ((cc ^ ram) * 16); \
                CP16(ab + sub * 16384 + d, sh + sub * 64 + cc * 8); \
            } \
            _Pragma("unroll") \
            for (int c = 0; c < 2; c++) { \
                int cc = cb2 + c; \
                unsigned d = rb * 128 + ((cc ^ rbm) * 16); \
                CP16(ab + 32768 + sub * 8192 + d, bs + sub * 64 + cc * 8); \
            } \
        } \
        CPCOMMIT(); \
    } while (0)

    // W prefetch for step 0: chunks 0..2 into stages 0..2
    FILL_B(0, 0); FILL_B(1, 1); FILL_B(2, 2);

    for (int t = 0; t < Tlen; t++) {
        const __half* hin = (t & 1) ? hB : hA;
        __half* hout      = (t & 1) ? hA : hB;
        Asrc = hin + (size_t)(b0 + ra) * Hdim;

        FILL_A(0, 0); FILL_A(1, 1); FILL_A(2, 2);

        for (int kc = 0; kc < 8; kc++) {
            // group accounting: stage kc needs its B (old) AND A (newer) group;
            // newest not-yet-needed pending groups = 2 for kc<=5, 1 @6, 0 @7.
            if (kc <= 5)      { CPWAIT(2); }
            else if (kc == 6) { CPWAIT(1); }
            else              { CPWAIT(0); }
            __syncthreads();
            if (wid == 0 && elect1()) {
                unsigned sb = smem_u + (kc & 3) * LSTG;
                #pragma unroll
                for (int sub = 0; sub < 2; sub++) {
                    unsigned long long ad = mk_desc(sb + sub * 16384);
                    unsigned long long bd = mk_desc(sb + 32768 + sub * 8192);
                    #pragma unroll
                    for (int ks = 0; ks < 4; ks++) {
                        unsigned en0 = (kc == 0 && sub == 0 && ks == 0) ? 0u : 1u;
                        tc_mma_f16_ss(tmem, ad + ks * 2, bd + ks * 2, IDESC_F16, en0);
                    }
                }
                TC_COMMIT(mbu[kc & 3]);
            }
            if (kc + 3 < 8) {
                if (kc >= 1) {
                    int s = (kc - 1) & 3;
                    MBAR_WAIT(mbu[s], (unsigned)(ph[s] & 1));
                    ph[s]++;
                }
                FILL_AB(kc + 3, (kc + 3) & 3);
            }
        }

        // prefetch epilogue operands while tail MMAs drain
        int tok = (t == 0) ? 0 : atom_truth[b * Tlen + (t - 1)];
        const float* xp = xpart + (size_t)b * G4 + jb + jh;
        const float* ep = embproj + (size_t)tok * G4 + jb + jh;
        float xg[4][8], eg[4][8];
        #pragma unroll
        for (int p = 0; p < 4; p++) {
            float4 a0 = *(const float4*)&xp[p * Hdim];
            float4 a1 = *(const float4*)&xp[p * Hdim + 4];
            float4 e0 = *(const float4*)&ep[p * Hdim];
            float4 e1 = *(const float4*)&ep[p * Hdim + 4];
            xg[p][0] = a0.x; xg[p][1] = a0.y; xg[p][2] = a0.z; xg[p][3] = a0.w;
            xg[p][4] = a1.x; xg[p][5] = a1.y; xg[p][6] = a1.z; xg[p][7] = a1.w;
            eg[p][0] = e0.x; eg[p][1] = e0.y; eg[p][2] = e0.z; eg[p][3] = e0.w;
            eg[p][4] = e1.x; eg[p][5] = e1.y; eg[p][6] = e1.z; eg[p][7] = e1.w;
        }

        // tail waits: chunks 4..7 (all 4 stages, second commit)
        #pragma unroll
        for (int c = 4; c < 8; c++) {
            int s = c & 3;
            MBAR_WAIT(mbu[s], (unsigned)(ph[s] & 1));
            ph[s]++;
        }
        TC_FENCE_AFTER();

        // next step's W prefetch, overlapped with epilogue + barrier
        if (t < Tlen - 1) { FILL_B(0, 0); FILL_B(1, 1); FILL_B(2, 2); }

        unsigned dr[32];
        TC_LD32(dr, tmem + (wid >> 2) * 32);
        TC_WAIT_LD();
        TC_FENCE_BEFORE();

        __half hh[8];
        #pragma unroll
        for (int jl = 0; jl < 8; jl++) {
            float ig = __uint_as_float(dr[4 * jl + 0]) + xg[0][jl] + eg[0][jl];
            float fg = __uint_as_float(dr[4 * jl + 1]) + xg[1][jl] + eg[1][jl];
            float gg = __uint_as_float(dr[4 * jl + 2]) + xg[2][jl] + eg[2][jl];
            float og = __uint_as_float(dr[4 * jl + 3]) + xg[3][jl] + eg[3][jl];
            ig = fsig(ig); fg = fsig(fg); og = fsig(og); gg = ftanh(gg);
            float cv = fg * creg[jl] + ig * gg;
            creg[jl] = cv;
            hh[jl] = __float2half_rn(og * ftanh(cv));
        }
        {
            size_t o = (size_t)b * Hdim + jb + jh;
            *(uint4*)&hout[o] = *(uint4*)&hh[0];
            size_t ho = ((size_t)t * Bsz + b) * Hdim + jb + jh;
            *(uint4*)&hs[ho] = *(uint4*)&hh[0];
        }

        if (t < Tlen - 1) {
            __syncthreads();
            if (tid == 0) {
                __threadfence();
                unsigned old = atomicAdd(&g_arr2[half], 1);
                if (old == 63) {
                    g_arr2[half] = 0;
                    asm volatile("st.release.gpu.b32 [%0], %1;"
                                 :: "l"(&g_gen2[half]), "r"((unsigned)(t + 1)) : "memory");
                } else {
                    unsigned g;
                    do {
                        asm volatile("ld.acquire.gpu.b32 %0, [%1];"
                                     : "=r"(g) : "l"(&g_gen2[half]) : "memory");
                        if (g < (unsigned)(t + 1)) __nanosleep(32);
                    } while (g < (unsigned)(t + 1));
                }
            }
            __syncthreads();
        }
    }

    __syncthreads();
    if (wid == 0) TC_DEALLOC(tmem, 512);
    #undef FILL_B
    #undef FILL_A
    #undef FILL_AB

#else
    // ===================== mma.sync fallback (fp16 single-term) =====================
    extern __shared__ __align__(1024) unsigned char dsm[];
    unsigned smem_u = smem_u32(dsm);
    float* Gs = (float*)dsm;

    const int bx = blockIdx.x;
    const int j0 = (bx & 31) * 32;
    const int b0 = (bx >> 5) * 64;
    const int gcol0 = j0 * 4;
    const int tid = threadIdx.x;
    const int lane = tid & 31, w = tid >> 5;
    const int wm = w & 1, wn = w >> 1;
    const int qr = lane >> 2, qk = (lane & 3) * 2;
    const int ar = tid >> 2, akc = (tid & 3) * 8;
    const int br = tid >> 1, bkc = (tid & 1) * 16;

    const __half* gB = whh + (size_t)(gcol0 + br) * Hdim + bkc;

    float creg[8];
    #pragma unroll
    for (int i = 0; i < 8; i++) {
        int idx = tid + i * 256;
        creg[i] = c0[(b0 + (idx >> 5)) * Hdim + j0 + (idx & 31)];
    }

    for (int t = 0; t < Tlen; t++) {
        const __half* hin = (t & 1) ? hB : hA;
        __half* hout      = (t & 1) ? hA : hB;

        float acc[2][4][4];
        #pragma unroll
        for (int mt = 0; mt < 2; mt++)
            #pragma unroll
            for (int nt = 0; nt < 4; nt++)
                #pragma unroll
                for (int q = 0; q < 4; q++) acc[mt][nt][q] = 0.f;

        mma_mainloop1(hin + (size_t)(b0 + ar) * Hdim + akc, gB, smem_u, tid, acc);

        __syncthreads();
        #pragma unroll
        for (int mt = 0; mt < 2; mt++)
            #pragma unroll
            for (int nt = 0; nt < 4; nt++) {
                int r = wm * 32 + mt * 16 + qr;
                int cc = wn * 32 + nt * 8 + qk;
                *(float2*)&Gs[r * 132 + cc]       = make_float2(acc[mt][nt][0], acc[mt][nt][1]);
                *(float2*)&Gs[(r + 8) * 132 + cc] = make_float2(acc[mt][nt][2], acc[mt][nt][3]);
            }
        __syncthreads();

        #pragma unroll
        for (int i = 0; i < 8; i++) {
            int idx = tid + i * 256;
            int bl = idx >> 5, jj = idx & 31;
            float4 gv = *(const float4*)&Gs[bl * 132 + jj * 4];
            int b = b0 + bl, j = j0 + jj;
            int tok = (t == 0) ? 0 : atom_truth[b * Tlen + (t - 1)];
            const float* xp = xpart + (size_t)b * G4 + j;
            const float* ep = embproj + (size_t)tok * G4 + j;
            float ig = gv.x + xp[0]        + ep[0];
            float fg = gv.y + xp[Hdim]     + ep[Hdim];
            float gg = gv.z + xp[2 * Hdim] + ep[2 * Hdim];
            float og = gv.w + xp[3 * Hdim] + ep[3 * Hdim];
            ig = fsig(ig); fg = fsig(fg); og = fsig(og); gg = ftanh(gg);
            float cv = fg * creg[i] + ig * gg;
            creg[i] = cv;
            __half hv = __float2half_rn(og * ftanh(cv));
            hout[b * Hdim + j] = hv;
            hs[((size_t)t * Bsz + b) * Hdim + j] = hv;
        }

        if (t < Tlen - 1) grid_sync(tid, (unsigned)(t + 1));
    }
#endif
}

// ---------------------------------------------------------------------------
// Logits GEMM, tcgen05: C[16384,512] = hs @ W_out^T + b_out.
// Single-term fp16. Tiles 128m x 64n; grid (8, 128).
// ---------------------------------------------------------------------------
__global__ __launch_bounds__(256, 1) void logits_tc(
    const __half* __restrict__ A_g,
    const __half* __restrict__ B_g,
    float* __restrict__ C,
    const float* __restrict__ bias)
{
#if defined(__CUDA_ARCH_FEAT_SM100_ALL)
    extern __shared__ __align__(1024) unsigned char dsm[];
    __shared__ unsigned s_tmem;
    __shared__ __align__(8) unsigned long long s_mbar[N_STG];

    const unsigned smem_u = smem_u32(dsm);
    const int tid = threadIdx.x;
    const int wid = tid >> 5, lane = tid & 31;
    const int n0 = blockIdx.x * 64;
    const int m0 = blockIdx.y * 128;

    if (tid == 0) {
        #pragma unroll
        for (int i = 0; i < N_STG; i++) MBAR_INIT(smem_u32(&s_mbar[i]), 1);
    }
    __syncthreads();
    if (wid == 0) TC_ALLOC(smem_u32(&s_tmem), 512);
    __syncthreads();
    const unsigned tmem = s_tmem;
    unsigned mbu[N_STG];
    #pragma unroll
    for (int i = 0; i < N_STG; i++) mbu[i] = smem_u32(&s_mbar[i]);
    int ph[N_STG] = {0, 0, 0, 0, 0, 0, 0, 0};

    const int ra = tid >> 1, ca = (tid & 1) * 4;
    const int rb = tid >> 2, cb2 = (tid & 3) * 2;
    const int ram = ra & 7, rbm = rb & 7;
    const __half* Asrc = A_g + (size_t)(m0 + ra) * Hdim;
    const __half* Bsrc = B_g + (size_t)(n0 + rb) * Hdim;

    #define LFILL(kc_, st_) do { \
        unsigned ab = smem_u + (st_) * STG_SZ; \
        const __half* sh = Asrc + (kc_) * 64; \
        _Pragma("unroll") \
        for (int c = 0; c < 4; c++) { \
            int cc = ca + c; \
            unsigned d = ra * 128 + ((cc ^ ram) * 16); \
            CP16(ab + d, sh + cc * 8); \
        } \
        const __half* bs = Bsrc + (kc_) * 64; \
        _Pragma("unroll") \
        for (int c = 0; c < 2; c++) { \
            int cc = cb2 + c; \
            unsigned d = rb * 128 + ((cc ^ rbm) * 16); \
            CP16(ab + 16384 + d, bs + cc * 8); \
        } \
        CPCOMMIT(); \
    } while (0)

    LFILL(0, 0); LFILL(1, 1); LFILL(2, 2); LFILL(3, 3);
    LFILL(4, 4); LFILL(5, 5); LFILL(6, 6);

    for (int kc = 0; kc < 16; kc++) {
        if (kc <= 9)       { CPWAIT(6); }
        else if (kc == 10) { CPWAIT(5); }
        else if (kc == 11) { CPWAIT(4); }
        else if (kc == 12) { CPWAIT(3); }
        else if (kc == 13) { CPWAIT(2); }
        else if (kc == 14) { CPWAIT(1); }
        else               { CPWAIT(0); }
        __syncthreads();
        if (wid == 0 && elect1()) {
            unsigned sb = smem_u + (kc % N_STG) * STG_SZ;
            unsigned long long ad = mk_desc(sb);
            unsigned long long bd = mk_desc(sb + 16384);
            #pragma unroll
            for (int ks = 0; ks < 4; ks++) {
                unsigned en0 = (kc == 0 && ks == 0) ? 0u : 1u;
                tc_mma_f16_ss(tmem, ad + ks * 2, bd + ks * 2, IDESC_F16, en0);
            }
            TC_COMMIT(mbu[kc % N_STG]);
        }
        if (kc + 7 < 16) {
            if (kc >= 1) {
                int s = (kc - 1) % N_STG;
                MBAR_WAIT(mbu[s], (unsigned)(ph[s] & 1));
                ph[s]++;
            }
            LFILL(kc + 7, (kc + 7) % N_STG);
        }
    }
    #pragma unroll
    for (int c = 8; c < 16; c++) {
        int s = c % N_STG;
        MBAR_WAIT(mbu[s], (unsigned)(ph[s] & 1));
        ph[s]++;
    }
    TC_FENCE_AFTER();

    unsigned dr[32];
    TC_LD32(dr, tmem + (wid >> 2) * 32);
    TC_WAIT_LD();
    TC_FENCE_BEFORE();

    // stage to smem [128][65] then coalesced write with bias
    float* S = (float*)dsm;
    {
        int r = (wid & 3) * 32 + lane;
        int cb = (wid >> 2) * 32;
        #pragma unroll
        for (int c = 0; c < 32; c++) S[r * 65 + cb + c] = __uint_as_float(dr[c]);
    }
    __syncthreads();
    #pragma unroll
    for (int q = 0; q < 8; q++) {
        int idx = tid + q * 256;
        int rr = idx >> 4, c4 = (idx & 15) * 4;
        float4 bv = *(const float4*)&bias[n0 + c4];
        float4 v;
        v.x = S[rr * 65 + c4 + 0] + bv.x;
        v.y = S[rr * 65 + c4 + 1] + bv.y;
        v.z = S[rr * 65 + c4 + 2] + bv.z;
        v.w = S[rr * 65 + c4 + 3] + bv.w;
        *(float4*)&C[(size_t)(m0 + rr) * NTAG + n0 + c4] = v;
    }
    __syncthreads();
    if (wid == 0) TC_DEALLOC(tmem, 512);
    #undef LFILL
#endif
}

// ---------------------------------------------------------------------------
// Logits fallback (mma.sync) — no-ops when tcgen05 cubin active.
// ---------------------------------------------------------------------------
__global__ __launch_bounds__(256) void logits_mma(
    const __half* __restrict__ A_g,
    const __half* __restrict__ B_g,
    float* __restrict__ C,
    const float* __restrict__ bias)
{
    if (g_use_tc) return;
    extern __shared__ __align__(16) unsigned char dsm2[];
    unsigned smem_u = (unsigned)__cvta_generic_to_shared(dsm2);

    const int n0 = blockIdx.x * 128;
    const int m0 = blockIdx.y * 64;
    const int tid = threadIdx.x;
    const int lane = tid & 31, w = tid >> 5;
    const int wm = w & 1, wn = w >> 1;
    const int qr = lane >> 2, qk = (lane & 3) * 2;
    const int ar = tid >> 2, akc = (tid & 3) * 8;
    const int br = tid >> 1, bkc = (tid & 1) * 16;

    float acc[2][4][4];
    #pragma unroll
    for (int mt = 0; mt < 2; mt++)
        #pragma unroll
        for (int nt = 0; nt < 4; nt++)
            #pragma unroll
            for (int q = 0; q < 4; q++) acc[mt][nt][q] = 0.f;

    mma_mainloop1(A_g + (size_t)(m0 + ar) * Hdim + akc,
                  B_g + (size_t)(n0 + br) * Hdim + bkc,
                  smem_u, tid, acc);

    #pragma unroll
    for (int mt = 0; mt < 2; mt++)
        #pragma unroll
        for (int nt = 0; nt < 4; nt++) {
            int m = m0 + wm * 32 + mt * 16 + qr;
            int n = n0 + wn * 32 + nt * 8 + qk;
            float b0v = bias[n], b1v = bias[n + 1];
            *(float2*)&C[(size_t)m * NTAG + n] =
                make_float2(acc[mt][nt][0] + b0v, acc[mt][nt][1] + b1v);
            *(float2*)&C[(size_t)(m + 8) * NTAG + n] =
                make_float2(acc[mt][nt][2] + b0v, acc[mt][nt][3] + b1v);
        }
}

// ---------------------------------------------------------------------------
// Mask detection / NLL / reduction
// ---------------------------------------------------------------------------
__global__ void detect_mask(const unsigned* __restrict__ m)
{
    __shared__ int isByte, isFloat;
    if (threadIdx.x == 0) { isByte = 0; isFloat = 0; }
    __syncthreads();
    for (int i = threadIdx.x; i < (Bsz * Tlen) / 4; i += blockDim.x) {
        unsigned v = m[i];
        if (v == 0x3F800000u) isFloat = 1;
        else if (v > 1u) isByte = 1;
    }
    __syncthreads();
    if (threadIdx.x == 0) g_mask_mode = isFloat ? 2 : (isByte ? 1 : 0);
}

__global__ __launch_bounds__(128) void nll_rows(
    const float* __restrict__ logits,
    const int* __restrict__ atom_truth,
    const void* __restrict__ atom_mask,
    float* __restrict__ rownll,
    float* __restrict__ rowmask)
{
    const int r = blockIdx.x;
    const int t = r >> 8;
    const int b = r & 255;
    const float* row = logits + (size_t)r * NTAG;
    const int tid = threadIdx.x;
    __shared__ float red[128];

    float mx = -1e30f;
    for (int i = tid; i < NTAG; i += 128) mx = fmaxf(mx, row[i]);
    red[tid] = mx; __syncthreads();
    for (int s = 64; s > 0; s >>= 1) {
        if (tid < s) red[tid] = fmaxf(red[tid], red[tid + s]);
        __syncthreads();
    }
    mx = red[0]; __syncthreads();

    float sm = 0.f;
    for (int i = tid; i < NTAG; i += 128) sm += __expf(row[i] - mx);
    red[tid] = sm; __syncthreads();
    for (int s = 64; s > 0; s >>= 1) {
        if (tid < s) red[tid] += red[tid + s];
        __syncthreads();
    }

    if (tid == 0) {
        int tgt = atom_truth[b * Tlen + t];
        float lp = row[tgt] - mx - logf(red[0]);
        int mode = g_mask_mode;
        float m;
        if (mode == 2)      m = (((const float*)atom_mask)[b * Tlen + t] != 0.f) ? 1.f : 0.f;
        else if (mode == 1) m = (((const unsigned char*)atom_mask)[b * Tlen + t] != 0) ? 1.f : 0.f;
        else                m = (((const int*)atom_mask)[b * Tlen + t] != 0) ? 1.f : 0.f;
        rownll[r]  = -lp * m;
        rowmask[r] = m;
    }
}

__global__ __launch_bounds__(256) void final_reduce(
    const float* __restrict__ rownll,
    const float* __restrict__ rowmask,
    float* __restrict__ out)
{
    __shared__ double rn[256], rm[256];
    double sn = 0.0, sm = 0.0;
    for (int i = threadIdx.x; i < Tlen * Bsz; i += 256) {
        sn += (double)rownll[i];
        sm += (double)rowmask[i];
    }
    rn[threadIdx.x] = sn; rm[threadIdx.x] = sm;
    __syncthreads();
    for (int s = 128; s > 0; s >>= 1) {
        if (threadIdx.x < s) {
            rn[threadIdx.x] += rn[threadIdx.x + s];
            rm[threadIdx.x] += rm[threadIdx.x + s];
        }
        __syncthreads();
    }
    if (threadIdx.x == 0) out[0] = (float)(rn[0] / rm[0]);
}

// ---------------------------------------------------------------------------
// Launch
// ---------------------------------------------------------------------------
extern "C" void kernel_launch(void* const* d_in, const int* in_sizes, int n_in,
                              void* d_out, int out_size)
{
    const float* x      = (const float*)d_in[0];
    const int*   atomtr = (const int*)d_in[1];
    const void*  mask   = d_in[2];
    const float* emb    = (const float*)d_in[3];
    const float* W_ih   = (const float*)d_in[4];
    const float* W_hh   = (const float*)d_in[5];
    const float* b_ih   = (const float*)d_in[6];
    const float* b_hh   = (const float*)d_in[7];
    const float* W_out  = (const float*)d_in[8];
    const float* b_out  = (const float*)d_in[9];
    const float* h0     = (const float*)d_in[10];
    const float* c0     = (const float*)d_in[11];

    float* sc = nullptr;
    cudaGetSymbolAddress((void**)&sc, g_scratch);
    float* xpart   = sc + 0;
    float* embproj = sc + 1048576;
    float* logits  = sc + 3407872;
    float* rownll  = sc + 11796480;
    float* rowmask = sc + 11812864;
    __half* hb = (__half*)(sc + 11829248);
    __half* whh  = hb + 0;
    __half* wout = hb + 8388608;
    __half* hA   = hb + 9437184;
    __half* hB   = hb + 9699328;
    __half* hs   = hb + 9961472;

    const int DSMEM_LOGTC = N_STG * STG_SZ;   // 196608
    const int DSMEM_LOG   = 3 * 15360;        // 46080
    static int attr_done = 0;
    if (!attr_done) {
        cudaFuncSetAttribute(lstm_seq,   cudaFuncAttributeMaxDynamicSharedMemorySize, DSMEM_LSTM);
        cudaFuncSetAttribute(logits_tc,  cudaFuncAttributeMaxDynamicSharedMemorySize, DSMEM_LOGTC);
        cudaFuncSetAttribute(logits_mma, cudaFuncAttributeMaxDynamicSharedMemorySize, DSMEM_LOG);
        attr_done = 1;
    }

    detect_mask<<<1, 256>>>((const unsigned*)mask);
    init_bar<<<1, 1>>>();

    // one-time weight / state conversions (single fp16)
    interleave_whh<<<4096, 256>>>(W_hh, whh);
    conv16<<<512, 256>>>(W_out, wout);
    conv16<<<256, 256>>>(h0, hA);

    // merged projection: xpart + embproj in one launch (grid 64x6)
    proj_dual<<<dim3(G4 / 64, 6), 256>>>(x, emb, W_ih, xpart, embproj, b_ih, b_hh);

    // all 64 LSTM steps in one persistent kernel
    lstm_seq<<<128, 256, DSMEM_LSTM>>>(
        hA, hB, c0, xpart, embproj, hs, whh, atomtr);

    // logits = hs @ W_out^T + b_out   [16384, 512]  (exactly one of these runs)
    logits_tc<<<dim3(NTAG / 64, (Tlen * Bsz) / 128), 256, DSMEM_LOGTC>>>(
        hs, wout, logits, b_out);
    logits_mma<<<dim3(NTAG / 128, (Tlen * Bsz) / 64), 256, DSMEM_LOG>>>(
        hs, wout, logits, b_out);

    nll_rows<<<Tlen * Bsz, 128>>>(logits, atomtr, mask, rownll, rowmask);
    final_reduce<<<1, 256>>>(rownll, rowmask, (float*)d_out);
}